// round 3
// baseline (speedup 1.0000x reference)
#include <cuda_runtime.h>
#include <math.h>

#define BATCH 8
#define SEQ   1024
#define DIM   1024
#define HEADS 16
#define DH    64
#define HFF   4096
#define MROWS (BATCH*SEQ)   // 8192

// ---------------- scratch (static device arrays: allocation-free) ----------
// g_ln is reused as the attention-output buffer after Q/K/V are formed.
// g_sc (scores, 512MB) is reused as the FFN hidden buffer after PV consumes it.
__device__ float g_ln [(size_t)MROWS*DIM];
__device__ float g_q  [(size_t)MROWS*DIM];
__device__ float g_k  [(size_t)MROWS*DIM];
__device__ float g_v  [(size_t)MROWS*DIM];
__device__ float g_x1 [(size_t)MROWS*DIM];
__device__ float g_sc [(size_t)BATCH*HEADS*SEQ*SEQ];   // >= MROWS*HFF

// ---------------- LayerNorm (ddof=1, divide by (std + eps)) ----------------
__global__ __launch_bounds__(256) void ln_kernel(const float* __restrict__ x,
                                                 float* __restrict__ y,
                                                 const float* __restrict__ alpha,
                                                 const float* __restrict__ beta) {
    __shared__ float sh_s[8], sh_q[8];
    const size_t row = blockIdx.x;
    const float4* xr = (const float4*)(x + row * DIM);
    float4* yr = (float4*)(y + row * DIM);
    const int tid = threadIdx.x;            // 256 threads, 4 elems each
    float4 v = xr[tid];
    float s = v.x + v.y + v.z + v.w;
    float q = v.x*v.x + v.y*v.y + v.z*v.z + v.w*v.w;
#pragma unroll
    for (int o = 16; o; o >>= 1) {
        s += __shfl_xor_sync(0xffffffffu, s, o);
        q += __shfl_xor_sync(0xffffffffu, q, o);
    }
    if ((tid & 31) == 0) { sh_s[tid >> 5] = s; sh_q[tid >> 5] = q; }
    __syncthreads();
    if (tid < 32) {
        s = (tid < 8) ? sh_s[tid] : 0.f;
        q = (tid < 8) ? sh_q[tid] : 0.f;
#pragma unroll
        for (int o = 4; o; o >>= 1) {
            s += __shfl_xor_sync(0xffffffffu, s, o);
            q += __shfl_xor_sync(0xffffffffu, q, o);
        }
        if (tid == 0) { sh_s[0] = s; sh_q[0] = q; }
    }
    __syncthreads();
    s = sh_s[0]; q = sh_q[0];
    const float mean = s * (1.0f / DIM);
    const float var  = (q - (float)DIM * mean * mean) * (1.0f / (DIM - 1));
    const float inv  = 1.0f / (sqrtf(fmaxf(var, 0.f)) + 1e-6f);
    const float4 a = ((const float4*)alpha)[tid];
    const float4 b = ((const float4*)beta)[tid];
    float4 o4;
    o4.x = a.x * (v.x - mean) * inv + b.x;
    o4.y = a.y * (v.y - mean) * inv + b.y;
    o4.z = a.z * (v.z - mean) * inv + b.z;
    o4.w = a.w * (v.w - mean) * inv + b.w;
    yr[tid] = o4;
}

// ---------------- row softmax over SEQ=1024 --------------------------------
__global__ __launch_bounds__(256) void softmax_kernel(float* __restrict__ p) {
    __shared__ float sh[8];
    __shared__ float bcast;
    float* pr = p + (size_t)blockIdx.x * SEQ;
    const int tid = threadIdx.x;
    float4 v = ((float4*)pr)[tid];
    float m = fmaxf(fmaxf(v.x, v.y), fmaxf(v.z, v.w));
#pragma unroll
    for (int o = 16; o; o >>= 1) m = fmaxf(m, __shfl_xor_sync(0xffffffffu, m, o));
    if ((tid & 31) == 0) sh[tid >> 5] = m;
    __syncthreads();
    if (tid < 32) {
        m = (tid < 8) ? sh[tid] : -INFINITY;
#pragma unroll
        for (int o = 4; o; o >>= 1) m = fmaxf(m, __shfl_xor_sync(0xffffffffu, m, o));
        if (tid == 0) bcast = m;
    }
    __syncthreads();
    m = bcast;
    v.x = __expf(v.x - m); v.y = __expf(v.y - m);
    v.z = __expf(v.z - m); v.w = __expf(v.w - m);
    float s = v.x + v.y + v.z + v.w;
    __syncthreads();   // protect sh reuse
#pragma unroll
    for (int o = 16; o; o >>= 1) s += __shfl_xor_sync(0xffffffffu, s, o);
    if ((tid & 31) == 0) sh[tid >> 5] = s;
    __syncthreads();
    if (tid < 32) {
        s = (tid < 8) ? sh[tid] : 0.f;
#pragma unroll
        for (int o = 4; o; o >>= 1) s += __shfl_xor_sync(0xffffffffu, s, o);
        if (tid == 0) bcast = s;
    }
    __syncthreads();
    const float inv = 1.0f / bcast;
    v.x *= inv; v.y *= inv; v.z *= inv; v.w *= inv;
    ((float4*)pr)[tid] = v;
}

// ---------------- GEMM NT: C[m,n] = scale * sum_k A[m,k]*B[n,k] (+bias,+relu,+resid)
// BM=BN=128, BK=16, 256 threads, 8x8 per thread. All dims multiples of 128.
// Batched via blockIdx.z with split offsets: z0 = z/zdiv, z1 = z%zdiv.
__global__ __launch_bounds__(256, 2) void gemm_nt(
    const float* __restrict__ A, int lda, long sA0, long sA1,
    const float* __restrict__ B, int ldb, long sB0, long sB1,
    float* __restrict__ C, int ldc, long sC0, long sC1,
    int zdiv, int K,
    const float* __restrict__ bias,
    const float* __restrict__ resid, int ldr,
    float scale, int relu)
{
    const int z  = blockIdx.z;
    const int z0 = z / zdiv;
    const int z1 = z - z0 * zdiv;
    A += z0 * sA0 + z1 * sA1;
    B += z0 * sB0 + z1 * sB1;
    C += z0 * sC0 + z1 * sC1;

    __shared__ float As[16][128];
    __shared__ float Bs[16][128];

    const int tid = threadIdx.x;
    const int tx  = tid & 15;
    const int ty  = tid >> 4;
    const int m0  = blockIdx.y * 128;
    const int n0  = blockIdx.x * 128;

    float acc[8][8];
#pragma unroll
    for (int i = 0; i < 8; i++)
#pragma unroll
        for (int j = 0; j < 8; j++) acc[i][j] = 0.f;

    const int lr = tid >> 2;          // 0..63
    const int lc = (tid & 3) * 4;     // 0,4,8,12

    for (int k0 = 0; k0 < K; k0 += 16) {
#pragma unroll
        for (int h = 0; h < 2; h++) {
            const int row = lr + h * 64;
            float4 va = *(const float4*)(A + (size_t)(m0 + row) * lda + (k0 + lc));
            As[lc + 0][row] = va.x; As[lc + 1][row] = va.y;
            As[lc + 2][row] = va.z; As[lc + 3][row] = va.w;
            float4 vb = *(const float4*)(B + (size_t)(n0 + row) * ldb + (k0 + lc));
            Bs[lc + 0][row] = vb.x; Bs[lc + 1][row] = vb.y;
            Bs[lc + 2][row] = vb.z; Bs[lc + 3][row] = vb.w;
        }
        __syncthreads();
#pragma unroll
        for (int kk = 0; kk < 16; kk++) {
            float a[8], b[8];
            *(float4*)(a)     = *(const float4*)(&As[kk][ty * 8]);
            *(float4*)(a + 4) = *(const float4*)(&As[kk][ty * 8 + 4]);
            *(float4*)(b)     = *(const float4*)(&Bs[kk][tx * 8]);
            *(float4*)(b + 4) = *(const float4*)(&Bs[kk][tx * 8 + 4]);
#pragma unroll
            for (int i = 0; i < 8; i++)
#pragma unroll
                for (int j = 0; j < 8; j++)
                    acc[i][j] = fmaf(a[i], b[j], acc[i][j]);
        }
        __syncthreads();
    }

#pragma unroll
    for (int i = 0; i < 8; i++) {
        const int m = m0 + ty * 8 + i;
#pragma unroll
        for (int j = 0; j < 8; j += 4) {
            const int n = n0 + tx * 8 + j;
            float4 r;
            r.x = acc[i][j + 0] * scale;
            r.y = acc[i][j + 1] * scale;
            r.z = acc[i][j + 2] * scale;
            r.w = acc[i][j + 3] * scale;
            if (bias) {
                float4 bb = *(const float4*)(bias + n);
                r.x += bb.x; r.y += bb.y; r.z += bb.z; r.w += bb.w;
            }
            if (relu) {
                r.x = fmaxf(r.x, 0.f); r.y = fmaxf(r.y, 0.f);
                r.z = fmaxf(r.z, 0.f); r.w = fmaxf(r.w, 0.f);
            }
            if (resid) {
                float4 rr = *(const float4*)(resid + (size_t)m * ldr + n);
                r.x += rr.x; r.y += rr.y; r.z += rr.z; r.w += rr.w;
            }
            *(float4*)(C + (size_t)m * ldc + n) = r;
        }
    }
}

// ---------------- PV GEMM (NN): O[b,q,h*64+d] = sum_j P[bh,q,j] * V[b,j,h*64+d]
// BM=128, BN=64(=Dh), BK=16, 256 threads, 8x4 per thread. grid (1, SEQ/128, B*H)
__global__ __launch_bounds__(256, 2) void gemm_pv(
    const float* __restrict__ P,
    const float* __restrict__ V,
    float* __restrict__ O)
{
    const int z = blockIdx.z;       // bh
    const int b = z >> 4, h = z & 15;
    const float* A = P + (size_t)z * SEQ * SEQ;
    const float* B = V + (size_t)b * SEQ * DIM + h * DH;
    float*       C = O + (size_t)b * SEQ * DIM + h * DH;

    __shared__ float As[16][128];
    __shared__ float Bs[16][64];

    const int tid = threadIdx.x;
    const int tx  = tid & 15;
    const int ty  = tid >> 4;
    const int m0  = blockIdx.y * 128;

    float acc[8][4];
#pragma unroll
    for (int i = 0; i < 8; i++)
#pragma unroll
        for (int j = 0; j < 4; j++) acc[i][j] = 0.f;

    const int lr = tid >> 2;
    const int lc = (tid & 3) * 4;
    const int br = tid >> 4;          // 0..15
    const int bc = (tid & 15) * 4;    // 0..60

    for (int k0 = 0; k0 < SEQ; k0 += 16) {
#pragma unroll
        for (int hh = 0; hh < 2; hh++) {
            const int row = lr + hh * 64;
            float4 va = *(const float4*)(A + (size_t)(m0 + row) * SEQ + (k0 + lc));
            As[lc + 0][row] = va.x; As[lc + 1][row] = va.y;
            As[lc + 2][row] = va.z; As[lc + 3][row] = va.w;
        }
        {
            float4 vb = *(const float4*)(B + (size_t)(k0 + br) * DIM + bc);
            *(float4*)(&Bs[br][bc]) = vb;
        }
        __syncthreads();
#pragma unroll
        for (int kk = 0; kk < 16; kk++) {
            float a[8], bb[4];
            *(float4*)(a)     = *(const float4*)(&As[kk][ty * 8]);
            *(float4*)(a + 4) = *(const float4*)(&As[kk][ty * 8 + 4]);
            *(float4*)(bb)    = *(const float4*)(&Bs[kk][tx * 4]);
#pragma unroll
            for (int i = 0; i < 8; i++)
#pragma unroll
                for (int j = 0; j < 4; j++)
                    acc[i][j] = fmaf(a[i], bb[j], acc[i][j]);
        }
        __syncthreads();
    }
#pragma unroll
    for (int i = 0; i < 8; i++) {
        const int m = m0 + ty * 8 + i;
        float4 r = make_float4(acc[i][0], acc[i][1], acc[i][2], acc[i][3]);
        *(float4*)(C + (size_t)m * DIM + tx * 4) = r;
    }
}

// ---------------- launch ----------------------------------------------------
static float* symaddr(const void* s) {
    void* p = nullptr;
    cudaGetSymbolAddress(&p, s);   // host-side query: not a stream op, capture-safe
    return (float*)p;
}

extern "C" void kernel_launch(void* const* d_in, const int* in_sizes, int n_in,
                              void* d_out, int out_size) {
    (void)in_sizes; (void)n_in; (void)out_size;
    const float* x     = (const float*)d_in[0];
    // d_in[1] = src_mask (unused by the reference implementation)
    const float* wq    = (const float*)d_in[2];
    const float* bq    = (const float*)d_in[3];
    const float* wk    = (const float*)d_in[4];
    const float* bk    = (const float*)d_in[5];
    const float* wv    = (const float*)d_in[6];
    const float* bv    = (const float*)d_in[7];
    const float* wo    = (const float*)d_in[8];
    const float* bo    = (const float*)d_in[9];
    const float* w1    = (const float*)d_in[10];
    const float* b1    = (const float*)d_in[11];
    const float* w2    = (const float*)d_in[12];
    const float* b2    = (const float*)d_in[13];
    const float* alpha = (const float*)d_in[14];
    const float* beta  = (const float*)d_in[15];
    float* out = (float*)d_out;

    float* ln   = symaddr(g_ln);
    float* q    = symaddr(g_q);
    float* k    = symaddr(g_k);
    float* v    = symaddr(g_v);
    float* x1   = symaddr(g_x1);
    float* sc   = symaddr(g_sc);
    float* attn = ln;   // reuse: ln consumed once q,k,v are formed
    float* hid  = sc;   // reuse: scores consumed after PV

    // 1) LN1
    ln_kernel<<<MROWS, 256>>>(x, ln, alpha, beta);

    // 2) Q, K, V projections: [8192,1024] = ln @ W^T + b
    dim3 gw(DIM / 128, MROWS / 128, 1);
    gemm_nt<<<gw, 256>>>(ln, DIM, 0, 0, wq, DIM, 0, 0, q, DIM, 0, 0,
                         1, DIM, bq, nullptr, 0, 1.f, 0);
    gemm_nt<<<gw, 256>>>(ln, DIM, 0, 0, wk, DIM, 0, 0, k, DIM, 0, 0,
                         1, DIM, bk, nullptr, 0, 1.f, 0);
    gemm_nt<<<gw, 256>>>(ln, DIM, 0, 0, wv, DIM, 0, 0, v, DIM, 0, 0,
                         1, DIM, bv, nullptr, 0, 1.f, 0);

    // 3) scores[bh,i,j] = q_i . k_j / 8   (batched NT, K=64)
    dim3 gs(SEQ / 128, SEQ / 128, BATCH * HEADS);
    gemm_nt<<<gs, 256>>>(q, DIM, (long)SEQ * DIM, DH,
                         k, DIM, (long)SEQ * DIM, DH,
                         sc, SEQ, (long)HEADS * SEQ * SEQ, (long)SEQ * SEQ,
                         HEADS, DH, nullptr, nullptr, 0, 0.125f, 0);

    // 4) softmax rows
    softmax_kernel<<<BATCH * HEADS * SEQ, 256>>>(sc);

    // 5) PV
    dim3 gp(1, SEQ / 128, BATCH * HEADS);
    gemm_pv<<<gp, 256>>>(sc, v, attn);

    // 6) O projection + residual x -> x1
    gemm_nt<<<gw, 256>>>(attn, DIM, 0, 0, wo, DIM, 0, 0, x1, DIM, 0, 0,
                         1, DIM, bo, x, DIM, 1.f, 0);

    // 7) LN2
    ln_kernel<<<MROWS, 256>>>(x1, ln, alpha, beta);

    // 8) FFN1: relu(ln @ w1^T + b1) -> hid [8192,4096]
    dim3 gf1(HFF / 128, MROWS / 128, 1);
    gemm_nt<<<gf1, 256>>>(ln, DIM, 0, 0, w1, DIM, 0, 0, hid, HFF, 0, 0,
                          1, DIM, b1, nullptr, 0, 1.f, 1);

    // 9) FFN2: hid @ w2^T + b2 + x1 -> out
    dim3 gf2(DIM / 128, MROWS / 128, 1);
    gemm_nt<<<gf2, 256>>>(hid, HFF, 0, 0, w2, HFF, 0, 0, out, DIM, 0, 0,
                          1, HFF, b2, x1, DIM, 1.f, 0);
}

// round 5
// speedup vs baseline: 1.8104x; 1.8104x over previous
#include <cuda_runtime.h>
#include <cuda_bf16.h>
#include <math.h>
#include <stdint.h>

#define BATCH 8
#define SEQ   1024
#define DIM   1024
#define HEADS 16
#define DH    64
#define HFF   4096
#define MROWS (BATCH*SEQ)   // 8192

// ---------------- scratch (static device arrays: allocation-free) ----------
__device__ float g_ln [(size_t)MROWS*DIM];
__device__ float g_q  [(size_t)MROWS*DIM];
__device__ float g_k  [(size_t)MROWS*DIM];
__device__ float g_v  [(size_t)MROWS*DIM];
__device__ float g_x1 [(size_t)MROWS*DIM];
__device__ float g_sc [(size_t)BATCH*HEADS*SEQ*SEQ];   // reused as FFN hidden

// ==================== helpers ====================
__device__ __forceinline__ uint32_t smem_u32(const void* p) {
    uint32_t a;
    asm("{ .reg .u64 t; cvta.to.shared.u64 t, %1; cvt.u32.u64 %0, t; }"
        : "=r"(a) : "l"(p));
    return a;
}

// fp32 -> (hi, lo) bf16 split, packed pairs (x = first elem = low half)
__device__ __forceinline__ void cvt2(float a, float b, uint32_t& h, uint32_t& l) {
    __nv_bfloat162 hh = __floats2bfloat162_rn(a, b);
    float ra = a - __bfloat162float(hh.x);
    float rb = b - __bfloat162float(hh.y);
    __nv_bfloat162 ll = __floats2bfloat162_rn(ra, rb);
    h = *(uint32_t*)&hh;
    l = *(uint32_t*)&ll;
}

#define LDM4(r0, r1, r2, r3, addr) \
    asm volatile("ldmatrix.sync.aligned.m8n8.x4.shared.b16 {%0,%1,%2,%3}, [%4];" \
                 : "=r"(r0), "=r"(r1), "=r"(r2), "=r"(r3) : "r"(addr))
#define LDM2(r0, r1, addr) \
    asm volatile("ldmatrix.sync.aligned.m8n8.x2.shared.b16 {%0,%1}, [%2];" \
                 : "=r"(r0), "=r"(r1) : "r"(addr))
#define MMA16816(c, a, b) \
    asm volatile("mma.sync.aligned.m16n8k16.row.col.f32.bf16.bf16.f32 " \
                 "{%0,%1,%2,%3}, {%4,%5,%6,%7}, {%8,%9}, {%0,%1,%2,%3};" \
                 : "+f"((c)[0]), "+f"((c)[1]), "+f"((c)[2]), "+f"((c)[3]) \
                 : "r"((a)[0]), "r"((a)[1]), "r"((a)[2]), "r"((a)[3]), \
                   "r"((b)[0]), "r"((b)[1]))

// ==================== split-bf16 mma.sync GEMM ====================
// C[m,n] = scale * sum_k A[m,k]*B[n,k] (+bias, +relu, +resid)
// BM=128, BK=32; BN=128 (weights/scores) or 64 (PV).
// smem rows padded to 80B so each 8-address ldmatrix phase hits 8 distinct
// 16B segments (80 mod 128 cycles through all 8 segments) -> conflict-free.
template<int BN, bool BNC>
__global__ __launch_bounds__(256) void gemm_mma(
    const float* __restrict__ A, int lda, long sA0, long sA1,
    const float* __restrict__ B, int ldb, long sB0, long sB1,
    float* __restrict__ C, int ldc, long sC0, long sC1,
    int zdiv, int K,
    const float* __restrict__ bias,
    const float* __restrict__ resid, int ldr,
    float scale, int relu)
{
    constexpr int BK = 32;
    constexpr int WN = BN / 4;      // warp n-extent: 32 or 16
    constexpr int NT = WN / 8;      // n8 tiles per warp: 4 or 2
    constexpr int ABYTES = 128 * 80;
    constexpr int BBYTES = BN * 80;
    constexpr int SS = 2 * ABYTES + 2 * BBYTES;   // one stage

    extern __shared__ char sm[];
    const uint32_t smBase = smem_u32(sm);

    const int tid = threadIdx.x;
    const int z = blockIdx.z, z0 = z / zdiv, z1 = z - z0 * zdiv;
    A += z0 * sA0 + z1 * sA1;
    B += z0 * sB0 + z1 * sB1;
    C += z0 * sC0 + z1 * sC1;
    const int m0 = blockIdx.y * 128;
    const int n0 = blockIdx.x * BN;

    const int wid = tid >> 5, lane = tid & 31;
    const int wm = wid >> 2, wn = wid & 3;

    float acc[4][NT][4];
#pragma unroll
    for (int i = 0; i < 4; i++)
#pragma unroll
        for (int j = 0; j < NT; j++)
#pragma unroll
            for (int r = 0; r < 4; r++) acc[i][j][r] = 0.f;

    auto load_stage = [&](int s, int t) {
        char* base = sm + s * SS;
        // A slab: 128 rows x 32 k
        const float* GA = A + (size_t)m0 * lda + t * BK;
#pragma unroll
        for (int id = tid; id < 128 * 8; id += 256) {
            const int row = id >> 3, k = (id & 7) * 4;
            const float4 v = *(const float4*)(GA + (size_t)row * lda + k);
            uint32_t h0, h1, l0, l1;
            cvt2(v.x, v.y, h0, l0);
            cvt2(v.z, v.w, h1, l1);
            char* p = base + row * 80 + k * 2;
            *(uint2*)p = make_uint2(h0, h1);
            *(uint2*)(p + ABYTES) = make_uint2(l0, l1);
        }
        char* bb = base + 2 * ABYTES;
        if (!BNC) {
            const float* GB = B + (size_t)n0 * ldb + t * BK;
#pragma unroll
            for (int id = tid; id < BN * 8; id += 256) {
                const int row = id >> 3, k = (id & 7) * 4;
                const float4 v = *(const float4*)(GB + (size_t)row * ldb + k);
                uint32_t h0, h1, l0, l1;
                cvt2(v.x, v.y, h0, l0);
                cvt2(v.z, v.w, h1, l1);
                char* p = bb + row * 80 + k * 2;
                *(uint2*)p = make_uint2(h0, h1);
                *(uint2*)(p + BBYTES) = make_uint2(l0, l1);
            }
        } else {
            // n-contiguous source: elem(k, n) = GB[k*ldb + n]; build Bs[n][k]
            const float* GB = B + (size_t)(t * BK) * ldb + n0;
#pragma unroll
            for (int id = tid; id < 16 * (BN / 4); id += 256) {
                const int kp = id / (BN / 4);            // k pair 0..15
                const int n4 = (id % (BN / 4)) * 4;
                const float* p = GB + (size_t)(2 * kp) * ldb + n4;
                const float4 v0 = *(const float4*)p;
                const float4 v1 = *(const float4*)(p + ldb);
                uint32_t h, l;
                cvt2(v0.x, v1.x, h, l);
                *(uint32_t*)(bb + (n4 + 0) * 80 + kp * 4) = h;
                *(uint32_t*)(bb + BBYTES + (n4 + 0) * 80 + kp * 4) = l;
                cvt2(v0.y, v1.y, h, l);
                *(uint32_t*)(bb + (n4 + 1) * 80 + kp * 4) = h;
                *(uint32_t*)(bb + BBYTES + (n4 + 1) * 80 + kp * 4) = l;
                cvt2(v0.z, v1.z, h, l);
                *(uint32_t*)(bb + (n4 + 2) * 80 + kp * 4) = h;
                *(uint32_t*)(bb + BBYTES + (n4 + 2) * 80 + kp * 4) = l;
                cvt2(v0.w, v1.w, h, l);
                *(uint32_t*)(bb + (n4 + 3) * 80 + kp * 4) = h;
                *(uint32_t*)(bb + BBYTES + (n4 + 3) * 80 + kp * 4) = l;
            }
        }
    };

    auto compute_stage = [&](int s) {
        const uint32_t aHiB = smBase + s * SS;
        const uint32_t aLoB = aHiB + ABYTES;
        const uint32_t bHiB = aHiB + 2 * ABYTES;
        const uint32_t bLoB = bHiB + BBYTES;
#pragma unroll
        for (int ks = 0; ks < 2; ks++) {
            uint32_t ah[4][4], al[4][4], bh[NT][2], bl[NT][2];
            const uint32_t kbA = (uint32_t)((ks * 16 + (lane >> 4) * 8) * 2);
#pragma unroll
            for (int mt = 0; mt < 4; mt++) {
                const uint32_t ra = (uint32_t)((wm * 64 + mt * 16 + (lane & 15)) * 80) + kbA;
                LDM4(ah[mt][0], ah[mt][1], ah[mt][2], ah[mt][3], aHiB + ra);
                LDM4(al[mt][0], al[mt][1], al[mt][2], al[mt][3], aLoB + ra);
            }
            const uint32_t kbB = (uint32_t)((ks * 16 + ((lane >> 3) & 1) * 8) * 2);
#pragma unroll
            for (int nt = 0; nt < NT; nt++) {
                const uint32_t rb = (uint32_t)((wn * WN + nt * 8 + (lane & 7)) * 80) + kbB;
                LDM2(bh[nt][0], bh[nt][1], bHiB + rb);
                LDM2(bl[nt][0], bl[nt][1], bLoB + rb);
            }
            // 3 passes -> accumulator RAW chains are NT*4 issues apart
#pragma unroll
            for (int mt = 0; mt < 4; mt++)
#pragma unroll
                for (int nt = 0; nt < NT; nt++)
                    MMA16816(acc[mt][nt], ah[mt], bh[nt]);
#pragma unroll
            for (int mt = 0; mt < 4; mt++)
#pragma unroll
                for (int nt = 0; nt < NT; nt++)
                    MMA16816(acc[mt][nt], ah[mt], bl[nt]);
#pragma unroll
            for (int mt = 0; mt < 4; mt++)
#pragma unroll
                for (int nt = 0; nt < NT; nt++)
                    MMA16816(acc[mt][nt], al[mt], bh[nt]);
        }
    };

    const int T = K / BK;
    load_stage(0, 0);
    __syncthreads();
    for (int t = 0; t < T; t++) {
        if (t + 1 < T) load_stage((t + 1) & 1, t + 1);   // overlaps compute below
        compute_stage(t & 1);
        __syncthreads();
    }

    // epilogue
#pragma unroll
    for (int mt = 0; mt < 4; mt++) {
#pragma unroll
        for (int nt = 0; nt < NT; nt++) {
            const int r0 = m0 + wm * 64 + mt * 16 + (lane >> 2);
            const int cc = n0 + wn * WN + nt * 8 + (lane & 3) * 2;
#pragma unroll
            for (int h = 0; h < 2; h++) {
                const int m = r0 + h * 8;
                float vx = acc[mt][nt][2 * h]     * scale;
                float vy = acc[mt][nt][2 * h + 1] * scale;
                if (bias)  { vx += bias[cc]; vy += bias[cc + 1]; }
                if (relu)  { vx = fmaxf(vx, 0.f); vy = fmaxf(vy, 0.f); }
                if (resid) {
                    const float2 rr = *(const float2*)(resid + (size_t)m * ldr + cc);
                    vx += rr.x; vy += rr.y;
                }
                *(float2*)(C + (size_t)m * ldc + cc) = make_float2(vx, vy);
            }
        }
    }
}

// ---------------- LayerNorm (ddof=1, divide by (std + eps)) ----------------
__global__ __launch_bounds__(256) void ln_kernel(const float* __restrict__ x,
                                                 float* __restrict__ y,
                                                 const float* __restrict__ alpha,
                                                 const float* __restrict__ beta) {
    __shared__ float sh_s[8], sh_q[8];
    const size_t row = blockIdx.x;
    const float4* xr = (const float4*)(x + row * DIM);
    float4* yr = (float4*)(y + row * DIM);
    const int tid = threadIdx.x;
    float4 v = xr[tid];
    float s = v.x + v.y + v.z + v.w;
    float q = v.x*v.x + v.y*v.y + v.z*v.z + v.w*v.w;
#pragma unroll
    for (int o = 16; o; o >>= 1) {
        s += __shfl_xor_sync(0xffffffffu, s, o);
        q += __shfl_xor_sync(0xffffffffu, q, o);
    }
    if ((tid & 31) == 0) { sh_s[tid >> 5] = s; sh_q[tid >> 5] = q; }
    __syncthreads();
    if (tid < 32) {
        s = (tid < 8) ? sh_s[tid] : 0.f;
        q = (tid < 8) ? sh_q[tid] : 0.f;
#pragma unroll
        for (int o = 4; o; o >>= 1) {
            s += __shfl_xor_sync(0xffffffffu, s, o);
            q += __shfl_xor_sync(0xffffffffu, q, o);
        }
        if (tid == 0) { sh_s[0] = s; sh_q[0] = q; }
    }
    __syncthreads();
    s = sh_s[0]; q = sh_q[0];
    const float mean = s * (1.0f / DIM);
    const float var  = (q - (float)DIM * mean * mean) * (1.0f / (DIM - 1));
    const float inv  = 1.0f / (sqrtf(fmaxf(var, 0.f)) + 1e-6f);
    const float4 a = ((const float4*)alpha)[tid];
    const float4 b = ((const float4*)beta)[tid];
    float4 o4;
    o4.x = a.x * (v.x - mean) * inv + b.x;
    o4.y = a.y * (v.y - mean) * inv + b.y;
    o4.z = a.z * (v.z - mean) * inv + b.z;
    o4.w = a.w * (v.w - mean) * inv + b.w;
    yr[tid] = o4;
}

// ---------------- row softmax over SEQ=1024 --------------------------------
__global__ __launch_bounds__(256) void softmax_kernel(float* __restrict__ p) {
    __shared__ float sh[8];
    __shared__ float bcast;
    float* pr = p + (size_t)blockIdx.x * SEQ;
    const int tid = threadIdx.x;
    float4 v = ((float4*)pr)[tid];
    float m = fmaxf(fmaxf(v.x, v.y), fmaxf(v.z, v.w));
#pragma unroll
    for (int o = 16; o; o >>= 1) m = fmaxf(m, __shfl_xor_sync(0xffffffffu, m, o));
    if ((tid & 31) == 0) sh[tid >> 5] = m;
    __syncthreads();
    if (tid < 32) {
        m = (tid < 8) ? sh[tid] : -INFINITY;
#pragma unroll
        for (int o = 4; o; o >>= 1) m = fmaxf(m, __shfl_xor_sync(0xffffffffu, m, o));
        if (tid == 0) bcast = m;
    }
    __syncthreads();
    m = bcast;
    v.x = __expf(v.x - m); v.y = __expf(v.y - m);
    v.z = __expf(v.z - m); v.w = __expf(v.w - m);
    float s = v.x + v.y + v.z + v.w;
    __syncthreads();
#pragma unroll
    for (int o = 16; o; o >>= 1) s += __shfl_xor_sync(0xffffffffu, s, o);
    if ((tid & 31) == 0) sh[tid >> 5] = s;
    __syncthreads();
    if (tid < 32) {
        s = (tid < 8) ? sh[tid] : 0.f;
#pragma unroll
        for (int o = 4; o; o >>= 1) s += __shfl_xor_sync(0xffffffffu, s, o);
        if (tid == 0) bcast = s;
    }
    __syncthreads();
    const float inv = 1.0f / bcast;
    v.x *= inv; v.y *= inv; v.z *= inv; v.w *= inv;
    ((float4*)pr)[tid] = v;
}

// ---------------- launch ----------------------------------------------------
static float* symaddr(const void* s) {
    void* p = nullptr;
    cudaGetSymbolAddress(&p, s);
    return (float*)p;
}

#define SMEM_128 (2 * (2 * 128 * 80 + 2 * 128 * 80))   // 81920
#define SMEM_64  (2 * (2 * 128 * 80 + 2 *  64 * 80))   // 61440

extern "C" void kernel_launch(void* const* d_in, const int* in_sizes, int n_in,
                              void* d_out, int out_size) {
    (void)in_sizes; (void)n_in; (void)out_size;
    const float* x     = (const float*)d_in[0];
    const float* wq    = (const float*)d_in[2];
    const float* bq    = (const float*)d_in[3];
    const float* wk    = (const float*)d_in[4];
    const float* bk    = (const float*)d_in[5];
    const float* wv    = (const float*)d_in[6];
    const float* bv    = (const float*)d_in[7];
    const float* wo    = (const float*)d_in[8];
    const float* bo    = (const float*)d_in[9];
    const float* w1    = (const float*)d_in[10];
    const float* b1    = (const float*)d_in[11];
    const float* w2    = (const float*)d_in[12];
    const float* b2    = (const float*)d_in[13];
    const float* alpha = (const float*)d_in[14];
    const float* beta  = (const float*)d_in[15];
    float* out = (float*)d_out;

    cudaFuncSetAttribute(gemm_mma<128, false>,
                         cudaFuncAttributeMaxDynamicSharedMemorySize, SMEM_128);
    cudaFuncSetAttribute(gemm_mma<64, true>,
                         cudaFuncAttributeMaxDynamicSharedMemorySize, SMEM_64);

    float* ln   = symaddr(g_ln);
    float* q    = symaddr(g_q);
    float* k    = symaddr(g_k);
    float* v    = symaddr(g_v);
    float* x1   = symaddr(g_x1);
    float* sc   = symaddr(g_sc);
    float* attn = ln;   // reuse after Q/K/V are formed
    float* hid  = sc;   // reuse after PV consumes scores

    // 1) LN1
    ln_kernel<<<MROWS, 256>>>(x, ln, alpha, beta);

    // 2) Q, K, V projections
    dim3 gw(DIM / 128, MROWS / 128, 1);
    gemm_mma<128, false><<<gw, 256, SMEM_128>>>(ln, DIM, 0, 0, wq, DIM, 0, 0,
        q, DIM, 0, 0, 1, DIM, bq, nullptr, 0, 1.f, 0);
    gemm_mma<128, false><<<gw, 256, SMEM_128>>>(ln, DIM, 0, 0, wk, DIM, 0, 0,
        k, DIM, 0, 0, 1, DIM, bk, nullptr, 0, 1.f, 0);
    gemm_mma<128, false><<<gw, 256, SMEM_128>>>(ln, DIM, 0, 0, wv, DIM, 0, 0,
        v, DIM, 0, 0, 1, DIM, bv, nullptr, 0, 1.f, 0);

    // 3) scores = Q K^T / 8
    dim3 gs(SEQ / 128, SEQ / 128, BATCH * HEADS);
    gemm_mma<128, false><<<gs, 256, SMEM_128>>>(
        q, DIM, (long)SEQ * DIM, DH,
        k, DIM, (long)SEQ * DIM, DH,
        sc, SEQ, (long)HEADS * SEQ * SEQ, (long)SEQ * SEQ,
        HEADS, DH, nullptr, nullptr, 0, 0.125f, 0);

    // 4) softmax
    softmax_kernel<<<BATCH * HEADS * SEQ, 256>>>(sc);

    // 5) PV (B = V is n-contiguous)
    dim3 gp(1, SEQ / 128, BATCH * HEADS);
    gemm_mma<64, true><<<gp, 256, SMEM_64>>>(
        sc, SEQ, (long)HEADS * SEQ * SEQ, (long)SEQ * SEQ,
        v, DIM, (long)SEQ * DIM, DH,
        attn, DIM, (long)SEQ * DIM, DH,
        HEADS, SEQ, nullptr, nullptr, 0, 1.f, 0);

    // 6) O projection + residual
    gemm_mma<128, false><<<gw, 256, SMEM_128>>>(attn, DIM, 0, 0, wo, DIM, 0, 0,
        x1, DIM, 0, 0, 1, DIM, bo, x, DIM, 1.f, 0);

    // 7) LN2
    ln_kernel<<<MROWS, 256>>>(x1, ln, alpha, beta);

    // 8) FFN1 (+ReLU)
    dim3 gf1(HFF / 128, MROWS / 128, 1);
    gemm_mma<128, false><<<gf1, 256, SMEM_128>>>(ln, DIM, 0, 0, w1, DIM, 0, 0,
        hid, HFF, 0, 0, 1, DIM, b1, nullptr, 0, 1.f, 1);

    // 9) FFN2 + residual
    dim3 gf2(DIM / 128, MROWS / 128, 1);
    gemm_mma<128, false><<<gf2, 256, SMEM_128>>>(hid, HFF, 0, 0, w2, HFF, 0, 0,
        out, DIM, 0, 0, 1, HFF, b2, x1, DIM, 1.f, 0);
}

// round 6
// speedup vs baseline: 2.2304x; 1.2320x over previous
#include <cuda_runtime.h>
#include <cuda_bf16.h>
#include <math.h>
#include <stdint.h>

#define BATCH 8
#define SEQ   1024
#define DIM   1024
#define HEADS 16
#define DH    64
#define HFF   4096
#define MROWS (BATCH*SEQ)   // 8192

// ---------------- scratch (static device arrays: allocation-free) ----------
// split-bf16 activation planes (hi, lo)
__device__ __nv_bfloat16 g_lnh[(size_t)MROWS*DIM], g_lnl[(size_t)MROWS*DIM];
__device__ __nv_bfloat16 g_qh [(size_t)MROWS*DIM], g_ql [(size_t)MROWS*DIM];
__device__ __nv_bfloat16 g_kh [(size_t)MROWS*DIM], g_kl [(size_t)MROWS*DIM];
__device__ __nv_bfloat16 g_vh [(size_t)MROWS*DIM], g_vl [(size_t)MROWS*DIM];
__device__ float g_x1[(size_t)MROWS*DIM];
// scores fp32; softmax converts rows in place to [hi(1024 bf16)|lo(1024 bf16)];
// later reused as FFN hidden split planes.
__device__ float g_sc[(size_t)BATCH*HEADS*SEQ*SEQ];

// ==================== helpers ====================
__device__ __forceinline__ uint32_t smem_u32(const void* p) {
    uint32_t a;
    asm("{ .reg .u64 t; cvta.to.shared.u64 t, %1; cvt.u32.u64 %0, t; }"
        : "=r"(a) : "l"(p));
    return a;
}
__device__ __forceinline__ void cp_async16(uint32_t dst, const void* src) {
    uint64_t g;
    asm("cvta.to.global.u64 %0, %1;" : "=l"(g) : "l"(src));
    asm volatile("cp.async.cg.shared.global [%0], [%1], 16;"
                 :: "r"(dst), "l"(g) : "memory");
}
#define CP_COMMIT() asm volatile("cp.async.commit_group;" ::: "memory")
#define CP_WAIT0()  asm volatile("cp.async.wait_group 0;"  ::: "memory")

// fp32 -> (hi, lo) bf16 split, packed pairs
__device__ __forceinline__ void cvt2(float a, float b, uint32_t& h, uint32_t& l) {
    __nv_bfloat162 hh = __floats2bfloat162_rn(a, b);
    float ra = a - __bfloat162float(hh.x);
    float rb = b - __bfloat162float(hh.y);
    __nv_bfloat162 ll = __floats2bfloat162_rn(ra, rb);
    h = *(uint32_t*)&hh;
    l = *(uint32_t*)&ll;
}

#define LDM4(r0, r1, r2, r3, addr) \
    asm volatile("ldmatrix.sync.aligned.m8n8.x4.shared.b16 {%0,%1,%2,%3}, [%4];" \
                 : "=r"(r0), "=r"(r1), "=r"(r2), "=r"(r3) : "r"(addr))
#define LDM2(r0, r1, addr) \
    asm volatile("ldmatrix.sync.aligned.m8n8.x2.shared.b16 {%0,%1}, [%2];" \
                 : "=r"(r0), "=r"(r1) : "r"(addr))
#define MMA16816(c, a, b) \
    asm volatile("mma.sync.aligned.m16n8k16.row.col.f32.bf16.bf16.f32 " \
                 "{%0,%1,%2,%3}, {%4,%5,%6,%7}, {%8,%9}, {%0,%1,%2,%3};" \
                 : "+f"((c)[0]), "+f"((c)[1]), "+f"((c)[2]), "+f"((c)[3]) \
                 : "r"((a)[0]), "r"((a)[1]), "r"((a)[2]), "r"((a)[3]), \
                   "r"((b)[0]), "r"((b)[1]))

// ==================== split-bf16 mma.sync GEMM v2 ====================
// C[m,n] = scale * sum_k A[m,k]*B[n,k] (+bias, +relu, +resid)
// A: always split-bf16 planes (hi/lo), K-major -> cp.async, no conversion.
// B: BMODE 0 = fp32 K-major (weights, LDG->cvt->STS, prefetched in regs)
//    BMODE 1 = split-bf16 K-major (scores' K operand, cp.async)
//    BMODE 2 = split-bf16 n-contiguous (PV's V operand, LDG->transpose->STS)
// Output: OSPLIT ? split-bf16 planes : fp32.
// smem rows padded to 80B -> conflict-free ldmatrix (5r mod 8 distinct).
template<int BN, int BMODE, bool OSPLIT>
__global__ __launch_bounds__(256) void gemm2(
    const __nv_bfloat16* __restrict__ Ah, const __nv_bfloat16* __restrict__ Al,
    int lda, long sA0, long sA1,
    const float* __restrict__ Bf,
    const __nv_bfloat16* __restrict__ Bh, const __nv_bfloat16* __restrict__ Bl,
    int ldb, long sB0, long sB1,
    float* __restrict__ Cf,
    __nv_bfloat16* __restrict__ Ch, __nv_bfloat16* __restrict__ Cl,
    int ldc, long sC0, long sC1,
    int zdiv, int K,
    const float* __restrict__ bias,
    const float* __restrict__ resid, int ldr,
    float scale, int relu)
{
    constexpr int BK = 32;
    constexpr int WN = BN / 4, NT = WN / 8;
    constexpr int ABYTES = 128 * 80;
    constexpr int BBYTES = BN * 80;
    constexpr int SS = 2 * ABYTES + 2 * BBYTES;

    extern __shared__ char sm[];
    const uint32_t smBase = smem_u32(sm);

    const int tid = threadIdx.x, wid = tid >> 5, lane = tid & 31;
    const int wm = wid >> 2, wn = wid & 3;
    const int z = blockIdx.z, z0 = z / zdiv, z1 = z - z0 * zdiv;
    const long aoff = z0 * sA0 + z1 * sA1;
    const long boff = z0 * sB0 + z1 * sB1;
    const long coff = z0 * sC0 + z1 * sC1;
    Ah += aoff; Al += aoff;
    if constexpr (BMODE == 0) { Bf += boff; } else { Bh += boff; Bl += boff; }
    if constexpr (OSPLIT) { Ch += coff; Cl += coff; } else { Cf += coff; }
    const int m0 = blockIdx.y * 128, n0 = blockIdx.x * BN;

    float acc[4][NT][4];
#pragma unroll
    for (int i = 0; i < 4; i++)
#pragma unroll
        for (int j = 0; j < NT; j++)
#pragma unroll
            for (int r = 0; r < 4; r++) acc[i][j][r] = 0.f;

    // B prefetch registers
    float4 rbf[4];
    uint32_t rn0[4], rn1[4];

    // ---- A: split planes, cp.async 16B chunks (128 rows x 32 k) ----
    auto issueA = [&](int s, int t) {
        const uint32_t sA = smBase + s * SS;
#pragma unroll
        for (int i = 0; i < 4; i++) {
            const int idx = i * 256 + tid;
            const int c = idx & 3, row = (idx >> 2) & 127, pl = idx >> 9;
            const __nv_bfloat16* g =
                (pl ? Al : Ah) + (size_t)(m0 + row) * lda + t * BK + c * 8;
            cp_async16(sA + pl * ABYTES + row * 80 + c * 16, g);
        }
    };
    // ---- B split K-major (BN=128), cp.async ----
    auto issueB1 = [&](int s, int t) {
        const uint32_t sB = smBase + s * SS + 2 * ABYTES;
#pragma unroll
        for (int i = 0; i < 4; i++) {
            const int idx = i * 256 + tid;
            const int c = idx & 3, row = (idx >> 2) & 127, pl = idx >> 9;
            const __nv_bfloat16* g =
                (pl ? Bl : Bh) + (size_t)(n0 + row) * ldb + t * BK + c * 8;
            cp_async16(sB + pl * BBYTES + row * 80 + c * 16, g);
        }
    };
    // ---- B fp32 K-major: LDG into regs ----
    auto ldgB0 = [&](int t) {
        const float* GB = Bf + (size_t)n0 * ldb + t * BK;
#pragma unroll
        for (int i = 0; i < 4; i++) {
            const int id = i * 256 + tid;
            const int row = id >> 3, kq = (id & 7) * 4;
            rbf[i] = *(const float4*)(GB + (size_t)row * ldb + kq);
        }
    };
    auto stsB0 = [&](int s) {
        char* bb = sm + s * SS + 2 * ABYTES;
#pragma unroll
        for (int i = 0; i < 4; i++) {
            const int id = i * 256 + tid;
            const int row = id >> 3, kq = (id & 7) * 4;
            uint32_t h0, h1, l0, l1;
            cvt2(rbf[i].x, rbf[i].y, h0, l0);
            cvt2(rbf[i].z, rbf[i].w, h1, l1);
            char* p = bb + row * 80 + kq * 2;
            *(uint2*)p = make_uint2(h0, h1);
            *(uint2*)(p + BBYTES) = make_uint2(l0, l1);
        }
    };
    // ---- B split n-contiguous (PV, BN=64): LDG pairs, transpose via prmt ----
    auto ldgB2 = [&](int t) {
#pragma unroll
        for (int i = 0; i < 4; i++) {
            const int id = i * 256 + tid;
            const int pl = id >> 9, rem = id & 511;
            const int kp = rem >> 5, n2 = rem & 31;
            const __nv_bfloat16* g =
                (pl ? Bl : Bh) + (size_t)(t * BK + 2 * kp) * ldb + n0 + 2 * n2;
            rn0[i] = *(const uint32_t*)g;
            rn1[i] = *(const uint32_t*)(g + ldb);
        }
    };
    auto stsB2 = [&](int s) {
        char* bb = sm + s * SS + 2 * ABYTES;
#pragma unroll
        for (int i = 0; i < 4; i++) {
            const int id = i * 256 + tid;
            const int pl = id >> 9, rem = id & 511;
            const int kp = rem >> 5, n2 = rem & 31;
            const uint32_t o0 = __byte_perm(rn0[i], rn1[i], 0x5410);
            const uint32_t o1 = __byte_perm(rn0[i], rn1[i], 0x7632);
            char* p = bb + pl * BBYTES + (2 * n2) * 80 + kp * 4;
            *(uint32_t*)p = o0;
            *(uint32_t*)(p + 80) = o1;
        }
    };

    auto compute = [&](int s) {
        const uint32_t aHiB = smBase + s * SS;
        const uint32_t aLoB = aHiB + ABYTES;
        const uint32_t bHiB = aHiB + 2 * ABYTES;
        const uint32_t bLoB = bHiB + BBYTES;
#pragma unroll
        for (int ks = 0; ks < 2; ks++) {
            uint32_t ah[4][4], al[4][4], bh[NT][2], bl[NT][2];
            const uint32_t kbA = (uint32_t)((ks * 16 + (lane >> 4) * 8) * 2);
#pragma unroll
            for (int mt = 0; mt < 4; mt++) {
                const uint32_t ra = (uint32_t)((wm * 64 + mt * 16 + (lane & 15)) * 80) + kbA;
                LDM4(ah[mt][0], ah[mt][1], ah[mt][2], ah[mt][3], aHiB + ra);
                LDM4(al[mt][0], al[mt][1], al[mt][2], al[mt][3], aLoB + ra);
            }
            const uint32_t kbB = (uint32_t)((ks * 16 + ((lane >> 3) & 1) * 8) * 2);
#pragma unroll
            for (int nt = 0; nt < NT; nt++) {
                const uint32_t rb = (uint32_t)((wn * WN + nt * 8 + (lane & 7)) * 80) + kbB;
                LDM2(bh[nt][0], bh[nt][1], bHiB + rb);
                LDM2(bl[nt][0], bl[nt][1], bLoB + rb);
            }
#pragma unroll
            for (int mt = 0; mt < 4; mt++)
#pragma unroll
                for (int nt = 0; nt < NT; nt++)
                    MMA16816(acc[mt][nt], ah[mt], bh[nt]);
#pragma unroll
            for (int mt = 0; mt < 4; mt++)
#pragma unroll
                for (int nt = 0; nt < NT; nt++)
                    MMA16816(acc[mt][nt], ah[mt], bl[nt]);
#pragma unroll
            for (int mt = 0; mt < 4; mt++)
#pragma unroll
                for (int nt = 0; nt < NT; nt++)
                    MMA16816(acc[mt][nt], al[mt], bh[nt]);
        }
    };

    const int T = K / BK;
    // prologue: stage 0
    issueA(0, 0);
    if constexpr (BMODE == 1) issueB1(0, 0);
    CP_COMMIT();
    if constexpr (BMODE == 0) { ldgB0(0); stsB0(0); }
    if constexpr (BMODE == 2) { ldgB2(0); stsB2(0); }
    CP_WAIT0();
    __syncthreads();

    for (int t = 0; t < T; t++) {
        const int s = t & 1;
        if (t + 1 < T) {
            issueA(s ^ 1, t + 1);
            if constexpr (BMODE == 1) issueB1(s ^ 1, t + 1);
            CP_COMMIT();
            if constexpr (BMODE == 0) ldgB0(t + 1);
            if constexpr (BMODE == 2) ldgB2(t + 1);
        }
        compute(s);                       // hides LDG + cp.async latency
        if (t + 1 < T) {
            if constexpr (BMODE == 0) stsB0(s ^ 1);
            if constexpr (BMODE == 2) stsB2(s ^ 1);
        }
        CP_WAIT0();
        __syncthreads();
    }

    // epilogue
#pragma unroll
    for (int mt = 0; mt < 4; mt++) {
#pragma unroll
        for (int nt = 0; nt < NT; nt++) {
            const int r0 = m0 + wm * 64 + mt * 16 + (lane >> 2);
            const int cc = n0 + wn * WN + nt * 8 + (lane & 3) * 2;
#pragma unroll
            for (int h = 0; h < 2; h++) {
                const int m = r0 + h * 8;
                float vx = acc[mt][nt][2 * h]     * scale;
                float vy = acc[mt][nt][2 * h + 1] * scale;
                if (bias)  { vx += bias[cc]; vy += bias[cc + 1]; }
                if (relu)  { vx = fmaxf(vx, 0.f); vy = fmaxf(vy, 0.f); }
                if (resid) {
                    const float2 rr = *(const float2*)(resid + (size_t)m * ldr + cc);
                    vx += rr.x; vy += rr.y;
                }
                if constexpr (OSPLIT) {
                    uint32_t hh, ll;
                    cvt2(vx, vy, hh, ll);
                    *(uint32_t*)(Ch + (size_t)m * ldc + cc) = hh;
                    *(uint32_t*)(Cl + (size_t)m * ldc + cc) = ll;
                } else {
                    *(float2*)(Cf + (size_t)m * ldc + cc) = make_float2(vx, vy);
                }
            }
        }
    }
}

// ---------------- LayerNorm -> split-bf16 planes ---------------------------
__global__ __launch_bounds__(256) void ln_kernel(const float* __restrict__ x,
                                                 __nv_bfloat16* __restrict__ yh,
                                                 __nv_bfloat16* __restrict__ yl,
                                                 const float* __restrict__ alpha,
                                                 const float* __restrict__ beta) {
    __shared__ float sh_s[8], sh_q[8];
    const size_t row = blockIdx.x;
    const float4* xr = (const float4*)(x + row * DIM);
    const int tid = threadIdx.x;
    float4 v = xr[tid];
    float s = v.x + v.y + v.z + v.w;
    float q = v.x*v.x + v.y*v.y + v.z*v.z + v.w*v.w;
#pragma unroll
    for (int o = 16; o; o >>= 1) {
        s += __shfl_xor_sync(0xffffffffu, s, o);
        q += __shfl_xor_sync(0xffffffffu, q, o);
    }
    if ((tid & 31) == 0) { sh_s[tid >> 5] = s; sh_q[tid >> 5] = q; }
    __syncthreads();
    if (tid < 32) {
        s = (tid < 8) ? sh_s[tid] : 0.f;
        q = (tid < 8) ? sh_q[tid] : 0.f;
#pragma unroll
        for (int o = 4; o; o >>= 1) {
            s += __shfl_xor_sync(0xffffffffu, s, o);
            q += __shfl_xor_sync(0xffffffffu, q, o);
        }
        if (tid == 0) { sh_s[0] = s; sh_q[0] = q; }
    }
    __syncthreads();
    s = sh_s[0]; q = sh_q[0];
    const float mean = s * (1.0f / DIM);
    const float var  = (q - (float)DIM * mean * mean) * (1.0f / (DIM - 1));
    const float inv  = 1.0f / (sqrtf(fmaxf(var, 0.f)) + 1e-6f);
    const float4 a = ((const float4*)alpha)[tid];
    const float4 b = ((const float4*)beta)[tid];
    float ox = a.x * (v.x - mean) * inv + b.x;
    float oy = a.y * (v.y - mean) * inv + b.y;
    float oz = a.z * (v.z - mean) * inv + b.z;
    float ow = a.w * (v.w - mean) * inv + b.w;
    uint32_t h0, l0, h1, l1;
    cvt2(ox, oy, h0, l0);
    cvt2(oz, ow, h1, l1);
    *(uint2*)(yh + row * DIM + 4 * tid) = make_uint2(h0, h1);
    *(uint2*)(yl + row * DIM + 4 * tid) = make_uint2(l0, l1);
}

// ------ row softmax over SEQ=1024, in-place fp32 -> [hi|lo] bf16 row -------
__global__ __launch_bounds__(256) void softmax_kernel(float* __restrict__ p) {
    __shared__ float sh[8];
    __shared__ float bcast;
    float* pr = p + (size_t)blockIdx.x * SEQ;
    const int tid = threadIdx.x;
    float4 v = ((float4*)pr)[tid];
    float m = fmaxf(fmaxf(v.x, v.y), fmaxf(v.z, v.w));
#pragma unroll
    for (int o = 16; o; o >>= 1) m = fmaxf(m, __shfl_xor_sync(0xffffffffu, m, o));
    if ((tid & 31) == 0) sh[tid >> 5] = m;
    __syncthreads();
    if (tid < 32) {
        m = (tid < 8) ? sh[tid] : -INFINITY;
#pragma unroll
        for (int o = 4; o; o >>= 1) m = fmaxf(m, __shfl_xor_sync(0xffffffffu, m, o));
        if (tid == 0) bcast = m;
    }
    __syncthreads();
    m = bcast;
    v.x = __expf(v.x - m); v.y = __expf(v.y - m);
    v.z = __expf(v.z - m); v.w = __expf(v.w - m);
    float s = v.x + v.y + v.z + v.w;
    __syncthreads();
#pragma unroll
    for (int o = 16; o; o >>= 1) s += __shfl_xor_sync(0xffffffffu, s, o);
    if ((tid & 31) == 0) sh[tid >> 5] = s;
    __syncthreads();
    if (tid < 32) {
        s = (tid < 8) ? sh[tid] : 0.f;
#pragma unroll
        for (int o = 4; o; o >>= 1) s += __shfl_xor_sync(0xffffffffu, s, o);
        if (tid == 0) bcast = s;
    }
    __syncthreads();
    const float inv = 1.0f / bcast;
    v.x *= inv; v.y *= inv; v.z *= inv; v.w *= inv;
    uint32_t h0, l0, h1, l1;
    cvt2(v.x, v.y, h0, l0);
    cvt2(v.z, v.w, h1, l1);
    uint16_t* row16 = (uint16_t*)pr;                 // 2048 halves per row
    *(uint2*)(row16 + 4 * tid)        = make_uint2(h0, h1);   // hi half
    *(uint2*)(row16 + 1024 + 4 * tid) = make_uint2(l0, l1);   // lo half
}

// ---------------- launch ----------------------------------------------------
template<typename T>
static T* symaddr(const void* s) {
    void* p = nullptr;
    cudaGetSymbolAddress(&p, s);
    return (T*)p;
}

#define SMEM_128 (2 * (2 * 128 * 80 + 2 * 128 * 80))   // 81920
#define SMEM_64  (2 * (2 * 128 * 80 + 2 *  64 * 80))   // 61440

typedef __nv_bfloat16 bf16;

extern "C" void kernel_launch(void* const* d_in, const int* in_sizes, int n_in,
                              void* d_out, int out_size) {
    (void)in_sizes; (void)n_in; (void)out_size;
    const float* x     = (const float*)d_in[0];
    const float* wq    = (const float*)d_in[2];
    const float* bq    = (const float*)d_in[3];
    const float* wk    = (const float*)d_in[4];
    const float* bk    = (const float*)d_in[5];
    const float* wv    = (const float*)d_in[6];
    const float* bv    = (const float*)d_in[7];
    const float* wo    = (const float*)d_in[8];
    const float* bo    = (const float*)d_in[9];
    const float* w1    = (const float*)d_in[10];
    const float* b1    = (const float*)d_in[11];
    const float* w2    = (const float*)d_in[12];
    const float* b2    = (const float*)d_in[13];
    const float* alpha = (const float*)d_in[14];
    const float* beta  = (const float*)d_in[15];
    float* out = (float*)d_out;

    cudaFuncSetAttribute(gemm2<128, 0, true>,
                         cudaFuncAttributeMaxDynamicSharedMemorySize, SMEM_128);
    cudaFuncSetAttribute(gemm2<128, 0, false>,
                         cudaFuncAttributeMaxDynamicSharedMemorySize, SMEM_128);
    cudaFuncSetAttribute(gemm2<128, 1, false>,
                         cudaFuncAttributeMaxDynamicSharedMemorySize, SMEM_128);
    cudaFuncSetAttribute(gemm2<64, 2, true>,
                         cudaFuncAttributeMaxDynamicSharedMemorySize, SMEM_64);

    bf16* lnh = symaddr<bf16>(g_lnh);  bf16* lnl = symaddr<bf16>(g_lnl);
    bf16* qh  = symaddr<bf16>(g_qh);   bf16* ql  = symaddr<bf16>(g_ql);
    bf16* kh  = symaddr<bf16>(g_kh);   bf16* kl  = symaddr<bf16>(g_kl);
    bf16* vh  = symaddr<bf16>(g_vh);   bf16* vl  = symaddr<bf16>(g_vl);
    float* x1 = symaddr<float>(g_x1);
    float* sc = symaddr<float>(g_sc);
    bf16* p16  = (bf16*)sc;                              // P split rows
    bf16* hidh = (bf16*)sc;                              // FFN hidden planes
    bf16* hidl = hidh + (size_t)MROWS * HFF;

    // 1) LN1 -> split planes
    ln_kernel<<<MROWS, 256>>>(x, lnh, lnl, alpha, beta);

    // 2) Q, K, V projections (split out)
    dim3 gw(DIM / 128, MROWS / 128, 1);
    gemm2<128, 0, true><<<gw, 256, SMEM_128>>>(
        lnh, lnl, DIM, 0, 0,
        wq, nullptr, nullptr, DIM, 0, 0,
        nullptr, qh, ql, DIM, 0, 0,
        1, DIM, bq, nullptr, 0, 1.f, 0);
    gemm2<128, 0, true><<<gw, 256, SMEM_128>>>(
        lnh, lnl, DIM, 0, 0,
        wk, nullptr, nullptr, DIM, 0, 0,
        nullptr, kh, kl, DIM, 0, 0,
        1, DIM, bk, nullptr, 0, 1.f, 0);
    gemm2<128, 0, true><<<gw, 256, SMEM_128>>>(
        lnh, lnl, DIM, 0, 0,
        wv, nullptr, nullptr, DIM, 0, 0,
        nullptr, vh, vl, DIM, 0, 0,
        1, DIM, bv, nullptr, 0, 1.f, 0);

    // 3) scores = Q K^T / 8  (both operands split, fp32 out)
    dim3 gs(SEQ / 128, SEQ / 128, BATCH * HEADS);
    gemm2<128, 1, false><<<gs, 256, SMEM_128>>>(
        qh, ql, DIM, (long)SEQ * DIM, DH,
        nullptr, kh, kl, DIM, (long)SEQ * DIM, DH,
        sc, nullptr, nullptr, SEQ, (long)HEADS * SEQ * SEQ, (long)SEQ * SEQ,
        HEADS, DH, nullptr, nullptr, 0, 0.125f, 0);

    // 4) softmax (in-place fp32 -> split-bf16 rows)
    softmax_kernel<<<BATCH * HEADS * SEQ, 256>>>(sc);

    // 5) PV: A = P split rows (stride 2*SEQ), B = V split n-contig; out split
    dim3 gp(1, SEQ / 128, BATCH * HEADS);
    gemm2<64, 2, true><<<gp, 256, SMEM_64>>>(
        p16, p16 + SEQ, 2 * SEQ, 16L * SEQ * 2 * SEQ, (long)SEQ * 2 * SEQ,
        nullptr, vh, vl, DIM, (long)SEQ * DIM, DH,
        nullptr, lnh, lnl, DIM, (long)SEQ * DIM, DH,
        HEADS, SEQ, nullptr, nullptr, 0, 1.f, 0);

    // 6) O projection + residual x -> x1 (fp32)
    gemm2<128, 0, false><<<gw, 256, SMEM_128>>>(
        lnh, lnl, DIM, 0, 0,
        wo, nullptr, nullptr, DIM, 0, 0,
        x1, nullptr, nullptr, DIM, 0, 0,
        1, DIM, bo, x, DIM, 1.f, 0);

    // 7) LN2 -> split planes
    ln_kernel<<<MROWS, 256>>>(x1, lnh, lnl, alpha, beta);

    // 8) FFN1 (+ReLU) -> split hidden planes
    dim3 gf1(HFF / 128, MROWS / 128, 1);
    gemm2<128, 0, true><<<gf1, 256, SMEM_128>>>(
        lnh, lnl, DIM, 0, 0,
        w1, nullptr, nullptr, DIM, 0, 0,
        nullptr, hidh, hidl, HFF, 0, 0,
        1, DIM, b1, nullptr, 0, 1.f, 1);

    // 9) FFN2 + residual x1 -> out (fp32)
    dim3 gf2(DIM / 128, MROWS / 128, 1);
    gemm2<128, 0, false><<<gf2, 256, SMEM_128>>>(
        hidh, hidl, HFF, 0, 0,
        w2, nullptr, nullptr, HFF, 0, 0,
        out, nullptr, nullptr, DIM, 0, 0,
        1, HFF, b2, x1, DIM, 1.f, 0);
}

// round 7
// speedup vs baseline: 2.5400x; 1.1388x over previous
#include <cuda_runtime.h>
#include <cuda_bf16.h>
#include <math.h>
#include <stdint.h>

#define BATCH 8
#define SEQ   1024
#define DIM   1024
#define HEADS 16
#define DH    64
#define HFF   4096
#define MROWS (BATCH*SEQ)   // 8192

typedef __nv_bfloat16 bf16;

// ---------------- scratch (static device arrays: allocation-free) ----------
__device__ bf16 g_lnh[(size_t)MROWS*DIM], g_lnl[(size_t)MROWS*DIM];
__device__ bf16 g_qh [(size_t)MROWS*DIM], g_ql [(size_t)MROWS*DIM];
__device__ bf16 g_kh [(size_t)MROWS*DIM], g_kl [(size_t)MROWS*DIM];
__device__ bf16 g_vh [(size_t)MROWS*DIM], g_vl [(size_t)MROWS*DIM];
__device__ float g_x1[(size_t)MROWS*DIM];
// scores fp32; softmax rewrites rows in place as [hi(1024)|lo(1024)] bf16.
__device__ float g_sc[(size_t)BATCH*HEADS*SEQ*SEQ];
// split-bf16 weight planes: wq|wk|wv|wo (1M each) then w1 (4M) then w2 (4M)
#define WOFF_Q  0
#define WOFF_K  ((size_t)DIM*DIM)
#define WOFF_V  ((size_t)2*DIM*DIM)
#define WOFF_O  ((size_t)3*DIM*DIM)
#define WOFF_1  ((size_t)4*DIM*DIM)
#define WOFF_2  ((size_t)4*DIM*DIM + (size_t)HFF*DIM)
__device__ bf16 g_wh[(size_t)4*DIM*DIM + (size_t)2*HFF*DIM];
__device__ bf16 g_wl[(size_t)4*DIM*DIM + (size_t)2*HFF*DIM];

// ==================== helpers ====================
__device__ __forceinline__ uint32_t smem_u32(const void* p) {
    uint32_t a;
    asm("{ .reg .u64 t; cvta.to.shared.u64 t, %1; cvt.u32.u64 %0, t; }"
        : "=r"(a) : "l"(p));
    return a;
}
__device__ __forceinline__ void cp_async16(uint32_t dst, const void* src) {
    uint64_t g;
    asm("cvta.to.global.u64 %0, %1;" : "=l"(g) : "l"(src));
    asm volatile("cp.async.cg.shared.global [%0], [%1], 16;"
                 :: "r"(dst), "l"(g) : "memory");
}
#define CP_COMMIT() asm volatile("cp.async.commit_group;" ::: "memory")
#define CP_WAIT0()  asm volatile("cp.async.wait_group 0;"  ::: "memory")

__device__ __forceinline__ void cvt2(float a, float b, uint32_t& h, uint32_t& l) {
    __nv_bfloat162 hh = __floats2bfloat162_rn(a, b);
    float ra = a - __bfloat162float(hh.x);
    float rb = b - __bfloat162float(hh.y);
    __nv_bfloat162 ll = __floats2bfloat162_rn(ra, rb);
    h = *(uint32_t*)&hh;
    l = *(uint32_t*)&ll;
}

#define LDM4(r0, r1, r2, r3, addr) \
    asm volatile("ldmatrix.sync.aligned.m8n8.x4.shared.b16 {%0,%1,%2,%3}, [%4];" \
                 : "=r"(r0), "=r"(r1), "=r"(r2), "=r"(r3) : "r"(addr))
#define LDM2(r0, r1, addr) \
    asm volatile("ldmatrix.sync.aligned.m8n8.x2.shared.b16 {%0,%1}, [%2];" \
                 : "=r"(r0), "=r"(r1) : "r"(addr))
#define MMA16816(c, a, b) \
    asm volatile("mma.sync.aligned.m16n8k16.row.col.f32.bf16.bf16.f32 " \
                 "{%0,%1,%2,%3}, {%4,%5,%6,%7}, {%8,%9}, {%0,%1,%2,%3};" \
                 : "+f"((c)[0]), "+f"((c)[1]), "+f"((c)[2]), "+f"((c)[3]) \
                 : "r"((a)[0]), "r"((a)[1]), "r"((a)[2]), "r"((a)[3]), \
                   "r"((b)[0]), "r"((b)[1]))

// ---------------- weight fp32 -> split-bf16 planes -------------------------
__global__ __launch_bounds__(256) void wconv(const float* __restrict__ w,
                                             bf16* __restrict__ h,
                                             bf16* __restrict__ l, int n4) {
    const int i = blockIdx.x * 256 + threadIdx.x;
    if (i >= n4) return;
    const float4 v = ((const float4*)w)[i];
    uint32_t h0, l0, h1, l1;
    cvt2(v.x, v.y, h0, l0);
    cvt2(v.z, v.w, h1, l1);
    ((uint2*)h)[i] = make_uint2(h0, h1);
    ((uint2*)l)[i] = make_uint2(l0, l1);
}

// ==================== split-bf16 mma.sync GEMM v3 ====================
// C[m,n] = scale * sum_k A[m,k]*B[n,k] (+bias, +relu, +resid)
// A: split-bf16 K-major planes -> cp.async.
// B: BMODE 1 = split-bf16 K-major -> cp.async
//    BMODE 2 = split-bf16 n-contiguous (PV's V) -> LDG + prmt transpose + STS
// smem rows padded to 80B -> conflict-free ldmatrix.
template<int BN, int BMODE, bool OSPLIT>
__global__ __launch_bounds__(256, 2) void gemm3(
    const bf16* __restrict__ Ah, const bf16* __restrict__ Al,
    int lda, long sA0, long sA1,
    const bf16* __restrict__ Bh, const bf16* __restrict__ Bl,
    int ldb, long sB0, long sB1,
    float* __restrict__ Cf,
    bf16* __restrict__ Ch, bf16* __restrict__ Cl,
    int ldc, long sC0, long sC1,
    int zdiv, int K,
    const float* __restrict__ bias,
    const float* __restrict__ resid, int ldr,
    float scale, int relu)
{
    constexpr int BK = 32;
    constexpr int WN = BN / 4, NT = WN / 8;
    constexpr int ABYTES = 128 * 80;
    constexpr int BBYTES = BN * 80;
    constexpr int SS = 2 * ABYTES + 2 * BBYTES;

    extern __shared__ char sm[];
    const uint32_t smBase = smem_u32(sm);

    const int tid = threadIdx.x, wid = tid >> 5, lane = tid & 31;
    const int wm = wid >> 2, wn = wid & 3;
    const int z = blockIdx.z, z0 = z / zdiv, z1 = z - z0 * zdiv;
    Ah += z0 * sA0 + z1 * sA1;
    Al += z0 * sA0 + z1 * sA1;
    Bh += z0 * sB0 + z1 * sB1;
    Bl += z0 * sB0 + z1 * sB1;
    const long coff = z0 * sC0 + z1 * sC1;
    if constexpr (OSPLIT) { Ch += coff; Cl += coff; } else { Cf += coff; }
    const int m0 = blockIdx.y * 128, n0 = blockIdx.x * BN;

    float acc[4][NT][4];
#pragma unroll
    for (int i = 0; i < 4; i++)
#pragma unroll
        for (int j = 0; j < NT; j++)
#pragma unroll
            for (int r = 0; r < 4; r++) acc[i][j][r] = 0.f;

    uint32_t rn0[4], rn1[4];   // BMODE2 staging

    auto issueA = [&](int s, int t) {
        const uint32_t sA = smBase + s * SS;
#pragma unroll
        for (int i = 0; i < 4; i++) {
            const int idx = i * 256 + tid;
            const int c = idx & 3, row = (idx >> 2) & 127, pl = idx >> 9;
            const bf16* g = (pl ? Al : Ah) + (size_t)(m0 + row) * lda + t * BK + c * 8;
            cp_async16(sA + pl * ABYTES + row * 80 + c * 16, g);
        }
    };
    auto issueB1 = [&](int s, int t) {
        const uint32_t sB = smBase + s * SS + 2 * ABYTES;
#pragma unroll
        for (int i = 0; i < 4; i++) {
            const int idx = i * 256 + tid;
            const int c = idx & 3, row = (idx >> 2) & 127, pl = idx >> 9;
            const bf16* g = (pl ? Bl : Bh) + (size_t)(n0 + row) * ldb + t * BK + c * 8;
            cp_async16(sB + pl * BBYTES + row * 80 + c * 16, g);
        }
    };
    auto ldgB2 = [&](int t) {
#pragma unroll
        for (int i = 0; i < 4; i++) {
            const int id = i * 256 + tid;
            const int pl = id >> 9, rem = id & 511;
            const int kp = rem >> 5, n2 = rem & 31;
            const bf16* g = (pl ? Bl : Bh) + (size_t)(t * BK + 2 * kp) * ldb + n0 + 2 * n2;
            rn0[i] = *(const uint32_t*)g;
            rn1[i] = *(const uint32_t*)(g + ldb);
        }
    };
    auto stsB2 = [&](int s) {
        char* bb = sm + s * SS + 2 * ABYTES;
#pragma unroll
        for (int i = 0; i < 4; i++) {
            const int id = i * 256 + tid;
            const int pl = id >> 9, rem = id & 511;
            const int kp = rem >> 5, n2 = rem & 31;
            const uint32_t o0 = __byte_perm(rn0[i], rn1[i], 0x5410);
            const uint32_t o1 = __byte_perm(rn0[i], rn1[i], 0x7632);
            char* p = bb + pl * BBYTES + (2 * n2) * 80 + kp * 4;
            *(uint32_t*)p = o0;
            *(uint32_t*)(p + 80) = o1;
        }
    };

    auto compute = [&](int s) {
        const uint32_t aHiB = smBase + s * SS;
        const uint32_t aLoB = aHiB + ABYTES;
        const uint32_t bHiB = aHiB + 2 * ABYTES;
        const uint32_t bLoB = bHiB + BBYTES;
#pragma unroll
        for (int ks = 0; ks < 2; ks++) {
            uint32_t bh[NT][2], bl[NT][2];
            const uint32_t kbB = (uint32_t)((ks * 16 + ((lane >> 3) & 1) * 8) * 2);
#pragma unroll
            for (int nt = 0; nt < NT; nt++) {
                const uint32_t rb = (uint32_t)((wn * WN + nt * 8 + (lane & 7)) * 80) + kbB;
                LDM2(bh[nt][0], bh[nt][1], bHiB + rb);
                LDM2(bl[nt][0], bl[nt][1], bLoB + rb);
            }
            const uint32_t kbA = (uint32_t)((ks * 16 + (lane >> 4) * 8) * 2);
#pragma unroll
            for (int mt = 0; mt < 4; mt++) {
                uint32_t ah[4], al[4];
                const uint32_t ra = (uint32_t)((wm * 64 + mt * 16 + (lane & 15)) * 80) + kbA;
                LDM4(ah[0], ah[1], ah[2], ah[3], aHiB + ra);
                LDM4(al[0], al[1], al[2], al[3], aLoB + ra);
#pragma unroll
                for (int nt = 0; nt < NT; nt++) MMA16816(acc[mt][nt], ah, bh[nt]);
#pragma unroll
                for (int nt = 0; nt < NT; nt++) MMA16816(acc[mt][nt], ah, bl[nt]);
#pragma unroll
                for (int nt = 0; nt < NT; nt++) MMA16816(acc[mt][nt], al, bh[nt]);
            }
        }
    };

    const int T = K / BK;
    issueA(0, 0);
    if constexpr (BMODE == 1) issueB1(0, 0);
    CP_COMMIT();
    if constexpr (BMODE == 2) { ldgB2(0); stsB2(0); }
    CP_WAIT0();
    __syncthreads();

    for (int t = 0; t < T; t++) {
        const int s = t & 1;
        if (t + 1 < T) {
            issueA(s ^ 1, t + 1);
            if constexpr (BMODE == 1) issueB1(s ^ 1, t + 1);
            CP_COMMIT();
            if constexpr (BMODE == 2) ldgB2(t + 1);
        }
        compute(s);
        if (t + 1 < T) {
            if constexpr (BMODE == 2) stsB2(s ^ 1);
        }
        CP_WAIT0();
        __syncthreads();
    }

    // epilogue
#pragma unroll
    for (int mt = 0; mt < 4; mt++) {
#pragma unroll
        for (int nt = 0; nt < NT; nt++) {
            const int r0 = m0 + wm * 64 + mt * 16 + (lane >> 2);
            const int cc = n0 + wn * WN + nt * 8 + (lane & 3) * 2;
#pragma unroll
            for (int h = 0; h < 2; h++) {
                const int m = r0 + h * 8;
                float vx = acc[mt][nt][2 * h]     * scale;
                float vy = acc[mt][nt][2 * h + 1] * scale;
                if (bias)  { vx += bias[cc]; vy += bias[cc + 1]; }
                if (relu)  { vx = fmaxf(vx, 0.f); vy = fmaxf(vy, 0.f); }
                if (resid) {
                    const float2 rr = *(const float2*)(resid + (size_t)m * ldr + cc);
                    vx += rr.x; vy += rr.y;
                }
                if constexpr (OSPLIT) {
                    uint32_t hh, ll;
                    cvt2(vx, vy, hh, ll);
                    *(uint32_t*)(Ch + (size_t)m * ldc + cc) = hh;
                    *(uint32_t*)(Cl + (size_t)m * ldc + cc) = ll;
                } else {
                    *(float2*)(Cf + (size_t)m * ldc + cc) = make_float2(vx, vy);
                }
            }
        }
    }
}

// ---------------- LayerNorm -> split-bf16 planes ---------------------------
__global__ __launch_bounds__(256) void ln_kernel(const float* __restrict__ x,
                                                 bf16* __restrict__ yh,
                                                 bf16* __restrict__ yl,
                                                 const float* __restrict__ alpha,
                                                 const float* __restrict__ beta) {
    __shared__ float sh_s[8], sh_q[8];
    const size_t row = blockIdx.x;
    const float4* xr = (const float4*)(x + row * DIM);
    const int tid = threadIdx.x;
    float4 v = xr[tid];
    float s = v.x + v.y + v.z + v.w;
    float q = v.x*v.x + v.y*v.y + v.z*v.z + v.w*v.w;
#pragma unroll
    for (int o = 16; o; o >>= 1) {
        s += __shfl_xor_sync(0xffffffffu, s, o);
        q += __shfl_xor_sync(0xffffffffu, q, o);
    }
    if ((tid & 31) == 0) { sh_s[tid >> 5] = s; sh_q[tid >> 5] = q; }
    __syncthreads();
    if (tid < 32) {
        s = (tid < 8) ? sh_s[tid] : 0.f;
        q = (tid < 8) ? sh_q[tid] : 0.f;
#pragma unroll
        for (int o = 4; o; o >>= 1) {
            s += __shfl_xor_sync(0xffffffffu, s, o);
            q += __shfl_xor_sync(0xffffffffu, q, o);
        }
        if (tid == 0) { sh_s[0] = s; sh_q[0] = q; }
    }
    __syncthreads();
    s = sh_s[0]; q = sh_q[0];
    const float mean = s * (1.0f / DIM);
    const float var  = (q - (float)DIM * mean * mean) * (1.0f / (DIM - 1));
    const float inv  = 1.0f / (sqrtf(fmaxf(var, 0.f)) + 1e-6f);
    const float4 a = ((const float4*)alpha)[tid];
    const float4 b = ((const float4*)beta)[tid];
    float ox = a.x * (v.x - mean) * inv + b.x;
    float oy = a.y * (v.y - mean) * inv + b.y;
    float oz = a.z * (v.z - mean) * inv + b.z;
    float ow = a.w * (v.w - mean) * inv + b.w;
    uint32_t h0, l0, h1, l1;
    cvt2(ox, oy, h0, l0);
    cvt2(oz, ow, h1, l1);
    *(uint2*)(yh + row * DIM + 4 * tid) = make_uint2(h0, h1);
    *(uint2*)(yl + row * DIM + 4 * tid) = make_uint2(l0, l1);
}

// ------ row softmax over SEQ=1024, in-place fp32 -> [hi|lo] bf16 row -------
__global__ __launch_bounds__(256) void softmax_kernel(float* __restrict__ p) {
    __shared__ float sh[8];
    __shared__ float bcast;
    float* pr = p + (size_t)blockIdx.x * SEQ;
    const int tid = threadIdx.x;
    float4 v = ((float4*)pr)[tid];
    float m = fmaxf(fmaxf(v.x, v.y), fmaxf(v.z, v.w));
#pragma unroll
    for (int o = 16; o; o >>= 1) m = fmaxf(m, __shfl_xor_sync(0xffffffffu, m, o));
    if ((tid & 31) == 0) sh[tid >> 5] = m;
    __syncthreads();
    if (tid < 32) {
        m = (tid < 8) ? sh[tid] : -INFINITY;
#pragma unroll
        for (int o = 4; o; o >>= 1) m = fmaxf(m, __shfl_xor_sync(0xffffffffu, m, o));
        if (tid == 0) bcast = m;
    }
    __syncthreads();
    m = bcast;
    v.x = __expf(v.x - m); v.y = __expf(v.y - m);
    v.z = __expf(v.z - m); v.w = __expf(v.w - m);
    float s = v.x + v.y + v.z + v.w;
    __syncthreads();
#pragma unroll
    for (int o = 16; o; o >>= 1) s += __shfl_xor_sync(0xffffffffu, s, o);
    if ((tid & 31) == 0) sh[tid >> 5] = s;
    __syncthreads();
    if (tid < 32) {
        s = (tid < 8) ? sh[tid] : 0.f;
#pragma unroll
        for (int o = 4; o; o >>= 1) s += __shfl_xor_sync(0xffffffffu, s, o);
        if (tid == 0) bcast = s;
    }
    __syncthreads();
    const float inv = 1.0f / bcast;
    v.x *= inv; v.y *= inv; v.z *= inv; v.w *= inv;
    uint32_t h0, l0, h1, l1;
    cvt2(v.x, v.y, h0, l0);
    cvt2(v.z, v.w, h1, l1);
    uint16_t* row16 = (uint16_t*)pr;
    *(uint2*)(row16 + 4 * tid)        = make_uint2(h0, h1);
    *(uint2*)(row16 + 1024 + 4 * tid) = make_uint2(l0, l1);
}

// ---------------- launch ----------------------------------------------------
template<typename T>
static T* symaddr(const void* s) {
    void* p = nullptr;
    cudaGetSymbolAddress(&p, s);
    return (T*)p;
}

#define SMEM_128 (2 * (2 * 128 * 80 + 2 * 128 * 80))   // 81920
#define SMEM_64  (2 * (2 * 128 * 80 + 2 *  64 * 80))   // 61440

extern "C" void kernel_launch(void* const* d_in, const int* in_sizes, int n_in,
                              void* d_out, int out_size) {
    (void)in_sizes; (void)n_in; (void)out_size;
    const float* x     = (const float*)d_in[0];
    const float* wq    = (const float*)d_in[2];
    const float* bq    = (const float*)d_in[3];
    const float* wk    = (const float*)d_in[4];
    const float* bk    = (const float*)d_in[5];
    const float* wv    = (const float*)d_in[6];
    const float* bv    = (const float*)d_in[7];
    const float* wo    = (const float*)d_in[8];
    const float* bo    = (const float*)d_in[9];
    const float* w1    = (const float*)d_in[10];
    const float* b1    = (const float*)d_in[11];
    const float* w2    = (const float*)d_in[12];
    const float* b2    = (const float*)d_in[13];
    const float* alpha = (const float*)d_in[14];
    const float* beta  = (const float*)d_in[15];
    float* out = (float*)d_out;

    cudaFuncSetAttribute(gemm3<128, 1, true>,
                         cudaFuncAttributeMaxDynamicSharedMemorySize, SMEM_128);
    cudaFuncSetAttribute(gemm3<128, 1, false>,
                         cudaFuncAttributeMaxDynamicSharedMemorySize, SMEM_128);
    cudaFuncSetAttribute(gemm3<64, 2, true>,
                         cudaFuncAttributeMaxDynamicSharedMemorySize, SMEM_64);

    bf16* lnh = symaddr<bf16>(g_lnh);  bf16* lnl = symaddr<bf16>(g_lnl);
    bf16* qh  = symaddr<bf16>(g_qh);   bf16* ql  = symaddr<bf16>(g_ql);
    bf16* kh  = symaddr<bf16>(g_kh);   bf16* kl  = symaddr<bf16>(g_kl);
    bf16* vh  = symaddr<bf16>(g_vh);   bf16* vl  = symaddr<bf16>(g_vl);
    float* x1 = symaddr<float>(g_x1);
    float* sc = symaddr<float>(g_sc);
    bf16* wh  = symaddr<bf16>(g_wh);   bf16* wl  = symaddr<bf16>(g_wl);
    bf16* p16  = (bf16*)sc;
    bf16* hidh = (bf16*)sc;
    bf16* hidl = hidh + (size_t)MROWS * HFF;

    // 0) weight conversion to split planes (runs concurrently with LN1)
    const int n4p = DIM * DIM / 4, n4f = HFF * DIM / 4;
    wconv<<<(n4p + 255) / 256, 256>>>(wq, wh + WOFF_Q, wl + WOFF_Q, n4p);
    wconv<<<(n4p + 255) / 256, 256>>>(wk, wh + WOFF_K, wl + WOFF_K, n4p);
    wconv<<<(n4p + 255) / 256, 256>>>(wv, wh + WOFF_V, wl + WOFF_V, n4p);
    wconv<<<(n4p + 255) / 256, 256>>>(wo, wh + WOFF_O, wl + WOFF_O, n4p);
    wconv<<<(n4f + 255) / 256, 256>>>(w1, wh + WOFF_1, wl + WOFF_1, n4f);
    wconv<<<(n4f + 255) / 256, 256>>>(w2, wh + WOFF_2, wl + WOFF_2, n4f);

    // 1) LN1
    ln_kernel<<<MROWS, 256>>>(x, lnh, lnl, alpha, beta);

    // 2) Q, K, V projections
    dim3 gw(DIM / 128, MROWS / 128, 1);
    gemm3<128, 1, true><<<gw, 256, SMEM_128>>>(
        lnh, lnl, DIM, 0, 0,
        wh + WOFF_Q, wl + WOFF_Q, DIM, 0, 0,
        nullptr, qh, ql, DIM, 0, 0,
        1, DIM, bq, nullptr, 0, 1.f, 0);
    gemm3<128, 1, true><<<gw, 256, SMEM_128>>>(
        lnh, lnl, DIM, 0, 0,
        wh + WOFF_K, wl + WOFF_K, DIM, 0, 0,
        nullptr, kh, kl, DIM, 0, 0,
        1, DIM, bk, nullptr, 0, 1.f, 0);
    gemm3<128, 1, true><<<gw, 256, SMEM_128>>>(
        lnh, lnl, DIM, 0, 0,
        wh + WOFF_V, wl + WOFF_V, DIM, 0, 0,
        nullptr, vh, vl, DIM, 0, 0,
        1, DIM, bv, nullptr, 0, 1.f, 0);

    // 3) scores = Q K^T / 8
    dim3 gs(SEQ / 128, SEQ / 128, BATCH * HEADS);
    gemm3<128, 1, false><<<gs, 256, SMEM_128>>>(
        qh, ql, DIM, (long)SEQ * DIM, DH,
        kh, kl, DIM, (long)SEQ * DIM, DH,
        sc, nullptr, nullptr, SEQ, (long)HEADS * SEQ * SEQ, (long)SEQ * SEQ,
        HEADS, DH, nullptr, nullptr, 0, 0.125f, 0);

    // 4) softmax (in-place fp32 -> split-bf16 rows)
    softmax_kernel<<<BATCH * HEADS * SEQ, 256>>>(sc);

    // 5) PV
    dim3 gp(1, SEQ / 128, BATCH * HEADS);
    gemm3<64, 2, true><<<gp, 256, SMEM_64>>>(
        p16, p16 + SEQ, 2 * SEQ, 16L * SEQ * 2 * SEQ, (long)SEQ * 2 * SEQ,
        vh, vl, DIM, (long)SEQ * DIM, DH,
        nullptr, lnh, lnl, DIM, (long)SEQ * DIM, DH,
        HEADS, SEQ, nullptr, nullptr, 0, 1.f, 0);

    // 6) O projection + residual x -> x1 (fp32)
    gemm3<128, 1, false><<<gw, 256, SMEM_128>>>(
        lnh, lnl, DIM, 0, 0,
        wh + WOFF_O, wl + WOFF_O, DIM, 0, 0,
        x1, nullptr, nullptr, DIM, 0, 0,
        1, DIM, bo, x, DIM, 1.f, 0);

    // 7) LN2
    ln_kernel<<<MROWS, 256>>>(x1, lnh, lnl, alpha, beta);

    // 8) FFN1 (+ReLU)
    dim3 gf1(HFF / 128, MROWS / 128, 1);
    gemm3<128, 1, true><<<gf1, 256, SMEM_128>>>(
        lnh, lnl, DIM, 0, 0,
        wh + WOFF_1, wl + WOFF_1, DIM, 0, 0,
        nullptr, hidh, hidl, HFF, 0, 0,
        1, DIM, b1, nullptr, 0, 1.f, 1);

    // 9) FFN2 + residual x1 -> out (fp32)
    dim3 gf2(DIM / 128, MROWS / 128, 1);
    gemm3<128, 1, false><<<gf2, 256, SMEM_128>>>(
        hidh, hidl, HFF, 0, 0,
        wh + WOFF_2, wl + WOFF_2, HFF, 0, 0,
        out, nullptr, nullptr, DIM, 0, 0,
        1, HFF, b2, x1, DIM, 1.f, 0);
}

// round 8
// speedup vs baseline: 2.9562x; 1.1639x over previous
#include <cuda_runtime.h>
#include <cuda_bf16.h>
#include <math.h>
#include <stdint.h>

#define BATCH 8
#define SEQ   1024
#define DIM   1024
#define HEADS 16
#define DH    64
#define HFF   4096
#define MROWS (BATCH*SEQ)   // 8192

typedef __nv_bfloat16 bf16;

// ---------------- scratch (static device arrays: allocation-free) ----------
__device__ bf16 g_lnh[(size_t)MROWS*DIM], g_lnl[(size_t)MROWS*DIM];
__device__ bf16 g_qh [(size_t)MROWS*DIM], g_ql [(size_t)MROWS*DIM];
__device__ bf16 g_kh [(size_t)MROWS*DIM], g_kl [(size_t)MROWS*DIM];
__device__ bf16 g_vh [(size_t)MROWS*DIM], g_vl [(size_t)MROWS*DIM];
__device__ float g_x1[(size_t)MROWS*DIM];
// FFN hidden split planes
__device__ bf16 g_hid[(size_t)2*MROWS*HFF];
// split-bf16 weight planes
#define WOFF_Q  0
#define WOFF_K  ((size_t)DIM*DIM)
#define WOFF_V  ((size_t)2*DIM*DIM)
#define WOFF_O  ((size_t)3*DIM*DIM)
#define WOFF_1  ((size_t)4*DIM*DIM)
#define WOFF_2  ((size_t)4*DIM*DIM + (size_t)HFF*DIM)
__device__ bf16 g_wh[(size_t)4*DIM*DIM + (size_t)2*HFF*DIM];
__device__ bf16 g_wl[(size_t)4*DIM*DIM + (size_t)2*HFF*DIM];

// ==================== helpers ====================
__device__ __forceinline__ uint32_t smem_u32(const void* p) {
    uint32_t a;
    asm("{ .reg .u64 t; cvta.to.shared.u64 t, %1; cvt.u32.u64 %0, t; }"
        : "=r"(a) : "l"(p));
    return a;
}
__device__ __forceinline__ void cp_async16(uint32_t dst, const void* src) {
    uint64_t g;
    asm("cvta.to.global.u64 %0, %1;" : "=l"(g) : "l"(src));
    asm volatile("cp.async.cg.shared.global [%0], [%1], 16;"
                 :: "r"(dst), "l"(g) : "memory");
}
#define CP_COMMIT() asm volatile("cp.async.commit_group;" ::: "memory")
#define CP_WAIT0()  asm volatile("cp.async.wait_group 0;"  ::: "memory")

__device__ __forceinline__ void cvt2(float a, float b, uint32_t& h, uint32_t& l) {
    __nv_bfloat162 hh = __floats2bfloat162_rn(a, b);
    float ra = a - __bfloat162float(hh.x);
    float rb = b - __bfloat162float(hh.y);
    __nv_bfloat162 ll = __floats2bfloat162_rn(ra, rb);
    h = *(uint32_t*)&hh;
    l = *(uint32_t*)&ll;
}

#define LDM4(r0, r1, r2, r3, addr) \
    asm volatile("ldmatrix.sync.aligned.m8n8.x4.shared.b16 {%0,%1,%2,%3}, [%4];" \
                 : "=r"(r0), "=r"(r1), "=r"(r2), "=r"(r3) : "r"(addr))
#define LDM2(r0, r1, addr) \
    asm volatile("ldmatrix.sync.aligned.m8n8.x2.shared.b16 {%0,%1}, [%2];" \
                 : "=r"(r0), "=r"(r1) : "r"(addr))
#define LDM2T(r0, r1, addr) \
    asm volatile("ldmatrix.sync.aligned.m8n8.x2.trans.shared.b16 {%0,%1}, [%2];" \
                 : "=r"(r0), "=r"(r1) : "r"(addr))
#define MMA16816(c, a, b) \
    asm volatile("mma.sync.aligned.m16n8k16.row.col.f32.bf16.bf16.f32 " \
                 "{%0,%1,%2,%3}, {%4,%5,%6,%7}, {%8,%9}, {%0,%1,%2,%3};" \
                 : "+f"((c)[0]), "+f"((c)[1]), "+f"((c)[2]), "+f"((c)[3]) \
                 : "r"((a)[0]), "r"((a)[1]), "r"((a)[2]), "r"((a)[3]), \
                   "r"((b)[0]), "r"((b)[1]))

// ---------------- weight fp32 -> split-bf16 planes -------------------------
__global__ __launch_bounds__(256) void wconv(const float* __restrict__ w,
                                             bf16* __restrict__ h,
                                             bf16* __restrict__ l, int n4) {
    const int i = blockIdx.x * 256 + threadIdx.x;
    if (i >= n4) return;
    const float4 v = ((const float4*)w)[i];
    uint32_t h0, l0, h1, l1;
    cvt2(v.x, v.y, h0, l0);
    cvt2(v.z, v.w, h1, l1);
    ((uint2*)h)[i] = make_uint2(h0, h1);
    ((uint2*)l)[i] = make_uint2(l0, l1);
}

// ==================== split-bf16 mma.sync GEMM (weights path) ==============
// C[m,n] = scale * sum_k A[m,k]*B[n,k] (+bias, +relu, +resid)
template<int BN, bool OSPLIT>
__global__ __launch_bounds__(256, 2) void gemm3(
    const bf16* __restrict__ Ah, const bf16* __restrict__ Al, int lda,
    const bf16* __restrict__ Bh, const bf16* __restrict__ Bl, int ldb,
    float* __restrict__ Cf,
    bf16* __restrict__ Ch, bf16* __restrict__ Cl, int ldc,
    int K,
    const float* __restrict__ bias,
    const float* __restrict__ resid, int ldr,
    float scale, int relu)
{
    constexpr int BK = 32;
    constexpr int WN = BN / 4, NT = WN / 8;
    constexpr int ABYTES = 128 * 80;
    constexpr int BBYTES = BN * 80;
    constexpr int SS = 2 * ABYTES + 2 * BBYTES;

    extern __shared__ char sm[];
    const uint32_t smBase = smem_u32(sm);

    const int tid = threadIdx.x, wid = tid >> 5, lane = tid & 31;
    const int wm = wid >> 2, wn = wid & 3;
    const int m0 = blockIdx.y * 128, n0 = blockIdx.x * BN;

    float acc[4][NT][4];
#pragma unroll
    for (int i = 0; i < 4; i++)
#pragma unroll
        for (int j = 0; j < NT; j++)
#pragma unroll
            for (int r = 0; r < 4; r++) acc[i][j][r] = 0.f;

    auto issueA = [&](int s, int t) {
        const uint32_t sA = smBase + s * SS;
#pragma unroll
        for (int i = 0; i < 4; i++) {
            const int idx = i * 256 + tid;
            const int c = idx & 3, row = (idx >> 2) & 127, pl = idx >> 9;
            const bf16* g = (pl ? Al : Ah) + (size_t)(m0 + row) * lda + t * BK + c * 8;
            cp_async16(sA + pl * ABYTES + row * 80 + c * 16, g);
        }
    };
    auto issueB = [&](int s, int t) {
        const uint32_t sB = smBase + s * SS + 2 * ABYTES;
#pragma unroll
        for (int i = 0; i < 4; i++) {
            const int idx = i * 256 + tid;
            const int c = idx & 3, row = (idx >> 2) & 127, pl = idx >> 9;
            const bf16* g = (pl ? Bl : Bh) + (size_t)(n0 + row) * ldb + t * BK + c * 8;
            cp_async16(sB + pl * BBYTES + row * 80 + c * 16, g);
        }
    };

    auto compute = [&](int s) {
        const uint32_t aHiB = smBase + s * SS;
        const uint32_t aLoB = aHiB + ABYTES;
        const uint32_t bHiB = aHiB + 2 * ABYTES;
        const uint32_t bLoB = bHiB + BBYTES;
#pragma unroll
        for (int ks = 0; ks < 2; ks++) {
            uint32_t bh[NT][2], bl[NT][2];
            const uint32_t kbB = (uint32_t)((ks * 16 + ((lane >> 3) & 1) * 8) * 2);
#pragma unroll
            for (int nt = 0; nt < NT; nt++) {
                const uint32_t rb = (uint32_t)((wn * WN + nt * 8 + (lane & 7)) * 80) + kbB;
                LDM2(bh[nt][0], bh[nt][1], bHiB + rb);
                LDM2(bl[nt][0], bl[nt][1], bLoB + rb);
            }
            const uint32_t kbA = (uint32_t)((ks * 16 + (lane >> 4) * 8) * 2);
#pragma unroll
            for (int mt = 0; mt < 4; mt++) {
                uint32_t ah[4], al[4];
                const uint32_t ra = (uint32_t)((wm * 64 + mt * 16 + (lane & 15)) * 80) + kbA;
                LDM4(ah[0], ah[1], ah[2], ah[3], aHiB + ra);
                LDM4(al[0], al[1], al[2], al[3], aLoB + ra);
#pragma unroll
                for (int nt = 0; nt < NT; nt++) MMA16816(acc[mt][nt], ah, bh[nt]);
#pragma unroll
                for (int nt = 0; nt < NT; nt++) MMA16816(acc[mt][nt], ah, bl[nt]);
#pragma unroll
                for (int nt = 0; nt < NT; nt++) MMA16816(acc[mt][nt], al, bh[nt]);
            }
        }
    };

    const int T = K / BK;
    issueA(0, 0);
    issueB(0, 0);
    CP_COMMIT();
    CP_WAIT0();
    __syncthreads();

    for (int t = 0; t < T; t++) {
        const int s = t & 1;
        if (t + 1 < T) {
            issueA(s ^ 1, t + 1);
            issueB(s ^ 1, t + 1);
            CP_COMMIT();
        }
        compute(s);
        CP_WAIT0();
        __syncthreads();
    }

#pragma unroll
    for (int mt = 0; mt < 4; mt++) {
#pragma unroll
        for (int nt = 0; nt < NT; nt++) {
            const int r0 = m0 + wm * 64 + mt * 16 + (lane >> 2);
            const int cc = n0 + wn * WN + nt * 8 + (lane & 3) * 2;
#pragma unroll
            for (int h = 0; h < 2; h++) {
                const int m = r0 + h * 8;
                float vx = acc[mt][nt][2 * h]     * scale;
                float vy = acc[mt][nt][2 * h + 1] * scale;
                if (bias)  { vx += bias[cc]; vy += bias[cc + 1]; }
                if (relu)  { vx = fmaxf(vx, 0.f); vy = fmaxf(vy, 0.f); }
                if (resid) {
                    const float2 rr = *(const float2*)(resid + (size_t)m * ldr + cc);
                    vx += rr.x; vy += rr.y;
                }
                if constexpr (OSPLIT) {
                    uint32_t hh, ll;
                    cvt2(vx, vy, hh, ll);
                    *(uint32_t*)(Ch + (size_t)m * ldc + cc) = hh;
                    *(uint32_t*)(Cl + (size_t)m * ldc + cc) = ll;
                } else {
                    *(float2*)(Cf + (size_t)m * ldc + cc) = make_float2(vx, vy);
                }
            }
        }
    }
}

// ==================== fused flash attention ====================
// Grid (SEQ/64, BATCH*HEADS), 128 threads (4 warps x 16 q-rows).
// Q tile resident; loop 8 KV tiles of 128 positions.
// S = (Q K^T)/8 via 3-MMA split (fp32-accurate), online softmax,
// P split to bf16 hi/lo in registers, O += P V via 3-MMA with
// ldmatrix.trans B-frags from row-major V.
#define FQ_PL 9216      // 64 rows * 144B per plane
#define FK_PL 18432     // 128 rows * 144B per plane
#define FSMEM (2*FQ_PL + 4*FK_PL)   // 92160

__global__ __launch_bounds__(128, 2) void flash_attn(
    const bf16* __restrict__ qh, const bf16* __restrict__ ql,
    const bf16* __restrict__ kh, const bf16* __restrict__ kl,
    const bf16* __restrict__ vh, const bf16* __restrict__ vl,
    bf16* __restrict__ oh, bf16* __restrict__ ol)
{
    extern __shared__ char sm[];
    const uint32_t smBase = smem_u32(sm);
    const int tid = threadIdx.x, lane = tid & 31, w = tid >> 5;
    const int b = blockIdx.y >> 4, h = blockIdx.y & 15;
    const size_t rowQ  = (size_t)b * SEQ + blockIdx.x * 64;
    const size_t rowKV = (size_t)b * SEQ;
    const int colh = h * DH;

    const uint32_t sQ = smBase;                 // 2 planes FQ_PL
    const uint32_t sK = smBase + 2 * FQ_PL;     // 2 planes FK_PL
    const uint32_t sV = sK + 2 * FK_PL;         // 2 planes FK_PL

    // Q (once) + KV tile 0
#pragma unroll
    for (int i = 0; i < 8; i++) {
        const int idx = i * 128 + tid;
        const int pl = idx >> 9, row = (idx >> 3) & 63, c = idx & 7;
        const bf16* g = (pl ? ql : qh) + (rowQ + row) * DIM + colh + c * 8;
        cp_async16(sQ + pl * FQ_PL + row * 144 + c * 16, g);
    }
    auto loadKV = [&](int kt) {
        const size_t base = (rowKV + kt * 128) * DIM + colh;
#pragma unroll
        for (int i = 0; i < 16; i++) {
            const int idx = i * 128 + tid;
            const int pl = idx >> 10, row = (idx >> 3) & 127, c = idx & 7;
            const size_t off = base + (size_t)row * DIM + c * 8;
            const uint32_t d = pl * FK_PL + row * 144 + c * 16;
            cp_async16(sK + d, (pl ? kl : kh) + off);
            cp_async16(sV + d, (pl ? vl : vh) + off);
        }
    };
    loadKV(0);
    CP_COMMIT(); CP_WAIT0();
    __syncthreads();

    float oacc[8][4];
#pragma unroll
    for (int i = 0; i < 8; i++)
#pragma unroll
        for (int j = 0; j < 4; j++) oacc[i][j] = 0.f;
    float m0 = -INFINITY, m1 = -INFINITY, l0 = 0.f, l1 = 0.f;

    for (int kt = 0; kt < 8; kt++) {
        // ---- S = Q K^T (16 q-rows x 128 kv per warp) ----
        float sfr[16][4];
#pragma unroll
        for (int i = 0; i < 16; i++)
#pragma unroll
            for (int j = 0; j < 4; j++) sfr[i][j] = 0.f;
#pragma unroll
        for (int ks = 0; ks < 4; ks++) {
            uint32_t qa[4], qb[4];
            const uint32_t ra = sQ + (w * 16 + (lane & 15)) * 144
                              + ks * 32 + (lane >> 4) * 16;
            LDM4(qa[0], qa[1], qa[2], qa[3], ra);
            LDM4(qb[0], qb[1], qb[2], qb[3], ra + FQ_PL);
#pragma unroll
            for (int nt = 0; nt < 16; nt++) {
                uint32_t kbh[2], kbl[2];
                const uint32_t rb = sK + (nt * 8 + (lane & 7)) * 144
                                  + ks * 32 + ((lane >> 3) & 1) * 16;
                LDM2(kbh[0], kbh[1], rb);
                LDM2(kbl[0], kbl[1], rb + FK_PL);
                MMA16816(sfr[nt], qa, kbh);
                MMA16816(sfr[nt], qa, kbl);
                MMA16816(sfr[nt], qb, kbh);
            }
        }
        // ---- online softmax (scale 1/8 applied here) ----
        float mx0 = -INFINITY, mx1 = -INFINITY;
#pragma unroll
        for (int nt = 0; nt < 16; nt++) {
            mx0 = fmaxf(mx0, fmaxf(sfr[nt][0], sfr[nt][1]));
            mx1 = fmaxf(mx1, fmaxf(sfr[nt][2], sfr[nt][3]));
        }
        mx0 = fmaxf(mx0, __shfl_xor_sync(0xffffffffu, mx0, 1));
        mx0 = fmaxf(mx0, __shfl_xor_sync(0xffffffffu, mx0, 2));
        mx1 = fmaxf(mx1, __shfl_xor_sync(0xffffffffu, mx1, 1));
        mx1 = fmaxf(mx1, __shfl_xor_sync(0xffffffffu, mx1, 2));
        const float mn0 = fmaxf(m0, 0.125f * mx0);
        const float mn1 = fmaxf(m1, 0.125f * mx1);
        const float f0 = __expf(m0 - mn0);
        const float f1 = __expf(m1 - mn1);
        float rs0 = 0.f, rs1 = 0.f;
#pragma unroll
        for (int nt = 0; nt < 16; nt++) {
            const float p0 = __expf(fmaf(sfr[nt][0], 0.125f, -mn0));
            const float p1 = __expf(fmaf(sfr[nt][1], 0.125f, -mn0));
            const float p2 = __expf(fmaf(sfr[nt][2], 0.125f, -mn1));
            const float p3 = __expf(fmaf(sfr[nt][3], 0.125f, -mn1));
            rs0 += p0 + p1; rs1 += p2 + p3;
            sfr[nt][0] = p0; sfr[nt][1] = p1; sfr[nt][2] = p2; sfr[nt][3] = p3;
        }
        rs0 += __shfl_xor_sync(0xffffffffu, rs0, 1);
        rs0 += __shfl_xor_sync(0xffffffffu, rs0, 2);
        rs1 += __shfl_xor_sync(0xffffffffu, rs1, 1);
        rs1 += __shfl_xor_sync(0xffffffffu, rs1, 2);
        l0 = l0 * f0 + rs0; l1 = l1 * f1 + rs1;
        m0 = mn0; m1 = mn1;
#pragma unroll
        for (int dt = 0; dt < 8; dt++) {
            oacc[dt][0] *= f0; oacc[dt][1] *= f0;
            oacc[dt][2] *= f1; oacc[dt][3] *= f1;
        }
        // ---- O += P V ----
#pragma unroll
        for (int ks = 0; ks < 8; ks++) {
            uint32_t ah[4], al[4];
            cvt2(sfr[2 * ks][0],     sfr[2 * ks][1],     ah[0], al[0]);
            cvt2(sfr[2 * ks][2],     sfr[2 * ks][3],     ah[1], al[1]);
            cvt2(sfr[2 * ks + 1][0], sfr[2 * ks + 1][1], ah[2], al[2]);
            cvt2(sfr[2 * ks + 1][2], sfr[2 * ks + 1][3], ah[3], al[3]);
#pragma unroll
            for (int dt = 0; dt < 8; dt++) {
                uint32_t vbh[2], vbl[2];
                const uint32_t rv = sV + (ks * 16 + (lane & 15)) * 144 + dt * 16;
                LDM2T(vbh[0], vbh[1], rv);
                LDM2T(vbl[0], vbl[1], rv + FK_PL);
                MMA16816(oacc[dt], ah, vbh);
                MMA16816(oacc[dt], ah, vbl);
                MMA16816(oacc[dt], al, vbh);
            }
        }
        if (kt < 7) {
            __syncthreads();
            loadKV(kt + 1);
            CP_COMMIT(); CP_WAIT0();
            __syncthreads();
        }
    }

    // ---- normalize + write split-bf16 planes ----
    const float i0 = 1.f / l0, i1 = 1.f / l1;
    const int r = w * 16 + (lane >> 2);
    const int cc = (lane & 3) * 2;
#pragma unroll
    for (int dt = 0; dt < 8; dt++) {
        uint32_t hh, ll;
        const size_t o0 = (rowQ + r) * DIM + colh + dt * 8 + cc;
        cvt2(oacc[dt][0] * i0, oacc[dt][1] * i0, hh, ll);
        *(uint32_t*)(oh + o0) = hh;
        *(uint32_t*)(ol + o0) = ll;
        const size_t o1 = o0 + 8 * DIM;
        cvt2(oacc[dt][2] * i1, oacc[dt][3] * i1, hh, ll);
        *(uint32_t*)(oh + o1) = hh;
        *(uint32_t*)(ol + o1) = ll;
    }
}

// ---------------- LayerNorm -> split-bf16 planes ---------------------------
__global__ __launch_bounds__(256) void ln_kernel(const float* __restrict__ x,
                                                 bf16* __restrict__ yh,
                                                 bf16* __restrict__ yl,
                                                 const float* __restrict__ alpha,
                                                 const float* __restrict__ beta) {
    __shared__ float sh_s[8], sh_q[8];
    const size_t row = blockIdx.x;
    const float4* xr = (const float4*)(x + row * DIM);
    const int tid = threadIdx.x;
    float4 v = xr[tid];
    float s = v.x + v.y + v.z + v.w;
    float q = v.x*v.x + v.y*v.y + v.z*v.z + v.w*v.w;
#pragma unroll
    for (int o = 16; o; o >>= 1) {
        s += __shfl_xor_sync(0xffffffffu, s, o);
        q += __shfl_xor_sync(0xffffffffu, q, o);
    }
    if ((tid & 31) == 0) { sh_s[tid >> 5] = s; sh_q[tid >> 5] = q; }
    __syncthreads();
    if (tid < 32) {
        s = (tid < 8) ? sh_s[tid] : 0.f;
        q = (tid < 8) ? sh_q[tid] : 0.f;
#pragma unroll
        for (int o = 4; o; o >>= 1) {
            s += __shfl_xor_sync(0xffffffffu, s, o);
            q += __shfl_xor_sync(0xffffffffu, q, o);
        }
        if (tid == 0) { sh_s[0] = s; sh_q[0] = q; }
    }
    __syncthreads();
    s = sh_s[0]; q = sh_q[0];
    const float mean = s * (1.0f / DIM);
    const float var  = (q - (float)DIM * mean * mean) * (1.0f / (DIM - 1));
    const float inv  = 1.0f / (sqrtf(fmaxf(var, 0.f)) + 1e-6f);
    const float4 a = ((const float4*)alpha)[tid];
    const float4 b = ((const float4*)beta)[tid];
    float ox = a.x * (v.x - mean) * inv + b.x;
    float oy = a.y * (v.y - mean) * inv + b.y;
    float oz = a.z * (v.z - mean) * inv + b.z;
    float ow = a.w * (v.w - mean) * inv + b.w;
    uint32_t h0, l0, h1, l1;
    cvt2(ox, oy, h0, l0);
    cvt2(oz, ow, h1, l1);
    *(uint2*)(yh + row * DIM + 4 * tid) = make_uint2(h0, h1);
    *(uint2*)(yl + row * DIM + 4 * tid) = make_uint2(l0, l1);
}

// ---------------- launch ----------------------------------------------------
template<typename T>
static T* symaddr(const void* s) {
    void* p = nullptr;
    cudaGetSymbolAddress(&p, s);
    return (T*)p;
}

#define SMEM_128 (2 * (2 * 128 * 80 + 2 * 128 * 80))   // 81920

extern "C" void kernel_launch(void* const* d_in, const int* in_sizes, int n_in,
                              void* d_out, int out_size) {
    (void)in_sizes; (void)n_in; (void)out_size;
    const float* x     = (const float*)d_in[0];
    const float* wq    = (const float*)d_in[2];
    const float* bq    = (const float*)d_in[3];
    const float* wk    = (const float*)d_in[4];
    const float* bk    = (const float*)d_in[5];
    const float* wv    = (const float*)d_in[6];
    const float* bv    = (const float*)d_in[7];
    const float* wo    = (const float*)d_in[8];
    const float* bo    = (const float*)d_in[9];
    const float* w1    = (const float*)d_in[10];
    const float* b1    = (const float*)d_in[11];
    const float* w2    = (const float*)d_in[12];
    const float* b2    = (const float*)d_in[13];
    const float* alpha = (const float*)d_in[14];
    const float* beta  = (const float*)d_in[15];
    float* out = (float*)d_out;

    cudaFuncSetAttribute(gemm3<128, true>,
                         cudaFuncAttributeMaxDynamicSharedMemorySize, SMEM_128);
    cudaFuncSetAttribute(gemm3<128, false>,
                         cudaFuncAttributeMaxDynamicSharedMemorySize, SMEM_128);
    cudaFuncSetAttribute(flash_attn,
                         cudaFuncAttributeMaxDynamicSharedMemorySize, FSMEM);

    bf16* lnh = symaddr<bf16>(g_lnh);  bf16* lnl = symaddr<bf16>(g_lnl);
    bf16* qh  = symaddr<bf16>(g_qh);   bf16* ql  = symaddr<bf16>(g_ql);
    bf16* kh  = symaddr<bf16>(g_kh);   bf16* kl  = symaddr<bf16>(g_kl);
    bf16* vh  = symaddr<bf16>(g_vh);   bf16* vl  = symaddr<bf16>(g_vl);
    float* x1 = symaddr<float>(g_x1);
    bf16* wh  = symaddr<bf16>(g_wh);   bf16* wl  = symaddr<bf16>(g_wl);
    bf16* hidh = symaddr<bf16>(g_hid);
    bf16* hidl = hidh + (size_t)MROWS * HFF;

    // 0) weight conversion to split planes
    const int n4p = DIM * DIM / 4, n4f = HFF * DIM / 4;
    wconv<<<(n4p + 255) / 256, 256>>>(wq, wh + WOFF_Q, wl + WOFF_Q, n4p);
    wconv<<<(n4p + 255) / 256, 256>>>(wk, wh + WOFF_K, wl + WOFF_K, n4p);
    wconv<<<(n4p + 255) / 256, 256>>>(wv, wh + WOFF_V, wl + WOFF_V, n4p);
    wconv<<<(n4p + 255) / 256, 256>>>(wo, wh + WOFF_O, wl + WOFF_O, n4p);
    wconv<<<(n4f + 255) / 256, 256>>>(w1, wh + WOFF_1, wl + WOFF_1, n4f);
    wconv<<<(n4f + 255) / 256, 256>>>(w2, wh + WOFF_2, wl + WOFF_2, n4f);

    // 1) LN1
    ln_kernel<<<MROWS, 256>>>(x, lnh, lnl, alpha, beta);

    // 2) Q, K, V projections
    dim3 gw(DIM / 128, MROWS / 128, 1);
    gemm3<128, true><<<gw, 256, SMEM_128>>>(
        lnh, lnl, DIM, wh + WOFF_Q, wl + WOFF_Q, DIM,
        nullptr, qh, ql, DIM, DIM, bq, nullptr, 0, 1.f, 0);
    gemm3<128, true><<<gw, 256, SMEM_128>>>(
        lnh, lnl, DIM, wh + WOFF_K, wl + WOFF_K, DIM,
        nullptr, kh, kl, DIM, DIM, bk, nullptr, 0, 1.f, 0);
    gemm3<128, true><<<gw, 256, SMEM_128>>>(
        lnh, lnl, DIM, wh + WOFF_V, wl + WOFF_V, DIM,
        nullptr, vh, vl, DIM, DIM, bv, nullptr, 0, 1.f, 0);

    // 3-5) fused attention -> split planes (into lnh/lnl, reused)
    dim3 gfa(SEQ / 64, BATCH * HEADS, 1);
    flash_attn<<<gfa, 128, FSMEM>>>(qh, ql, kh, kl, vh, vl, lnh, lnl);

    // 6) O projection + residual x -> x1 (fp32)
    gemm3<128, false><<<gw, 256, SMEM_128>>>(
        lnh, lnl, DIM, wh + WOFF_O, wl + WOFF_O, DIM,
        x1, nullptr, nullptr, DIM, DIM, bo, x, DIM, 1.f, 0);

    // 7) LN2
    ln_kernel<<<MROWS, 256>>>(x1, lnh, lnl, alpha, beta);

    // 8) FFN1 (+ReLU)
    dim3 gf1(HFF / 128, MROWS / 128, 1);
    gemm3<128, true><<<gf1, 256, SMEM_128>>>(
        lnh, lnl, DIM, wh + WOFF_1, wl + WOFF_1, DIM,
        nullptr, hidh, hidl, HFF, DIM, b1, nullptr, 0, 1.f, 1);

    // 9) FFN2 + residual x1 -> out (fp32)
    dim3 gf2(DIM / 128, MROWS / 128, 1);
    gemm3<128, false><<<gf2, 256, SMEM_128>>>(
        hidh, hidl, HFF, wh + WOFF_2, wl + WOFF_2, HFF,
        out, nullptr, nullptr, DIM, HFF, b2, x1, DIM, 1.f, 0);
}

// round 9
// speedup vs baseline: 3.0787x; 1.0414x over previous
#include <cuda_runtime.h>
#include <cuda_bf16.h>
#include <math.h>
#include <stdint.h>

#define BATCH 8
#define SEQ   1024
#define DIM   1024
#define HEADS 16
#define DH    64
#define HFF   4096
#define MROWS (BATCH*SEQ)   // 8192
#define QKVN  (3*DIM)       // 3072

typedef __nv_bfloat16 bf16;

// ---------------- scratch (static device arrays: allocation-free) ----------
__device__ bf16 g_lnh[(size_t)MROWS*DIM], g_lnl[(size_t)MROWS*DIM];
__device__ bf16 g_qkvh[(size_t)MROWS*QKVN], g_qkvl[(size_t)MROWS*QKVN];
__device__ float g_x1[(size_t)MROWS*DIM];
__device__ bf16 g_hid[(size_t)2*MROWS*HFF];
__device__ float g_b3[QKVN];
// split-bf16 weight planes: wq|wk|wv (combined QKV), wo, w1, w2
#define WOFF_Q  0
#define WOFF_O  ((size_t)3*DIM*DIM)
#define WOFF_1  ((size_t)4*DIM*DIM)
#define WOFF_2  ((size_t)4*DIM*DIM + (size_t)HFF*DIM)
__device__ bf16 g_wh[(size_t)4*DIM*DIM + (size_t)2*HFF*DIM];
__device__ bf16 g_wl[(size_t)4*DIM*DIM + (size_t)2*HFF*DIM];

// ==================== helpers ====================
__device__ __forceinline__ uint32_t smem_u32(const void* p) {
    uint32_t a;
    asm("{ .reg .u64 t; cvta.to.shared.u64 t, %1; cvt.u32.u64 %0, t; }"
        : "=r"(a) : "l"(p));
    return a;
}
__device__ __forceinline__ void cp_async16(uint32_t dst, const void* src) {
    uint64_t g;
    asm("cvta.to.global.u64 %0, %1;" : "=l"(g) : "l"(src));
    asm volatile("cp.async.cg.shared.global [%0], [%1], 16;"
                 :: "r"(dst), "l"(g) : "memory");
}
#define CP_COMMIT() asm volatile("cp.async.commit_group;" ::: "memory")
#define CP_WAIT0()  asm volatile("cp.async.wait_group 0;"  ::: "memory")

__device__ __forceinline__ void cvt2(float a, float b, uint32_t& h, uint32_t& l) {
    __nv_bfloat162 hh = __floats2bfloat162_rn(a, b);
    float ra = a - __bfloat162float(hh.x);
    float rb = b - __bfloat162float(hh.y);
    __nv_bfloat162 ll = __floats2bfloat162_rn(ra, rb);
    h = *(uint32_t*)&hh;
    l = *(uint32_t*)&ll;
}

#define LDM4(r0, r1, r2, r3, addr) \
    asm volatile("ldmatrix.sync.aligned.m8n8.x4.shared.b16 {%0,%1,%2,%3}, [%4];" \
                 : "=r"(r0), "=r"(r1), "=r"(r2), "=r"(r3) : "r"(addr))
#define LDM2(r0, r1, addr) \
    asm volatile("ldmatrix.sync.aligned.m8n8.x2.shared.b16 {%0,%1}, [%2];" \
                 : "=r"(r0), "=r"(r1) : "r"(addr))
#define LDM2T(r0, r1, addr) \
    asm volatile("ldmatrix.sync.aligned.m8n8.x2.trans.shared.b16 {%0,%1}, [%2];" \
                 : "=r"(r0), "=r"(r1) : "r"(addr))
#define MMA16816(c, a, b) \
    asm volatile("mma.sync.aligned.m16n8k16.row.col.f32.bf16.bf16.f32 " \
                 "{%0,%1,%2,%3}, {%4,%5,%6,%7}, {%8,%9}, {%0,%1,%2,%3};" \
                 : "+f"((c)[0]), "+f"((c)[1]), "+f"((c)[2]), "+f"((c)[3]) \
                 : "r"((a)[0]), "r"((a)[1]), "r"((a)[2]), "r"((a)[3]), \
                   "r"((b)[0]), "r"((b)[1]))

// ---------------- weight fp32 -> split-bf16 planes -------------------------
__global__ __launch_bounds__(256) void wconv(const float* __restrict__ w,
                                             bf16* __restrict__ h,
                                             bf16* __restrict__ l, int n4) {
    const int i = blockIdx.x * 256 + threadIdx.x;
    if (i >= n4) return;
    const float4 v = ((const float4*)w)[i];
    uint32_t h0, l0, h1, l1;
    cvt2(v.x, v.y, h0, l0);
    cvt2(v.z, v.w, h1, l1);
    ((uint2*)h)[i] = make_uint2(h0, h1);
    ((uint2*)l)[i] = make_uint2(l0, l1);
}
// concat bq|bk|bv -> g_b3
__global__ __launch_bounds__(256) void bcat(const float* __restrict__ a,
                                            const float* __restrict__ b,
                                            const float* __restrict__ c,
                                            float* __restrict__ o) {
    const int i = blockIdx.x * 256 + threadIdx.x;
    if (i < DIM)            o[i] = a[i];
    else if (i < 2 * DIM)   o[i] = b[i - DIM];
    else if (i < 3 * DIM)   o[i] = c[i - 2 * DIM];
}

// ==================== split-bf16 mma.sync GEMM (weights path) ==============
// C[m,n] = scale * sum_k A[m,k]*B[n,k] (+bias, +relu, +resid)
template<bool OSPLIT>
__global__ __launch_bounds__(256, 2) void gemm3(
    const bf16* __restrict__ Ah, const bf16* __restrict__ Al, int lda,
    const bf16* __restrict__ Bh, const bf16* __restrict__ Bl, int ldb,
    float* __restrict__ Cf,
    bf16* __restrict__ Ch, bf16* __restrict__ Cl, int ldc,
    int K,
    const float* __restrict__ bias,
    const float* __restrict__ resid, int ldr,
    float scale, int relu)
{
    constexpr int BK = 32;
    constexpr int WN = 32, NT = 4;
    constexpr int ABYTES = 128 * 80;
    constexpr int BBYTES = 128 * 80;
    constexpr int SS = 2 * ABYTES + 2 * BBYTES;

    extern __shared__ char sm[];
    const uint32_t smBase = smem_u32(sm);

    const int tid = threadIdx.x, wid = tid >> 5, lane = tid & 31;
    const int wm = wid >> 2, wn = wid & 3;
    const int m0 = blockIdx.y * 128, n0 = blockIdx.x * 128;

    float acc[4][NT][4];
#pragma unroll
    for (int i = 0; i < 4; i++)
#pragma unroll
        for (int j = 0; j < NT; j++)
#pragma unroll
            for (int r = 0; r < 4; r++) acc[i][j][r] = 0.f;

    auto issueA = [&](int s, int t) {
        const uint32_t sA = smBase + s * SS;
#pragma unroll
        for (int i = 0; i < 4; i++) {
            const int idx = i * 256 + tid;
            const int c = idx & 3, row = (idx >> 2) & 127, pl = idx >> 9;
            const bf16* g = (pl ? Al : Ah) + (size_t)(m0 + row) * lda + t * BK + c * 8;
            cp_async16(sA + pl * ABYTES + row * 80 + c * 16, g);
        }
    };
    auto issueB = [&](int s, int t) {
        const uint32_t sB = smBase + s * SS + 2 * ABYTES;
#pragma unroll
        for (int i = 0; i < 4; i++) {
            const int idx = i * 256 + tid;
            const int c = idx & 3, row = (idx >> 2) & 127, pl = idx >> 9;
            const bf16* g = (pl ? Bl : Bh) + (size_t)(n0 + row) * ldb + t * BK + c * 8;
            cp_async16(sB + pl * BBYTES + row * 80 + c * 16, g);
        }
    };

    auto compute = [&](int s) {
        const uint32_t aHiB = smBase + s * SS;
        const uint32_t aLoB = aHiB + ABYTES;
        const uint32_t bHiB = aHiB + 2 * ABYTES;
        const uint32_t bLoB = bHiB + BBYTES;
#pragma unroll
        for (int ks = 0; ks < 2; ks++) {
            // B frags via x4: matrices = (nt2p klo, nt2p khi, nt2p+1 klo, nt2p+1 khi)
            uint32_t bh[NT][2], bl[NT][2];
#pragma unroll
            for (int p = 0; p < NT / 2; p++) {
                const uint32_t rb =
                    (uint32_t)((wn * WN + p * 16 + ((lane >> 4) & 1) * 8 + (lane & 7)) * 80
                               + ks * 32 + ((lane >> 3) & 1) * 16);
                LDM4(bh[2*p][0], bh[2*p][1], bh[2*p+1][0], bh[2*p+1][1], bHiB + rb);
                LDM4(bl[2*p][0], bl[2*p][1], bl[2*p+1][0], bl[2*p+1][1], bLoB + rb);
            }
            const uint32_t kbA = (uint32_t)((ks * 16 + (lane >> 4) * 8) * 2);
#pragma unroll
            for (int mt = 0; mt < 4; mt++) {
                uint32_t ah[4], al[4];
                const uint32_t ra = (uint32_t)((wm * 64 + mt * 16 + (lane & 15)) * 80) + kbA;
                LDM4(ah[0], ah[1], ah[2], ah[3], aHiB + ra);
                LDM4(al[0], al[1], al[2], al[3], aLoB + ra);
#pragma unroll
                for (int nt = 0; nt < NT; nt++) MMA16816(acc[mt][nt], ah, bh[nt]);
#pragma unroll
                for (int nt = 0; nt < NT; nt++) MMA16816(acc[mt][nt], ah, bl[nt]);
#pragma unroll
                for (int nt = 0; nt < NT; nt++) MMA16816(acc[mt][nt], al, bh[nt]);
            }
        }
    };

    const int T = K / BK;
    issueA(0, 0);
    issueB(0, 0);
    CP_COMMIT();
    CP_WAIT0();
    __syncthreads();

    for (int t = 0; t < T; t++) {
        const int s = t & 1;
        if (t + 1 < T) {
            issueA(s ^ 1, t + 1);
            issueB(s ^ 1, t + 1);
            CP_COMMIT();
        }
        compute(s);
        CP_WAIT0();
        __syncthreads();
    }

#pragma unroll
    for (int mt = 0; mt < 4; mt++) {
#pragma unroll
        for (int nt = 0; nt < NT; nt++) {
            const int r0 = m0 + wm * 64 + mt * 16 + (lane >> 2);
            const int cc = n0 + wn * WN + nt * 8 + (lane & 3) * 2;
#pragma unroll
            for (int h = 0; h < 2; h++) {
                const int m = r0 + h * 8;
                float vx = acc[mt][nt][2 * h]     * scale;
                float vy = acc[mt][nt][2 * h + 1] * scale;
                if (bias)  { vx += bias[cc]; vy += bias[cc + 1]; }
                if (relu)  { vx = fmaxf(vx, 0.f); vy = fmaxf(vy, 0.f); }
                if (resid) {
                    const float2 rr = *(const float2*)(resid + (size_t)m * ldr + cc);
                    vx += rr.x; vy += rr.y;
                }
                if constexpr (OSPLIT) {
                    uint32_t hh, ll;
                    cvt2(vx, vy, hh, ll);
                    *(uint32_t*)(Ch + (size_t)m * ldc + cc) = hh;
                    *(uint32_t*)(Cl + (size_t)m * ldc + cc) = ll;
                } else {
                    *(float2*)(Cf + (size_t)m * ldc + cc) = make_float2(vx, vy);
                }
            }
        }
    }
}

// ==================== fused flash attention ====================
// Q/K/V live in the combined QKV buffer (stride QKVN, col offsets 0/1024/2048).
#define FQ_PL 9216      // 64 rows * 144B per plane
#define FK_PL 18432     // 128 rows * 144B per plane
#define FSMEM (2*FQ_PL + 4*FK_PL)   // 92160

__global__ __launch_bounds__(128, 2) void flash_attn(
    const bf16* __restrict__ qkvh, const bf16* __restrict__ qkvl,
    bf16* __restrict__ oh, bf16* __restrict__ ol)
{
    extern __shared__ char sm[];
    const uint32_t smBase = smem_u32(sm);
    const int tid = threadIdx.x, lane = tid & 31, w = tid >> 5;
    const int b = blockIdx.y >> 4, h = blockIdx.y & 15;
    const size_t rowQ  = (size_t)b * SEQ + blockIdx.x * 64;
    const size_t rowKV = (size_t)b * SEQ;
    const int colh = h * DH;

    const uint32_t sQ = smBase;
    const uint32_t sK = smBase + 2 * FQ_PL;
    const uint32_t sV = sK + 2 * FK_PL;

#pragma unroll
    for (int i = 0; i < 8; i++) {
        const int idx = i * 128 + tid;
        const int pl = idx >> 9, row = (idx >> 3) & 63, c = idx & 7;
        const bf16* g = (pl ? qkvl : qkvh) + (rowQ + row) * QKVN + colh + c * 8;
        cp_async16(sQ + pl * FQ_PL + row * 144 + c * 16, g);
    }
    auto loadKV = [&](int kt) {
        const size_t base = (rowKV + kt * 128) * QKVN + colh;
#pragma unroll
        for (int i = 0; i < 16; i++) {
            const int idx = i * 128 + tid;
            const int pl = idx >> 10, row = (idx >> 3) & 127, c = idx & 7;
            const size_t off = base + (size_t)row * QKVN + c * 8;
            const uint32_t d = pl * FK_PL + row * 144 + c * 16;
            cp_async16(sK + d, (pl ? qkvl : qkvh) + off + DIM);
            cp_async16(sV + d, (pl ? qkvl : qkvh) + off + 2 * DIM);
        }
    };
    loadKV(0);
    CP_COMMIT(); CP_WAIT0();
    __syncthreads();

    float oacc[8][4];
#pragma unroll
    for (int i = 0; i < 8; i++)
#pragma unroll
        for (int j = 0; j < 4; j++) oacc[i][j] = 0.f;
    float m0 = -INFINITY, m1 = -INFINITY, l0 = 0.f, l1 = 0.f;

    for (int kt = 0; kt < 8; kt++) {
        float sfr[16][4];
#pragma unroll
        for (int i = 0; i < 16; i++)
#pragma unroll
            for (int j = 0; j < 4; j++) sfr[i][j] = 0.f;
#pragma unroll
        for (int ks = 0; ks < 4; ks++) {
            uint32_t qa[4], qb[4];
            const uint32_t ra = sQ + (w * 16 + (lane & 15)) * 144
                              + ks * 32 + (lane >> 4) * 16;
            LDM4(qa[0], qa[1], qa[2], qa[3], ra);
            LDM4(qb[0], qb[1], qb[2], qb[3], ra + FQ_PL);
#pragma unroll
            for (int p = 0; p < 8; p++) {
                uint32_t kbh[4], kbl[4];
                const uint32_t rb = sK + (p * 16 + ((lane >> 4) & 1) * 8 + (lane & 7)) * 144
                                  + ks * 32 + ((lane >> 3) & 1) * 16;
                LDM4(kbh[0], kbh[1], kbh[2], kbh[3], rb);
                LDM4(kbl[0], kbl[1], kbl[2], kbl[3], rb + FK_PL);
                MMA16816(sfr[2*p],   qa, (&kbh[0]));
                MMA16816(sfr[2*p],   qa, (&kbl[0]));
                MMA16816(sfr[2*p],   qb, (&kbh[0]));
                MMA16816(sfr[2*p+1], qa, (&kbh[2]));
                MMA16816(sfr[2*p+1], qa, (&kbl[2]));
                MMA16816(sfr[2*p+1], qb, (&kbh[2]));
            }
        }
        float mx0 = -INFINITY, mx1 = -INFINITY;
#pragma unroll
        for (int nt = 0; nt < 16; nt++) {
            mx0 = fmaxf(mx0, fmaxf(sfr[nt][0], sfr[nt][1]));
            mx1 = fmaxf(mx1, fmaxf(sfr[nt][2], sfr[nt][3]));
        }
        mx0 = fmaxf(mx0, __shfl_xor_sync(0xffffffffu, mx0, 1));
        mx0 = fmaxf(mx0, __shfl_xor_sync(0xffffffffu, mx0, 2));
        mx1 = fmaxf(mx1, __shfl_xor_sync(0xffffffffu, mx1, 1));
        mx1 = fmaxf(mx1, __shfl_xor_sync(0xffffffffu, mx1, 2));
        const float mn0 = fmaxf(m0, 0.125f * mx0);
        const float mn1 = fmaxf(m1, 0.125f * mx1);
        const float f0 = __expf(m0 - mn0);
        const float f1 = __expf(m1 - mn1);
        float rs0 = 0.f, rs1 = 0.f;
#pragma unroll
        for (int nt = 0; nt < 16; nt++) {
            const float p0 = __expf(fmaf(sfr[nt][0], 0.125f, -mn0));
            const float p1 = __expf(fmaf(sfr[nt][1], 0.125f, -mn0));
            const float p2 = __expf(fmaf(sfr[nt][2], 0.125f, -mn1));
            const float p3 = __expf(fmaf(sfr[nt][3], 0.125f, -mn1));
            rs0 += p0 + p1; rs1 += p2 + p3;
            sfr[nt][0] = p0; sfr[nt][1] = p1; sfr[nt][2] = p2; sfr[nt][3] = p3;
        }
        rs0 += __shfl_xor_sync(0xffffffffu, rs0, 1);
        rs0 += __shfl_xor_sync(0xffffffffu, rs0, 2);
        rs1 += __shfl_xor_sync(0xffffffffu, rs1, 1);
        rs1 += __shfl_xor_sync(0xffffffffu, rs1, 2);
        l0 = l0 * f0 + rs0; l1 = l1 * f1 + rs1;
        m0 = mn0; m1 = mn1;
#pragma unroll
        for (int dt = 0; dt < 8; dt++) {
            oacc[dt][0] *= f0; oacc[dt][1] *= f0;
            oacc[dt][2] *= f1; oacc[dt][3] *= f1;
        }
#pragma unroll
        for (int ks = 0; ks < 8; ks++) {
            uint32_t ah[4], al[4];
            cvt2(sfr[2 * ks][0],     sfr[2 * ks][1],     ah[0], al[0]);
            cvt2(sfr[2 * ks][2],     sfr[2 * ks][3],     ah[1], al[1]);
            cvt2(sfr[2 * ks + 1][0], sfr[2 * ks + 1][1], ah[2], al[2]);
            cvt2(sfr[2 * ks + 1][2], sfr[2 * ks + 1][3], ah[3], al[3]);
#pragma unroll
            for (int dt = 0; dt < 8; dt++) {
                uint32_t vbh[2], vbl[2];
                const uint32_t rv = sV + (ks * 16 + (lane & 15)) * 144 + dt * 16;
                LDM2T(vbh[0], vbh[1], rv);
                LDM2T(vbl[0], vbl[1], rv + FK_PL);
                MMA16816(oacc[dt], ah, vbh);
                MMA16816(oacc[dt], ah, vbl);
                MMA16816(oacc[dt], al, vbh);
            }
        }
        if (kt < 7) {
            __syncthreads();
            loadKV(kt + 1);
            CP_COMMIT(); CP_WAIT0();
            __syncthreads();
        }
    }

    const float i0 = 1.f / l0, i1 = 1.f / l1;
    const int r = w * 16 + (lane >> 2);
    const int cc = (lane & 3) * 2;
#pragma unroll
    for (int dt = 0; dt < 8; dt++) {
        uint32_t hh, ll;
        const size_t o0 = (rowQ + r) * DIM + colh + dt * 8 + cc;
        cvt2(oacc[dt][0] * i0, oacc[dt][1] * i0, hh, ll);
        *(uint32_t*)(oh + o0) = hh;
        *(uint32_t*)(ol + o0) = ll;
        const size_t o1 = o0 + 8 * DIM;
        cvt2(oacc[dt][2] * i1, oacc[dt][3] * i1, hh, ll);
        *(uint32_t*)(oh + o1) = hh;
        *(uint32_t*)(ol + o1) = ll;
    }
}

// ---------------- LayerNorm -> split-bf16 planes ---------------------------
__global__ __launch_bounds__(256) void ln_kernel(const float* __restrict__ x,
                                                 bf16* __restrict__ yh,
                                                 bf16* __restrict__ yl,
                                                 const float* __restrict__ alpha,
                                                 const float* __restrict__ beta) {
    __shared__ float sh_s[8], sh_q[8];
    const size_t row = blockIdx.x;
    const float4* xr = (const float4*)(x + row * DIM);
    const int tid = threadIdx.x;
    float4 v = xr[tid];
    float s = v.x + v.y + v.z + v.w;
    float q = v.x*v.x + v.y*v.y + v.z*v.z + v.w*v.w;
#pragma unroll
    for (int o = 16; o; o >>= 1) {
        s += __shfl_xor_sync(0xffffffffu, s, o);
        q += __shfl_xor_sync(0xffffffffu, q, o);
    }
    if ((tid & 31) == 0) { sh_s[tid >> 5] = s; sh_q[tid >> 5] = q; }
    __syncthreads();
    if (tid < 32) {
        s = (tid < 8) ? sh_s[tid] : 0.f;
        q = (tid < 8) ? sh_q[tid] : 0.f;
#pragma unroll
        for (int o = 4; o; o >>= 1) {
            s += __shfl_xor_sync(0xffffffffu, s, o);
            q += __shfl_xor_sync(0xffffffffu, q, o);
        }
        if (tid == 0) { sh_s[0] = s; sh_q[0] = q; }
    }
    __syncthreads();
    s = sh_s[0]; q = sh_q[0];
    const float mean = s * (1.0f / DIM);
    const float var  = (q - (float)DIM * mean * mean) * (1.0f / (DIM - 1));
    const float inv  = 1.0f / (sqrtf(fmaxf(var, 0.f)) + 1e-6f);
    const float4 a = ((const float4*)alpha)[tid];
    const float4 b = ((const float4*)beta)[tid];
    float ox = a.x * (v.x - mean) * inv + b.x;
    float oy = a.y * (v.y - mean) * inv + b.y;
    float oz = a.z * (v.z - mean) * inv + b.z;
    float ow = a.w * (v.w - mean) * inv + b.w;
    uint32_t h0, l0, h1, l1;
    cvt2(ox, oy, h0, l0);
    cvt2(oz, ow, h1, l1);
    *(uint2*)(yh + row * DIM + 4 * tid) = make_uint2(h0, h1);
    *(uint2*)(yl + row * DIM + 4 * tid) = make_uint2(l0, l1);
}

// ---------------- launch ----------------------------------------------------
template<typename T>
static T* symaddr(const void* s) {
    void* p = nullptr;
    cudaGetSymbolAddress(&p, s);
    return (T*)p;
}

#define SMEM_G (2 * (2 * 128 * 80 + 2 * 128 * 80))   // 81920

extern "C" void kernel_launch(void* const* d_in, const int* in_sizes, int n_in,
                              void* d_out, int out_size) {
    (void)in_sizes; (void)n_in; (void)out_size;
    const float* x     = (const float*)d_in[0];
    const float* wq    = (const float*)d_in[2];
    const float* bq    = (const float*)d_in[3];
    const float* wk    = (const float*)d_in[4];
    const float* bk    = (const float*)d_in[5];
    const float* wv    = (const float*)d_in[6];
    const float* bv    = (const float*)d_in[7];
    const float* wo    = (const float*)d_in[8];
    const float* bo    = (const float*)d_in[9];
    const float* w1    = (const float*)d_in[10];
    const float* b1    = (const float*)d_in[11];
    const float* w2    = (const float*)d_in[12];
    const float* b2    = (const float*)d_in[13];
    const float* alpha = (const float*)d_in[14];
    const float* beta  = (const float*)d_in[15];
    float* out = (float*)d_out;

    cudaFuncSetAttribute(gemm3<true>,
                         cudaFuncAttributeMaxDynamicSharedMemorySize, SMEM_G);
    cudaFuncSetAttribute(gemm3<false>,
                         cudaFuncAttributeMaxDynamicSharedMemorySize, SMEM_G);
    cudaFuncSetAttribute(flash_attn,
                         cudaFuncAttributeMaxDynamicSharedMemorySize, FSMEM);

    bf16* lnh = symaddr<bf16>(g_lnh);  bf16* lnl = symaddr<bf16>(g_lnl);
    bf16* qkvh = symaddr<bf16>(g_qkvh);
    bf16* qkvl = symaddr<bf16>(g_qkvl);
    float* x1 = symaddr<float>(g_x1);
    bf16* wh  = symaddr<bf16>(g_wh);   bf16* wl  = symaddr<bf16>(g_wl);
    bf16* hidh = symaddr<bf16>(g_hid);
    bf16* hidl = hidh + (size_t)MROWS * HFF;
    float* b3 = symaddr<float>(g_b3);

    // 0) weight conversion + bias concat
    const int n4p = DIM * DIM / 4, n4f = HFF * DIM / 4;
    wconv<<<(n4p + 255) / 256, 256>>>(wq, wh + WOFF_Q, wl + WOFF_Q, n4p);
    wconv<<<(n4p + 255) / 256, 256>>>(wk, wh + WOFF_Q + (size_t)DIM*DIM,
                                      wl + WOFF_Q + (size_t)DIM*DIM, n4p);
    wconv<<<(n4p + 255) / 256, 256>>>(wv, wh + WOFF_Q + (size_t)2*DIM*DIM,
                                      wl + WOFF_Q + (size_t)2*DIM*DIM, n4p);
    wconv<<<(n4p + 255) / 256, 256>>>(wo, wh + WOFF_O, wl + WOFF_O, n4p);
    wconv<<<(n4f + 255) / 256, 256>>>(w1, wh + WOFF_1, wl + WOFF_1, n4f);
    wconv<<<(n4f + 255) / 256, 256>>>(w2, wh + WOFF_2, wl + WOFF_2, n4f);
    bcat<<<(QKVN + 255) / 256, 256>>>(bq, bk, bv, b3);

    // 1) LN1
    ln_kernel<<<MROWS, 256>>>(x, lnh, lnl, alpha, beta);

    // 2) fused QKV projection: [8192, 3072]
    dim3 gqkv(QKVN / 128, MROWS / 128, 1);
    gemm3<true><<<gqkv, 256, SMEM_G>>>(
        lnh, lnl, DIM, wh + WOFF_Q, wl + WOFF_Q, DIM,
        nullptr, qkvh, qkvl, QKVN, DIM, b3, nullptr, 0, 1.f, 0);

    // 3-5) fused attention -> split planes (into lnh/lnl, reused)
    dim3 gfa(SEQ / 64, BATCH * HEADS, 1);
    flash_attn<<<gfa, 128, FSMEM>>>(qkvh, qkvl, lnh, lnl);

    // 6) O projection + residual x -> x1 (fp32)
    dim3 gw(DIM / 128, MROWS / 128, 1);
    gemm3<false><<<gw, 256, SMEM_G>>>(
        lnh, lnl, DIM, wh + WOFF_O, wl + WOFF_O, DIM,
        x1, nullptr, nullptr, DIM, DIM, bo, x, DIM, 1.f, 0);

    // 7) LN2
    ln_kernel<<<MROWS, 256>>>(x1, lnh, lnl, alpha, beta);

    // 8) FFN1 (+ReLU)
    dim3 gf1(HFF / 128, MROWS / 128, 1);
    gemm3<true><<<gf1, 256, SMEM_G>>>(
        lnh, lnl, DIM, wh + WOFF_1, wl + WOFF_1, DIM,
        nullptr, hidh, hidl, HFF, DIM, b1, nullptr, 0, 1.f, 1);

    // 9) FFN2 + residual x1 -> out (fp32)
    dim3 gf2(DIM / 128, MROWS / 128, 1);
    gemm3<false><<<gf2, 256, SMEM_G>>>(
        hidh, hidl, HFF, wh + WOFF_2, wl + WOFF_2, HFF,
        out, nullptr, nullptr, DIM, HFF, b2, x1, DIM, 1.f, 0);
}

// round 10
// speedup vs baseline: 3.2044x; 1.0408x over previous
#include <cuda_runtime.h>
#include <cuda_bf16.h>
#include <math.h>
#include <stdint.h>

#define BATCH 8
#define SEQ   1024
#define DIM   1024
#define HEADS 16
#define DH    64
#define HFF   4096
#define MROWS (BATCH*SEQ)   // 8192
#define QKVN  (3*DIM)       // 3072

typedef __nv_bfloat16 bf16;

// ---------------- scratch (static device arrays: allocation-free) ----------
__device__ bf16 g_lnh[(size_t)MROWS*DIM], g_lnl[(size_t)MROWS*DIM];
__device__ bf16 g_qkvh[(size_t)MROWS*QKVN], g_qkvl[(size_t)MROWS*QKVN];
__device__ float g_x1[(size_t)MROWS*DIM];
__device__ bf16 g_hid[(size_t)2*MROWS*HFF];
__device__ float g_b3[QKVN];
// split-bf16 weight planes: wq|wk|wv (combined QKV), wo, w1, w2
#define WOFF_Q  0
#define WOFF_O  ((size_t)3*DIM*DIM)
#define WOFF_1  ((size_t)4*DIM*DIM)
#define WOFF_2  ((size_t)4*DIM*DIM + (size_t)HFF*DIM)
__device__ bf16 g_wh[(size_t)4*DIM*DIM + (size_t)2*HFF*DIM];
__device__ bf16 g_wl[(size_t)4*DIM*DIM + (size_t)2*HFF*DIM];

// ==================== helpers ====================
__device__ __forceinline__ uint32_t smem_u32(const void* p) {
    uint32_t a;
    asm("{ .reg .u64 t; cvta.to.shared.u64 t, %1; cvt.u32.u64 %0, t; }"
        : "=r"(a) : "l"(p));
    return a;
}
__device__ __forceinline__ void cp_async16(uint32_t dst, const void* src) {
    uint64_t g;
    asm("cvta.to.global.u64 %0, %1;" : "=l"(g) : "l"(src));
    asm volatile("cp.async.cg.shared.global [%0], [%1], 16;"
                 :: "r"(dst), "l"(g) : "memory");
}
#define CP_COMMIT() asm volatile("cp.async.commit_group;" ::: "memory")
#define CP_WAIT0()  asm volatile("cp.async.wait_group 0;"  ::: "memory")

__device__ __forceinline__ void cvt2(float a, float b, uint32_t& h, uint32_t& l) {
    __nv_bfloat162 hh = __floats2bfloat162_rn(a, b);
    float ra = a - __bfloat162float(hh.x);
    float rb = b - __bfloat162float(hh.y);
    __nv_bfloat162 ll = __floats2bfloat162_rn(ra, rb);
    h = *(uint32_t*)&hh;
    l = *(uint32_t*)&ll;
}

#define LDM4(r0, r1, r2, r3, addr) \
    asm volatile("ldmatrix.sync.aligned.m8n8.x4.shared.b16 {%0,%1,%2,%3}, [%4];" \
                 : "=r"(r0), "=r"(r1), "=r"(r2), "=r"(r3) : "r"(addr))
#define LDM2T(r0, r1, addr) \
    asm volatile("ldmatrix.sync.aligned.m8n8.x2.trans.shared.b16 {%0,%1}, [%2];" \
                 : "=r"(r0), "=r"(r1) : "r"(addr))
#define MMA16816(c, a, b) \
    asm volatile("mma.sync.aligned.m16n8k16.row.col.f32.bf16.bf16.f32 " \
                 "{%0,%1,%2,%3}, {%4,%5,%6,%7}, {%8,%9}, {%0,%1,%2,%3};" \
                 : "+f"((c)[0]), "+f"((c)[1]), "+f"((c)[2]), "+f"((c)[3]) \
                 : "r"((a)[0]), "r"((a)[1]), "r"((a)[2]), "r"((a)[3]), \
                   "r"((b)[0]), "r"((b)[1]))

// ---------------- weight fp32 -> split-bf16 planes -------------------------
__global__ __launch_bounds__(256) void wconv(const float* __restrict__ w,
                                             bf16* __restrict__ h,
                                             bf16* __restrict__ l, int n4) {
    const int i = blockIdx.x * 256 + threadIdx.x;
    if (i >= n4) return;
    const float4 v = ((const float4*)w)[i];
    uint32_t h0, l0, h1, l1;
    cvt2(v.x, v.y, h0, l0);
    cvt2(v.z, v.w, h1, l1);
    ((uint2*)h)[i] = make_uint2(h0, h1);
    ((uint2*)l)[i] = make_uint2(l0, l1);
}
__global__ __launch_bounds__(256) void bcat(const float* __restrict__ a,
                                            const float* __restrict__ b,
                                            const float* __restrict__ c,
                                            float* __restrict__ o) {
    const int i = blockIdx.x * 256 + threadIdx.x;
    if (i < DIM)            o[i] = a[i];
    else if (i < 2 * DIM)   o[i] = b[i - DIM];
    else if (i < 3 * DIM)   o[i] = c[i - 2 * DIM];
}

// ==================== split-bf16 mma.sync GEMM v4 ====================
// 128 threads, warp grid 2x2, warp tile 64x64 -> 2x less smem duplication.
// C[m,n] = scale * sum_k A[m,k]*B[n,k] (+bias, +relu, +resid)
template<bool OSPLIT>
__global__ __launch_bounds__(128, 2) void gemm4(
    const bf16* __restrict__ Ah, const bf16* __restrict__ Al, int lda,
    const bf16* __restrict__ Bh, const bf16* __restrict__ Bl, int ldb,
    float* __restrict__ Cf,
    bf16* __restrict__ Ch, bf16* __restrict__ Cl, int ldc,
    int K,
    const float* __restrict__ bias,
    const float* __restrict__ resid, int ldr,
    float scale, int relu)
{
    constexpr int BK = 32;
    constexpr int ABYTES = 128 * 80;
    constexpr int BBYTES = 128 * 80;
    constexpr int SS = 2 * ABYTES + 2 * BBYTES;

    extern __shared__ char sm[];
    const uint32_t smBase = smem_u32(sm);

    const int tid = threadIdx.x, wid = tid >> 5, lane = tid & 31;
    const int wm = wid >> 1, wn = wid & 1;
    const int m0 = blockIdx.y * 128, n0 = blockIdx.x * 128;

    float acc[4][8][4];
#pragma unroll
    for (int i = 0; i < 4; i++)
#pragma unroll
        for (int j = 0; j < 8; j++)
#pragma unroll
            for (int r = 0; r < 4; r++) acc[i][j][r] = 0.f;

    auto issueA = [&](int s, int t) {
        const uint32_t sA = smBase + s * SS;
#pragma unroll
        for (int i = 0; i < 8; i++) {
            const int idx = i * 128 + tid;
            const int c = idx & 3, row = (idx >> 2) & 127, pl = idx >> 9;
            const bf16* g = (pl ? Al : Ah) + (size_t)(m0 + row) * lda + t * BK + c * 8;
            cp_async16(sA + pl * ABYTES + row * 80 + c * 16, g);
        }
    };
    auto issueB = [&](int s, int t) {
        const uint32_t sB = smBase + s * SS + 2 * ABYTES;
#pragma unroll
        for (int i = 0; i < 8; i++) {
            const int idx = i * 128 + tid;
            const int c = idx & 3, row = (idx >> 2) & 127, pl = idx >> 9;
            const bf16* g = (pl ? Bl : Bh) + (size_t)(n0 + row) * ldb + t * BK + c * 8;
            cp_async16(sB + pl * BBYTES + row * 80 + c * 16, g);
        }
    };

    auto compute = [&](int s) {
        const uint32_t aHiB = smBase + s * SS;
        const uint32_t aLoB = aHiB + ABYTES;
        const uint32_t bHiB = aHiB + 2 * ABYTES;
        const uint32_t bLoB = bHiB + BBYTES;
#pragma unroll
        for (int ks = 0; ks < 2; ks++) {
            // B frags (64 cols = 8 n8 tiles) via LDM4 pairs
            uint32_t bh[8][2], bl[8][2];
#pragma unroll
            for (int p = 0; p < 4; p++) {
                const uint32_t rb =
                    (uint32_t)((wn * 64 + p * 16 + ((lane >> 4) & 1) * 8 + (lane & 7)) * 80
                               + ks * 32 + ((lane >> 3) & 1) * 16);
                LDM4(bh[2*p][0], bh[2*p][1], bh[2*p+1][0], bh[2*p+1][1], bHiB + rb);
                LDM4(bl[2*p][0], bl[2*p][1], bl[2*p+1][0], bl[2*p+1][1], bLoB + rb);
            }
            const uint32_t kbA = (uint32_t)((ks * 16 + (lane >> 4) * 8) * 2);
#pragma unroll
            for (int mt = 0; mt < 4; mt++) {
                uint32_t ah[4], al[4];
                const uint32_t ra = (uint32_t)((wm * 64 + mt * 16 + (lane & 15)) * 80) + kbA;
                LDM4(ah[0], ah[1], ah[2], ah[3], aHiB + ra);
                LDM4(al[0], al[1], al[2], al[3], aLoB + ra);
#pragma unroll
                for (int nt = 0; nt < 8; nt++) MMA16816(acc[mt][nt], ah, bh[nt]);
#pragma unroll
                for (int nt = 0; nt < 8; nt++) MMA16816(acc[mt][nt], ah, bl[nt]);
#pragma unroll
                for (int nt = 0; nt < 8; nt++) MMA16816(acc[mt][nt], al, bh[nt]);
            }
        }
    };

    const int T = K / BK;
    issueA(0, 0);
    issueB(0, 0);
    CP_COMMIT();
    CP_WAIT0();
    __syncthreads();

    for (int t = 0; t < T; t++) {
        const int s = t & 1;
        if (t + 1 < T) {
            issueA(s ^ 1, t + 1);
            issueB(s ^ 1, t + 1);
            CP_COMMIT();
        }
        compute(s);
        CP_WAIT0();
        __syncthreads();
    }

#pragma unroll
    for (int mt = 0; mt < 4; mt++) {
#pragma unroll
        for (int nt = 0; nt < 8; nt++) {
            const int r0 = m0 + wm * 64 + mt * 16 + (lane >> 2);
            const int cc = n0 + wn * 64 + nt * 8 + (lane & 3) * 2;
#pragma unroll
            for (int h = 0; h < 2; h++) {
                const int m = r0 + h * 8;
                float vx = acc[mt][nt][2 * h]     * scale;
                float vy = acc[mt][nt][2 * h + 1] * scale;
                if (bias)  { vx += bias[cc]; vy += bias[cc + 1]; }
                if (relu)  { vx = fmaxf(vx, 0.f); vy = fmaxf(vy, 0.f); }
                if (resid) {
                    const float2 rr = *(const float2*)(resid + (size_t)m * ldr + cc);
                    vx += rr.x; vy += rr.y;
                }
                if constexpr (OSPLIT) {
                    uint32_t hh, ll;
                    cvt2(vx, vy, hh, ll);
                    *(uint32_t*)(Ch + (size_t)m * ldc + cc) = hh;
                    *(uint32_t*)(Cl + (size_t)m * ldc + cc) = ll;
                } else {
                    *(float2*)(Cf + (size_t)m * ldc + cc) = make_float2(vx, vy);
                }
            }
        }
    }
}

// ==================== fused flash attention ====================
#define FQ_PL 9216      // 64 rows * 144B per plane
#define FK_PL 18432     // 128 rows * 144B per plane
#define FSMEM (2*FQ_PL + 4*FK_PL)   // 92160

__global__ __launch_bounds__(128, 2) void flash_attn(
    const bf16* __restrict__ qkvh, const bf16* __restrict__ qkvl,
    bf16* __restrict__ oh, bf16* __restrict__ ol)
{
    extern __shared__ char sm[];
    const uint32_t smBase = smem_u32(sm);
    const int tid = threadIdx.x, lane = tid & 31, w = tid >> 5;
    const int b = blockIdx.y >> 4, h = blockIdx.y & 15;
    const size_t rowQ  = (size_t)b * SEQ + blockIdx.x * 64;
    const size_t rowKV = (size_t)b * SEQ;
    const int colh = h * DH;

    const uint32_t sQ = smBase;
    const uint32_t sK = smBase + 2 * FQ_PL;
    const uint32_t sV = sK + 2 * FK_PL;

#pragma unroll
    for (int i = 0; i < 8; i++) {
        const int idx = i * 128 + tid;
        const int pl = idx >> 9, row = (idx >> 3) & 63, c = idx & 7;
        const bf16* g = (pl ? qkvl : qkvh) + (rowQ + row) * QKVN + colh + c * 8;
        cp_async16(sQ + pl * FQ_PL + row * 144 + c * 16, g);
    }
    auto loadKV = [&](int kt) {
        const size_t base = (rowKV + kt * 128) * QKVN + colh;
#pragma unroll
        for (int i = 0; i < 16; i++) {
            const int idx = i * 128 + tid;
            const int pl = idx >> 10, row = (idx >> 3) & 127, c = idx & 7;
            const size_t off = base + (size_t)row * QKVN + c * 8;
            const uint32_t d = pl * FK_PL + row * 144 + c * 16;
            cp_async16(sK + d, (pl ? qkvl : qkvh) + off + DIM);
            cp_async16(sV + d, (pl ? qkvl : qkvh) + off + 2 * DIM);
        }
    };
    loadKV(0);
    CP_COMMIT(); CP_WAIT0();
    __syncthreads();

    float oacc[8][4];
#pragma unroll
    for (int i = 0; i < 8; i++)
#pragma unroll
        for (int j = 0; j < 4; j++) oacc[i][j] = 0.f;
    float m0 = -INFINITY, m1 = -INFINITY, l0 = 0.f, l1 = 0.f;

    for (int kt = 0; kt < 8; kt++) {
        float sfr[16][4];
#pragma unroll
        for (int i = 0; i < 16; i++)
#pragma unroll
            for (int j = 0; j < 4; j++) sfr[i][j] = 0.f;
#pragma unroll
        for (int ks = 0; ks < 4; ks++) {
            uint32_t qa[4], qb[4];
            const uint32_t ra = sQ + (w * 16 + (lane & 15)) * 144
                              + ks * 32 + (lane >> 4) * 16;
            LDM4(qa[0], qa[1], qa[2], qa[3], ra);
            LDM4(qb[0], qb[1], qb[2], qb[3], ra + FQ_PL);
#pragma unroll
            for (int p = 0; p < 8; p++) {
                uint32_t kbh[4], kbl[4];
                const uint32_t rb = sK + (p * 16 + ((lane >> 4) & 1) * 8 + (lane & 7)) * 144
                                  + ks * 32 + ((lane >> 3) & 1) * 16;
                LDM4(kbh[0], kbh[1], kbh[2], kbh[3], rb);
                LDM4(kbl[0], kbl[1], kbl[2], kbl[3], rb + FK_PL);
                MMA16816(sfr[2*p],   qa, (&kbh[0]));
                MMA16816(sfr[2*p],   qa, (&kbl[0]));
                MMA16816(sfr[2*p],   qb, (&kbh[0]));
                MMA16816(sfr[2*p+1], qa, (&kbh[2]));
                MMA16816(sfr[2*p+1], qa, (&kbl[2]));
                MMA16816(sfr[2*p+1], qb, (&kbh[2]));
            }
        }
        float mx0 = -INFINITY, mx1 = -INFINITY;
#pragma unroll
        for (int nt = 0; nt < 16; nt++) {
            mx0 = fmaxf(mx0, fmaxf(sfr[nt][0], sfr[nt][1]));
            mx1 = fmaxf(mx1, fmaxf(sfr[nt][2], sfr[nt][3]));
        }
        mx0 = fmaxf(mx0, __shfl_xor_sync(0xffffffffu, mx0, 1));
        mx0 = fmaxf(mx0, __shfl_xor_sync(0xffffffffu, mx0, 2));
        mx1 = fmaxf(mx1, __shfl_xor_sync(0xffffffffu, mx1, 1));
        mx1 = fmaxf(mx1, __shfl_xor_sync(0xffffffffu, mx1, 2));
        const float mn0 = fmaxf(m0, 0.125f * mx0);
        const float mn1 = fmaxf(m1, 0.125f * mx1);
        const float f0 = __expf(m0 - mn0);
        const float f1 = __expf(m1 - mn1);
        float rs0 = 0.f, rs1 = 0.f;
#pragma unroll
        for (int nt = 0; nt < 16; nt++) {
            const float p0 = __expf(fmaf(sfr[nt][0], 0.125f, -mn0));
            const float p1 = __expf(fmaf(sfr[nt][1], 0.125f, -mn0));
            const float p2 = __expf(fmaf(sfr[nt][2], 0.125f, -mn1));
            const float p3 = __expf(fmaf(sfr[nt][3], 0.125f, -mn1));
            rs0 += p0 + p1; rs1 += p2 + p3;
            sfr[nt][0] = p0; sfr[nt][1] = p1; sfr[nt][2] = p2; sfr[nt][3] = p3;
        }
        rs0 += __shfl_xor_sync(0xffffffffu, rs0, 1);
        rs0 += __shfl_xor_sync(0xffffffffu, rs0, 2);
        rs1 += __shfl_xor_sync(0xffffffffu, rs1, 1);
        rs1 += __shfl_xor_sync(0xffffffffu, rs1, 2);
        l0 = l0 * f0 + rs0; l1 = l1 * f1 + rs1;
        m0 = mn0; m1 = mn1;
#pragma unroll
        for (int dt = 0; dt < 8; dt++) {
            oacc[dt][0] *= f0; oacc[dt][1] *= f0;
            oacc[dt][2] *= f1; oacc[dt][3] *= f1;
        }
#pragma unroll
        for (int ks = 0; ks < 8; ks++) {
            uint32_t ah[4], al[4];
            cvt2(sfr[2 * ks][0],     sfr[2 * ks][1],     ah[0], al[0]);
            cvt2(sfr[2 * ks][2],     sfr[2 * ks][3],     ah[1], al[1]);
            cvt2(sfr[2 * ks + 1][0], sfr[2 * ks + 1][1], ah[2], al[2]);
            cvt2(sfr[2 * ks + 1][2], sfr[2 * ks + 1][3], ah[3], al[3]);
#pragma unroll
            for (int dt = 0; dt < 8; dt++) {
                uint32_t vbh[2], vbl[2];
                const uint32_t rv = sV + (ks * 16 + (lane & 15)) * 144 + dt * 16;
                LDM2T(vbh[0], vbh[1], rv);
                LDM2T(vbl[0], vbl[1], rv + FK_PL);
                MMA16816(oacc[dt], ah, vbh);
                MMA16816(oacc[dt], ah, vbl);
                MMA16816(oacc[dt], al, vbh);
            }
        }
        if (kt < 7) {
            __syncthreads();
            loadKV(kt + 1);
            CP_COMMIT(); CP_WAIT0();
            __syncthreads();
        }
    }

    const float i0 = 1.f / l0, i1 = 1.f / l1;
    const int r = w * 16 + (lane >> 2);
    const int cc = (lane & 3) * 2;
#pragma unroll
    for (int dt = 0; dt < 8; dt++) {
        uint32_t hh, ll;
        const size_t o0 = (rowQ + r) * DIM + colh + dt * 8 + cc;
        cvt2(oacc[dt][0] * i0, oacc[dt][1] * i0, hh, ll);
        *(uint32_t*)(oh + o0) = hh;
        *(uint32_t*)(ol + o0) = ll;
        const size_t o1 = o0 + 8 * DIM;
        cvt2(oacc[dt][2] * i1, oacc[dt][3] * i1, hh, ll);
        *(uint32_t*)(oh + o1) = hh;
        *(uint32_t*)(ol + o1) = ll;
    }
}

// ---------------- LayerNorm -> split-bf16 planes ---------------------------
__global__ __launch_bounds__(256) void ln_kernel(const float* __restrict__ x,
                                                 bf16* __restrict__ yh,
                                                 bf16* __restrict__ yl,
                                                 const float* __restrict__ alpha,
                                                 const float* __restrict__ beta) {
    __shared__ float sh_s[8], sh_q[8];
    const size_t row = blockIdx.x;
    const float4* xr = (const float4*)(x + row * DIM);
    const int tid = threadIdx.x;
    float4 v = xr[tid];
    float s = v.x + v.y + v.z + v.w;
    float q = v.x*v.x + v.y*v.y + v.z*v.z + v.w*v.w;
#pragma unroll
    for (int o = 16; o; o >>= 1) {
        s += __shfl_xor_sync(0xffffffffu, s, o);
        q += __shfl_xor_sync(0xffffffffu, q, o);
    }
    if ((tid & 31) == 0) { sh_s[tid >> 5] = s; sh_q[tid >> 5] = q; }
    __syncthreads();
    if (tid < 32) {
        s = (tid < 8) ? sh_s[tid] : 0.f;
        q = (tid < 8) ? sh_q[tid] : 0.f;
#pragma unroll
        for (int o = 4; o; o >>= 1) {
            s += __shfl_xor_sync(0xffffffffu, s, o);
            q += __shfl_xor_sync(0xffffffffu, q, o);
        }
        if (tid == 0) { sh_s[0] = s; sh_q[0] = q; }
    }
    __syncthreads();
    s = sh_s[0]; q = sh_q[0];
    const float mean = s * (1.0f / DIM);
    const float var  = (q - (float)DIM * mean * mean) * (1.0f / (DIM - 1));
    const float inv  = 1.0f / (sqrtf(fmaxf(var, 0.f)) + 1e-6f);
    const float4 a = ((const float4*)alpha)[tid];
    const float4 b = ((const float4*)beta)[tid];
    float ox = a.x * (v.x - mean) * inv + b.x;
    float oy = a.y * (v.y - mean) * inv + b.y;
    float oz = a.z * (v.z - mean) * inv + b.z;
    float ow = a.w * (v.w - mean) * inv + b.w;
    uint32_t h0, l0, h1, l1;
    cvt2(ox, oy, h0, l0);
    cvt2(oz, ow, h1, l1);
    *(uint2*)(yh + row * DIM + 4 * tid) = make_uint2(h0, h1);
    *(uint2*)(yl + row * DIM + 4 * tid) = make_uint2(l0, l1);
}

// ---------------- launch ----------------------------------------------------
template<typename T>
static T* symaddr(const void* s) {
    void* p = nullptr;
    cudaGetSymbolAddress(&p, s);
    return (T*)p;
}

#define SMEM_G (2 * (2 * 128 * 80 + 2 * 128 * 80))   // 81920

extern "C" void kernel_launch(void* const* d_in, const int* in_sizes, int n_in,
                              void* d_out, int out_size) {
    (void)in_sizes; (void)n_in; (void)out_size;
    const float* x     = (const float*)d_in[0];
    const float* wq    = (const float*)d_in[2];
    const float* bq    = (const float*)d_in[3];
    const float* wk    = (const float*)d_in[4];
    const float* bk    = (const float*)d_in[5];
    const float* wv    = (const float*)d_in[6];
    const float* bv    = (const float*)d_in[7];
    const float* wo    = (const float*)d_in[8];
    const float* bo    = (const float*)d_in[9];
    const float* w1    = (const float*)d_in[10];
    const float* b1    = (const float*)d_in[11];
    const float* w2    = (const float*)d_in[12];
    const float* b2    = (const float*)d_in[13];
    const float* alpha = (const float*)d_in[14];
    const float* beta  = (const float*)d_in[15];
    float* out = (float*)d_out;

    cudaFuncSetAttribute(gemm4<true>,
                         cudaFuncAttributeMaxDynamicSharedMemorySize, SMEM_G);
    cudaFuncSetAttribute(gemm4<false>,
                         cudaFuncAttributeMaxDynamicSharedMemorySize, SMEM_G);
    cudaFuncSetAttribute(flash_attn,
                         cudaFuncAttributeMaxDynamicSharedMemorySize, FSMEM);

    bf16* lnh = symaddr<bf16>(g_lnh);  bf16* lnl = symaddr<bf16>(g_lnl);
    bf16* qkvh = symaddr<bf16>(g_qkvh);
    bf16* qkvl = symaddr<bf16>(g_qkvl);
    float* x1 = symaddr<float>(g_x1);
    bf16* wh  = symaddr<bf16>(g_wh);   bf16* wl  = symaddr<bf16>(g_wl);
    bf16* hidh = symaddr<bf16>(g_hid);
    bf16* hidl = hidh + (size_t)MROWS * HFF;
    float* b3 = symaddr<float>(g_b3);

    // 0) weight conversion + bias concat
    const int n4p = DIM * DIM / 4, n4f = HFF * DIM / 4;
    wconv<<<(n4p + 255) / 256, 256>>>(wq, wh + WOFF_Q, wl + WOFF_Q, n4p);
    wconv<<<(n4p + 255) / 256, 256>>>(wk, wh + WOFF_Q + (size_t)DIM*DIM,
                                      wl + WOFF_Q + (size_t)DIM*DIM, n4p);
    wconv<<<(n4p + 255) / 256, 256>>>(wv, wh + WOFF_Q + (size_t)2*DIM*DIM,
                                      wl + WOFF_Q + (size_t)2*DIM*DIM, n4p);
    wconv<<<(n4p + 255) / 256, 256>>>(wo, wh + WOFF_O, wl + WOFF_O, n4p);
    wconv<<<(n4f + 255) / 256, 256>>>(w1, wh + WOFF_1, wl + WOFF_1, n4f);
    wconv<<<(n4f + 255) / 256, 256>>>(w2, wh + WOFF_2, wl + WOFF_2, n4f);
    bcat<<<(QKVN + 255) / 256, 256>>>(bq, bk, bv, b3);

    // 1) LN1
    ln_kernel<<<MROWS, 256>>>(x, lnh, lnl, alpha, beta);

    // 2) fused QKV projection: [8192, 3072]
    dim3 gqkv(QKVN / 128, MROWS / 128, 1);
    gemm4<true><<<gqkv, 128, SMEM_G>>>(
        lnh, lnl, DIM, wh + WOFF_Q, wl + WOFF_Q, DIM,
        nullptr, qkvh, qkvl, QKVN, DIM, b3, nullptr, 0, 1.f, 0);

    // 3-5) fused attention -> split planes (into lnh/lnl, reused)
    dim3 gfa(SEQ / 64, BATCH * HEADS, 1);
    flash_attn<<<gfa, 128, FSMEM>>>(qkvh, qkvl, lnh, lnl);

    // 6) O projection + residual x -> x1 (fp32)
    dim3 gw(DIM / 128, MROWS / 128, 1);
    gemm4<false><<<gw, 128, SMEM_G>>>(
        lnh, lnl, DIM, wh + WOFF_O, wl + WOFF_O, DIM,
        x1, nullptr, nullptr, DIM, DIM, bo, x, DIM, 1.f, 0);

    // 7) LN2
    ln_kernel<<<MROWS, 256>>>(x1, lnh, lnl, alpha, beta);

    // 8) FFN1 (+ReLU)
    dim3 gf1(HFF / 128, MROWS / 128, 1);
    gemm4<true><<<gf1, 128, SMEM_G>>>(
        lnh, lnl, DIM, wh + WOFF_1, wl + WOFF_1, DIM,
        nullptr, hidh, hidl, HFF, DIM, b1, nullptr, 0, 1.f, 1);

    // 9) FFN2 + residual x1 -> out (fp32)
    dim3 gf2(DIM / 128, MROWS / 128, 1);
    gemm4<false><<<gf2, 128, SMEM_G>>>(
        hidh, hidl, HFF, wh + WOFF_2, wl + WOFF_2, HFF,
        out, nullptr, nullptr, DIM, HFF, b2, x1, DIM, 1.f, 0);
}

// round 11
// speedup vs baseline: 3.8497x; 1.2014x over previous
#include <cuda_runtime.h>
#include <cuda_bf16.h>
#include <cuda_fp16.h>
#include <math.h>
#include <stdint.h>

#define BATCH 8
#define SEQ   1024
#define DIM   1024
#define HEADS 16
#define DH    64
#define HFF   4096
#define MROWS (BATCH*SEQ)   // 8192
#define QKVN  (3*DIM)       // 3072

typedef __nv_bfloat16 bf16;

// ---------------- scratch (static device arrays: allocation-free) ----------
__device__ bf16 g_lnh[(size_t)MROWS*DIM], g_lnl[(size_t)MROWS*DIM];
__device__ bf16 g_qkvh[(size_t)MROWS*QKVN], g_qkvl[(size_t)MROWS*QKVN];
__device__ float g_x1[(size_t)MROWS*DIM];
__device__ bf16 g_hid[(size_t)2*MROWS*HFF];       // fp16 split planes (punned)
__device__ float g_b3[QKVN];
// weight planes: wq|wk|wv|wo bf16 split; w1,w2 single fp16 (punned into g_wh)
#define WOFF_Q  0
#define WOFF_O  ((size_t)3*DIM*DIM)
#define WOFF_1  ((size_t)4*DIM*DIM)
#define WOFF_2  ((size_t)4*DIM*DIM + (size_t)HFF*DIM)
__device__ bf16 g_wh[(size_t)4*DIM*DIM + (size_t)2*HFF*DIM];
__device__ bf16 g_wl[(size_t)4*DIM*DIM];

// ==================== helpers ====================
__device__ __forceinline__ uint32_t smem_u32(const void* p) {
    uint32_t a;
    asm("{ .reg .u64 t; cvta.to.shared.u64 t, %1; cvt.u32.u64 %0, t; }"
        : "=r"(a) : "l"(p));
    return a;
}
__device__ __forceinline__ void cp_async16(uint32_t dst, const void* src) {
    uint64_t g;
    asm("cvta.to.global.u64 %0, %1;" : "=l"(g) : "l"(src));
    asm volatile("cp.async.cg.shared.global [%0], [%1], 16;"
                 :: "r"(dst), "l"(g) : "memory");
}
#define CP_COMMIT() asm volatile("cp.async.commit_group;" ::: "memory")
#define CP_WAIT0()  asm volatile("cp.async.wait_group 0;"  ::: "memory")

// fp32 -> (hi, lo) bf16 split, packed pairs
__device__ __forceinline__ void cvt2(float a, float b, uint32_t& h, uint32_t& l) {
    __nv_bfloat162 hh = __floats2bfloat162_rn(a, b);
    float ra = a - __bfloat162float(hh.x);
    float rb = b - __bfloat162float(hh.y);
    __nv_bfloat162 ll = __floats2bfloat162_rn(ra, rb);
    h = *(uint32_t*)&hh;
    l = *(uint32_t*)&ll;
}
// fp32 -> (hi, lo) fp16 split, packed pairs
__device__ __forceinline__ void cvt2h(float a, float b, uint32_t& h, uint32_t& l) {
    __half2 hh = __floats2half2_rn(a, b);
    float ra = a - __half2float(__low2half(hh));
    float rb = b - __half2float(__high2half(hh));
    __half2 ll = __floats2half2_rn(ra, rb);
    h = *(uint32_t*)&hh;
    l = *(uint32_t*)&ll;
}

#define LDM4(r0, r1, r2, r3, addr) \
    asm volatile("ldmatrix.sync.aligned.m8n8.x4.shared.b16 {%0,%1,%2,%3}, [%4];" \
                 : "=r"(r0), "=r"(r1), "=r"(r2), "=r"(r3) : "r"(addr))
#define LDM2T(r0, r1, addr) \
    asm volatile("ldmatrix.sync.aligned.m8n8.x2.trans.shared.b16 {%0,%1}, [%2];" \
                 : "=r"(r0), "=r"(r1) : "r"(addr))
#define MMA16816(c, a, b) \
    asm volatile("mma.sync.aligned.m16n8k16.row.col.f32.bf16.bf16.f32 " \
                 "{%0,%1,%2,%3}, {%4,%5,%6,%7}, {%8,%9}, {%0,%1,%2,%3};" \
                 : "+f"((c)[0]), "+f"((c)[1]), "+f"((c)[2]), "+f"((c)[3]) \
                 : "r"((a)[0]), "r"((a)[1]), "r"((a)[2]), "r"((a)[3]), \
                   "r"((b)[0]), "r"((b)[1]))
#define MMAH16816(c, a, b) \
    asm volatile("mma.sync.aligned.m16n8k16.row.col.f32.f16.f16.f32 " \
                 "{%0,%1,%2,%3}, {%4,%5,%6,%7}, {%8,%9}, {%0,%1,%2,%3};" \
                 : "+f"((c)[0]), "+f"((c)[1]), "+f"((c)[2]), "+f"((c)[3]) \
                 : "r"((a)[0]), "r"((a)[1]), "r"((a)[2]), "r"((a)[3]), \
                   "r"((b)[0]), "r"((b)[1]))

// ------------- weight conversions -------------------------------------------
// all 4 projection weights (1M fp32 each) -> bf16 split planes, one launch
__global__ __launch_bounds__(256) void wconv_all(
    const float* __restrict__ w0, const float* __restrict__ w1p,
    const float* __restrict__ w2p, const float* __restrict__ w3,
    bf16* __restrict__ h, bf16* __restrict__ l) {
    const int n4p = DIM * DIM / 4;
    const int i = blockIdx.x * 256 + threadIdx.x;       // [0, 4*n4p)
    const float* src = (i < n4p) ? w0 : (i < 2 * n4p) ? w1p
                     : (i < 3 * n4p) ? w2p : w3;
    const int j = i & (n4p - 1);
    const float4 v = ((const float4*)src)[j];
    uint32_t h0, l0, h1, l1;
    cvt2(v.x, v.y, h0, l0);
    cvt2(v.z, v.w, h1, l1);
    ((uint2*)h)[i] = make_uint2(h0, h1);
    ((uint2*)l)[i] = make_uint2(l0, l1);
}
// fp32 -> single fp16 plane
__global__ __launch_bounds__(256) void wconvh(const float* __restrict__ w,
                                              __half* __restrict__ o, int n2) {
    const int i = blockIdx.x * 256 + threadIdx.x;
    if (i >= n2) return;
    const float2 v = ((const float2*)w)[i];
    ((__half2*)o)[i] = __floats2half2_rn(v.x, v.y);
}
__global__ __launch_bounds__(256) void bcat(const float* __restrict__ a,
                                            const float* __restrict__ b,
                                            const float* __restrict__ c,
                                            float* __restrict__ o) {
    const int i = blockIdx.x * 256 + threadIdx.x;
    if (i < DIM)            o[i] = a[i];
    else if (i < 2 * DIM)   o[i] = b[i - DIM];
    else if (i < 3 * DIM)   o[i] = c[i - 2 * DIM];
}

// ==================== split-bf16 3-MMA GEMM (QKV / O projection) ===========
template<bool OSPLIT>
__global__ __launch_bounds__(128, 2) void gemm4(
    const bf16* __restrict__ Ah, const bf16* __restrict__ Al, int lda,
    const bf16* __restrict__ Bh, const bf16* __restrict__ Bl, int ldb,
    float* __restrict__ Cf,
    bf16* __restrict__ Ch, bf16* __restrict__ Cl, int ldc,
    int K,
    const float* __restrict__ bias,
    const float* __restrict__ resid, int ldr,
    float scale, int relu)
{
    constexpr int BK = 32;
    constexpr int ABYTES = 128 * 80;
    constexpr int BBYTES = 128 * 80;
    constexpr int SS = 2 * ABYTES + 2 * BBYTES;

    extern __shared__ char sm[];
    const uint32_t smBase = smem_u32(sm);

    const int tid = threadIdx.x, wid = tid >> 5, lane = tid & 31;
    const int wm = wid >> 1, wn = wid & 1;
    const int m0 = blockIdx.y * 128, n0 = blockIdx.x * 128;

    float acc[4][8][4];
#pragma unroll
    for (int i = 0; i < 4; i++)
#pragma unroll
        for (int j = 0; j < 8; j++)
#pragma unroll
            for (int r = 0; r < 4; r++) acc[i][j][r] = 0.f;

    auto issueA = [&](int s, int t) {
        const uint32_t sA = smBase + s * SS;
#pragma unroll
        for (int i = 0; i < 8; i++) {
            const int idx = i * 128 + tid;
            const int c = idx & 3, row = (idx >> 2) & 127, pl = idx >> 9;
            const bf16* g = (pl ? Al : Ah) + (size_t)(m0 + row) * lda + t * BK + c * 8;
            cp_async16(sA + pl * ABYTES + row * 80 + c * 16, g);
        }
    };
    auto issueB = [&](int s, int t) {
        const uint32_t sB = smBase + s * SS + 2 * ABYTES;
#pragma unroll
        for (int i = 0; i < 8; i++) {
            const int idx = i * 128 + tid;
            const int c = idx & 3, row = (idx >> 2) & 127, pl = idx >> 9;
            const bf16* g = (pl ? Bl : Bh) + (size_t)(n0 + row) * ldb + t * BK + c * 8;
            cp_async16(sB + pl * BBYTES + row * 80 + c * 16, g);
        }
    };

    auto compute = [&](int s) {
        const uint32_t aHiB = smBase + s * SS;
        const uint32_t aLoB = aHiB + ABYTES;
        const uint32_t bHiB = aHiB + 2 * ABYTES;
        const uint32_t bLoB = bHiB + BBYTES;
#pragma unroll
        for (int ks = 0; ks < 2; ks++) {
            uint32_t bh[8][2], bl[8][2];
#pragma unroll
            for (int p = 0; p < 4; p++) {
                const uint32_t rb =
                    (uint32_t)((wn * 64 + p * 16 + ((lane >> 4) & 1) * 8 + (lane & 7)) * 80
                               + ks * 32 + ((lane >> 3) & 1) * 16);
                LDM4(bh[2*p][0], bh[2*p][1], bh[2*p+1][0], bh[2*p+1][1], bHiB + rb);
                LDM4(bl[2*p][0], bl[2*p][1], bl[2*p+1][0], bl[2*p+1][1], bLoB + rb);
            }
            const uint32_t kbA = (uint32_t)((ks * 16 + (lane >> 4) * 8) * 2);
#pragma unroll
            for (int mt = 0; mt < 4; mt++) {
                uint32_t ah[4], al[4];
                const uint32_t ra = (uint32_t)((wm * 64 + mt * 16 + (lane & 15)) * 80) + kbA;
                LDM4(ah[0], ah[1], ah[2], ah[3], aHiB + ra);
                LDM4(al[0], al[1], al[2], al[3], aLoB + ra);
#pragma unroll
                for (int nt = 0; nt < 8; nt++) MMA16816(acc[mt][nt], ah, bh[nt]);
#pragma unroll
                for (int nt = 0; nt < 8; nt++) MMA16816(acc[mt][nt], ah, bl[nt]);
#pragma unroll
                for (int nt = 0; nt < 8; nt++) MMA16816(acc[mt][nt], al, bh[nt]);
            }
        }
    };

    const int T = K / BK;
    issueA(0, 0);
    issueB(0, 0);
    CP_COMMIT();
    CP_WAIT0();
    __syncthreads();

    for (int t = 0; t < T; t++) {
        const int s = t & 1;
        if (t + 1 < T) {
            issueA(s ^ 1, t + 1);
            issueB(s ^ 1, t + 1);
            CP_COMMIT();
        }
        compute(s);
        CP_WAIT0();
        __syncthreads();
    }

#pragma unroll
    for (int mt = 0; mt < 4; mt++) {
#pragma unroll
        for (int nt = 0; nt < 8; nt++) {
            const int r0 = m0 + wm * 64 + mt * 16 + (lane >> 2);
            const int cc = n0 + wn * 64 + nt * 8 + (lane & 3) * 2;
#pragma unroll
            for (int h = 0; h < 2; h++) {
                const int m = r0 + h * 8;
                float vx = acc[mt][nt][2 * h]     * scale;
                float vy = acc[mt][nt][2 * h + 1] * scale;
                if (bias)  { vx += bias[cc]; vy += bias[cc + 1]; }
                if (relu)  { vx = fmaxf(vx, 0.f); vy = fmaxf(vy, 0.f); }
                if (resid) {
                    const float2 rr = *(const float2*)(resid + (size_t)m * ldr + cc);
                    vx += rr.x; vy += rr.y;
                }
                if constexpr (OSPLIT) {
                    uint32_t hh, ll;
                    cvt2(vx, vy, hh, ll);
                    *(uint32_t*)(Ch + (size_t)m * ldc + cc) = hh;
                    *(uint32_t*)(Cl + (size_t)m * ldc + cc) = ll;
                } else {
                    *(float2*)(Cf + (size_t)m * ldc + cc) = make_float2(vx, vy);
                }
            }
        }
    }
}

// ==================== fp16 2-MMA GEMM (FFN path) ============================
// A: exact fp16 hi/lo split planes; B: single fp16 plane (weight-rounded).
// C = scale*(Ah+Al)B + bias (+relu, +resid). Error ~2^-11.8 from B rounding.
template<bool OSPLIT>
__global__ __launch_bounds__(128, 2) void gemm_h2(
    const __half* __restrict__ Ah, const __half* __restrict__ Al, int lda,
    const __half* __restrict__ B, int ldb,
    float* __restrict__ Cf,
    __half* __restrict__ Ch, __half* __restrict__ Cl, int ldc,
    int K,
    const float* __restrict__ bias,
    const float* __restrict__ resid, int ldr,
    int relu)
{
    constexpr int BK = 32;
    constexpr int ABYTES = 128 * 80;
    constexpr int BBYTES = 128 * 80;
    constexpr int SS = 2 * ABYTES + BBYTES;   // 30720

    extern __shared__ char sm[];
    const uint32_t smBase = smem_u32(sm);

    const int tid = threadIdx.x, wid = tid >> 5, lane = tid & 31;
    const int wm = wid >> 1, wn = wid & 1;
    const int m0 = blockIdx.y * 128, n0 = blockIdx.x * 128;

    float acc[4][8][4];
#pragma unroll
    for (int i = 0; i < 4; i++)
#pragma unroll
        for (int j = 0; j < 8; j++)
#pragma unroll
            for (int r = 0; r < 4; r++) acc[i][j][r] = 0.f;

    auto issueA = [&](int s, int t) {
        const uint32_t sA = smBase + s * SS;
#pragma unroll
        for (int i = 0; i < 8; i++) {
            const int idx = i * 128 + tid;
            const int c = idx & 3, row = (idx >> 2) & 127, pl = idx >> 9;
            const __half* g = (pl ? Al : Ah) + (size_t)(m0 + row) * lda + t * BK + c * 8;
            cp_async16(sA + pl * ABYTES + row * 80 + c * 16, g);
        }
    };
    auto issueB = [&](int s, int t) {
        const uint32_t sB = smBase + s * SS + 2 * ABYTES;
#pragma unroll
        for (int i = 0; i < 4; i++) {
            const int idx = i * 128 + tid;
            const int c = idx & 3, row = idx >> 2;
            const __half* g = B + (size_t)(n0 + row) * ldb + t * BK + c * 8;
            cp_async16(sB + row * 80 + c * 16, g);
        }
    };

    auto compute = [&](int s) {
        const uint32_t aHiB = smBase + s * SS;
        const uint32_t aLoB = aHiB + ABYTES;
        const uint32_t bB   = aHiB + 2 * ABYTES;
#pragma unroll
        for (int ks = 0; ks < 2; ks++) {
            uint32_t bf[8][2];
#pragma unroll
            for (int p = 0; p < 4; p++) {
                const uint32_t rb =
                    (uint32_t)((wn * 64 + p * 16 + ((lane >> 4) & 1) * 8 + (lane & 7)) * 80
                               + ks * 32 + ((lane >> 3) & 1) * 16);
                LDM4(bf[2*p][0], bf[2*p][1], bf[2*p+1][0], bf[2*p+1][1], bB + rb);
            }
            const uint32_t kbA = (uint32_t)((ks * 16 + (lane >> 4) * 8) * 2);
#pragma unroll
            for (int mt = 0; mt < 4; mt++) {
                uint32_t ah[4], al[4];
                const uint32_t ra = (uint32_t)((wm * 64 + mt * 16 + (lane & 15)) * 80) + kbA;
                LDM4(ah[0], ah[1], ah[2], ah[3], aHiB + ra);
                LDM4(al[0], al[1], al[2], al[3], aLoB + ra);
#pragma unroll
                for (int nt = 0; nt < 8; nt++) MMAH16816(acc[mt][nt], ah, bf[nt]);
#pragma unroll
                for (int nt = 0; nt < 8; nt++) MMAH16816(acc[mt][nt], al, bf[nt]);
            }
        }
    };

    const int T = K / BK;
    issueA(0, 0);
    issueB(0, 0);
    CP_COMMIT();
    CP_WAIT0();
    __syncthreads();

    for (int t = 0; t < T; t++) {
        const int s = t & 1;
        if (t + 1 < T) {
            issueA(s ^ 1, t + 1);
            issueB(s ^ 1, t + 1);
            CP_COMMIT();
        }
        compute(s);
        CP_WAIT0();
        __syncthreads();
    }

#pragma unroll
    for (int mt = 0; mt < 4; mt++) {
#pragma unroll
        for (int nt = 0; nt < 8; nt++) {
            const int r0 = m0 + wm * 64 + mt * 16 + (lane >> 2);
            const int cc = n0 + wn * 64 + nt * 8 + (lane & 3) * 2;
#pragma unroll
            for (int h = 0; h < 2; h++) {
                const int m = r0 + h * 8;
                float vx = acc[mt][nt][2 * h];
                float vy = acc[mt][nt][2 * h + 1];
                if (bias)  { vx += bias[cc]; vy += bias[cc + 1]; }
                if (relu)  { vx = fmaxf(vx, 0.f); vy = fmaxf(vy, 0.f); }
                if (resid) {
                    const float2 rr = *(const float2*)(resid + (size_t)m * ldr + cc);
                    vx += rr.x; vy += rr.y;
                }
                if constexpr (OSPLIT) {
                    uint32_t hh, ll;
                    cvt2h(vx, vy, hh, ll);
                    *(uint32_t*)(Ch + (size_t)m * ldc + cc) = hh;
                    *(uint32_t*)(Cl + (size_t)m * ldc + cc) = ll;
                } else {
                    *(float2*)(Cf + (size_t)m * ldc + cc) = make_float2(vx, vy);
                }
            }
        }
    }
}

// ==================== fused flash attention ====================
#define FQ_PL 9216
#define FK_PL 18432
#define FSMEM (2*FQ_PL + 4*FK_PL)   // 92160

__global__ __launch_bounds__(128, 2) void flash_attn(
    const bf16* __restrict__ qkvh, const bf16* __restrict__ qkvl,
    bf16* __restrict__ oh, bf16* __restrict__ ol)
{
    extern __shared__ char sm[];
    const uint32_t smBase = smem_u32(sm);
    const int tid = threadIdx.x, lane = tid & 31, w = tid >> 5;
    const int b = blockIdx.y >> 4, h = blockIdx.y & 15;
    const size_t rowQ  = (size_t)b * SEQ + blockIdx.x * 64;
    const size_t rowKV = (size_t)b * SEQ;
    const int colh = h * DH;

    const uint32_t sQ = smBase;
    const uint32_t sK = smBase + 2 * FQ_PL;
    const uint32_t sV = sK + 2 * FK_PL;

#pragma unroll
    for (int i = 0; i < 8; i++) {
        const int idx = i * 128 + tid;
        const int pl = idx >> 9, row = (idx >> 3) & 63, c = idx & 7;
        const bf16* g = (pl ? qkvl : qkvh) + (rowQ + row) * QKVN + colh + c * 8;
        cp_async16(sQ + pl * FQ_PL + row * 144 + c * 16, g);
    }
    auto loadKV = [&](int kt) {
        const size_t base = (rowKV + kt * 128) * QKVN + colh;
#pragma unroll
        for (int i = 0; i < 16; i++) {
            const int idx = i * 128 + tid;
            const int pl = idx >> 10, row = (idx >> 3) & 127, c = idx & 7;
            const size_t off = base + (size_t)row * QKVN + c * 8;
            const uint32_t d = pl * FK_PL + row * 144 + c * 16;
            cp_async16(sK + d, (pl ? qkvl : qkvh) + off + DIM);
            cp_async16(sV + d, (pl ? qkvl : qkvh) + off + 2 * DIM);
        }
    };
    loadKV(0);
    CP_COMMIT(); CP_WAIT0();
    __syncthreads();

    float oacc[8][4];
#pragma unroll
    for (int i = 0; i < 8; i++)
#pragma unroll
        for (int j = 0; j < 4; j++) oacc[i][j] = 0.f;
    float m0 = -INFINITY, m1 = -INFINITY, l0 = 0.f, l1 = 0.f;

    for (int kt = 0; kt < 8; kt++) {
        float sfr[16][4];
#pragma unroll
        for (int i = 0; i < 16; i++)
#pragma unroll
            for (int j = 0; j < 4; j++) sfr[i][j] = 0.f;
#pragma unroll
        for (int ks = 0; ks < 4; ks++) {
            uint32_t qa[4], qb[4];
            const uint32_t ra = sQ + (w * 16 + (lane & 15)) * 144
                              + ks * 32 + (lane >> 4) * 16;
            LDM4(qa[0], qa[1], qa[2], qa[3], ra);
            LDM4(qb[0], qb[1], qb[2], qb[3], ra + FQ_PL);
#pragma unroll
            for (int p = 0; p < 8; p++) {
                uint32_t kbh[4], kbl[4];
                const uint32_t rb = sK + (p * 16 + ((lane >> 4) & 1) * 8 + (lane & 7)) * 144
                                  + ks * 32 + ((lane >> 3) & 1) * 16;
                LDM4(kbh[0], kbh[1], kbh[2], kbh[3], rb);
                LDM4(kbl[0], kbl[1], kbl[2], kbl[3], rb + FK_PL);
                MMA16816(sfr[2*p],   qa, (&kbh[0]));
                MMA16816(sfr[2*p],   qa, (&kbl[0]));
                MMA16816(sfr[2*p],   qb, (&kbh[0]));
                MMA16816(sfr[2*p+1], qa, (&kbh[2]));
                MMA16816(sfr[2*p+1], qa, (&kbl[2]));
                MMA16816(sfr[2*p+1], qb, (&kbh[2]));
            }
        }
        float mx0 = -INFINITY, mx1 = -INFINITY;
#pragma unroll
        for (int nt = 0; nt < 16; nt++) {
            mx0 = fmaxf(mx0, fmaxf(sfr[nt][0], sfr[nt][1]));
            mx1 = fmaxf(mx1, fmaxf(sfr[nt][2], sfr[nt][3]));
        }
        mx0 = fmaxf(mx0, __shfl_xor_sync(0xffffffffu, mx0, 1));
        mx0 = fmaxf(mx0, __shfl_xor_sync(0xffffffffu, mx0, 2));
        mx1 = fmaxf(mx1, __shfl_xor_sync(0xffffffffu, mx1, 1));
        mx1 = fmaxf(mx1, __shfl_xor_sync(0xffffffffu, mx1, 2));
        const float mn0 = fmaxf(m0, 0.125f * mx0);
        const float mn1 = fmaxf(m1, 0.125f * mx1);
        const float f0 = __expf(m0 - mn0);
        const float f1 = __expf(m1 - mn1);
        float rs0 = 0.f, rs1 = 0.f;
#pragma unroll
        for (int nt = 0; nt < 16; nt++) {
            const float p0 = __expf(fmaf(sfr[nt][0], 0.125f, -mn0));
            const float p1 = __expf(fmaf(sfr[nt][1], 0.125f, -mn0));
            const float p2 = __expf(fmaf(sfr[nt][2], 0.125f, -mn1));
            const float p3 = __expf(fmaf(sfr[nt][3], 0.125f, -mn1));
            rs0 += p0 + p1; rs1 += p2 + p3;
            sfr[nt][0] = p0; sfr[nt][1] = p1; sfr[nt][2] = p2; sfr[nt][3] = p3;
        }
        rs0 += __shfl_xor_sync(0xffffffffu, rs0, 1);
        rs0 += __shfl_xor_sync(0xffffffffu, rs0, 2);
        rs1 += __shfl_xor_sync(0xffffffffu, rs1, 1);
        rs1 += __shfl_xor_sync(0xffffffffu, rs1, 2);
        l0 = l0 * f0 + rs0; l1 = l1 * f1 + rs1;
        m0 = mn0; m1 = mn1;
#pragma unroll
        for (int dt = 0; dt < 8; dt++) {
            oacc[dt][0] *= f0; oacc[dt][1] *= f0;
            oacc[dt][2] *= f1; oacc[dt][3] *= f1;
        }
#pragma unroll
        for (int ks = 0; ks < 8; ks++) {
            uint32_t ah[4], al[4];
            cvt2(sfr[2 * ks][0],     sfr[2 * ks][1],     ah[0], al[0]);
            cvt2(sfr[2 * ks][2],     sfr[2 * ks][3],     ah[1], al[1]);
            cvt2(sfr[2 * ks + 1][0], sfr[2 * ks + 1][1], ah[2], al[2]);
            cvt2(sfr[2 * ks + 1][2], sfr[2 * ks + 1][3], ah[3], al[3]);
#pragma unroll
            for (int dt = 0; dt < 8; dt++) {
                uint32_t vbh[2], vbl[2];
                const uint32_t rv = sV + (ks * 16 + (lane & 15)) * 144 + dt * 16;
                LDM2T(vbh[0], vbh[1], rv);
                LDM2T(vbl[0], vbl[1], rv + FK_PL);
                MMA16816(oacc[dt], ah, vbh);
                MMA16816(oacc[dt], ah, vbl);
                MMA16816(oacc[dt], al, vbh);
            }
        }
        if (kt < 7) {
            __syncthreads();
            loadKV(kt + 1);
            CP_COMMIT(); CP_WAIT0();
            __syncthreads();
        }
    }

    const float i0 = 1.f / l0, i1 = 1.f / l1;
    const int r = w * 16 + (lane >> 2);
    const int cc = (lane & 3) * 2;
#pragma unroll
    for (int dt = 0; dt < 8; dt++) {
        uint32_t hh, ll;
        const size_t o0 = (rowQ + r) * DIM + colh + dt * 8 + cc;
        cvt2(oacc[dt][0] * i0, oacc[dt][1] * i0, hh, ll);
        *(uint32_t*)(oh + o0) = hh;
        *(uint32_t*)(ol + o0) = ll;
        const size_t o1 = o0 + 8 * DIM;
        cvt2(oacc[dt][2] * i1, oacc[dt][3] * i1, hh, ll);
        *(uint32_t*)(oh + o1) = hh;
        *(uint32_t*)(ol + o1) = ll;
    }
}

// ---------------- LayerNorm -> split planes (bf16 or fp16) ------------------
template<bool FP16>
__global__ __launch_bounds__(256) void ln_kernel(const float* __restrict__ x,
                                                 uint16_t* __restrict__ yh,
                                                 uint16_t* __restrict__ yl,
                                                 const float* __restrict__ alpha,
                                                 const float* __restrict__ beta) {
    __shared__ float sh_s[8], sh_q[8];
    const size_t row = blockIdx.x;
    const float4* xr = (const float4*)(x + row * DIM);
    const int tid = threadIdx.x;
    float4 v = xr[tid];
    float s = v.x + v.y + v.z + v.w;
    float q = v.x*v.x + v.y*v.y + v.z*v.z + v.w*v.w;
#pragma unroll
    for (int o = 16; o; o >>= 1) {
        s += __shfl_xor_sync(0xffffffffu, s, o);
        q += __shfl_xor_sync(0xffffffffu, q, o);
    }
    if ((tid & 31) == 0) { sh_s[tid >> 5] = s; sh_q[tid >> 5] = q; }
    __syncthreads();
    if (tid < 32) {
        s = (tid < 8) ? sh_s[tid] : 0.f;
        q = (tid < 8) ? sh_q[tid] : 0.f;
#pragma unroll
        for (int o = 4; o; o >>= 1) {
            s += __shfl_xor_sync(0xffffffffu, s, o);
            q += __shfl_xor_sync(0xffffffffu, q, o);
        }
        if (tid == 0) { sh_s[0] = s; sh_q[0] = q; }
    }
    __syncthreads();
    s = sh_s[0]; q = sh_q[0];
    const float mean = s * (1.0f / DIM);
    const float var  = (q - (float)DIM * mean * mean) * (1.0f / (DIM - 1));
    const float inv  = 1.0f / (sqrtf(fmaxf(var, 0.f)) + 1e-6f);
    const float4 a = ((const float4*)alpha)[tid];
    const float4 b = ((const float4*)beta)[tid];
    float ox = a.x * (v.x - mean) * inv + b.x;
    float oy = a.y * (v.y - mean) * inv + b.y;
    float oz = a.z * (v.z - mean) * inv + b.z;
    float ow = a.w * (v.w - mean) * inv + b.w;
    uint32_t h0, l0, h1, l1;
    if constexpr (FP16) {
        cvt2h(ox, oy, h0, l0);
        cvt2h(oz, ow, h1, l1);
    } else {
        cvt2(ox, oy, h0, l0);
        cvt2(oz, ow, h1, l1);
    }
    *(uint2*)(yh + row * DIM + 4 * tid) = make_uint2(h0, h1);
    *(uint2*)(yl + row * DIM + 4 * tid) = make_uint2(l0, l1);
}

// ---------------- launch ----------------------------------------------------
template<typename T>
static T* symaddr(const void* s) {
    void* p = nullptr;
    cudaGetSymbolAddress(&p, s);
    return (T*)p;
}

#define SMEM_G  (2 * (2 * 128 * 80 + 2 * 128 * 80))   // 81920
#define SMEM_H2 (2 * (2 * 128 * 80 + 128 * 80))       // 61440

extern "C" void kernel_launch(void* const* d_in, const int* in_sizes, int n_in,
                              void* d_out, int out_size) {
    (void)in_sizes; (void)n_in; (void)out_size;
    const float* x     = (const float*)d_in[0];
    const float* wq    = (const float*)d_in[2];
    const float* bq    = (const float*)d_in[3];
    const float* wk    = (const float*)d_in[4];
    const float* bk    = (const float*)d_in[5];
    const float* wv    = (const float*)d_in[6];
    const float* bv    = (const float*)d_in[7];
    const float* wo    = (const float*)d_in[8];
    const float* bo    = (const float*)d_in[9];
    const float* w1    = (const float*)d_in[10];
    const float* b1    = (const float*)d_in[11];
    const float* w2    = (const float*)d_in[12];
    const float* b2    = (const float*)d_in[13];
    const float* alpha = (const float*)d_in[14];
    const float* beta  = (const float*)d_in[15];
    float* out = (float*)d_out;

    cudaFuncSetAttribute(gemm4<true>,
                         cudaFuncAttributeMaxDynamicSharedMemorySize, SMEM_G);
    cudaFuncSetAttribute(gemm4<false>,
                         cudaFuncAttributeMaxDynamicSharedMemorySize, SMEM_G);
    cudaFuncSetAttribute(gemm_h2<true>,
                         cudaFuncAttributeMaxDynamicSharedMemorySize, SMEM_H2);
    cudaFuncSetAttribute(gemm_h2<false>,
                         cudaFuncAttributeMaxDynamicSharedMemorySize, SMEM_H2);
    cudaFuncSetAttribute(flash_attn,
                         cudaFuncAttributeMaxDynamicSharedMemorySize, FSMEM);

    bf16* lnh = symaddr<bf16>(g_lnh);  bf16* lnl = symaddr<bf16>(g_lnl);
    bf16* qkvh = symaddr<bf16>(g_qkvh);
    bf16* qkvl = symaddr<bf16>(g_qkvl);
    float* x1 = symaddr<float>(g_x1);
    bf16* wh  = symaddr<bf16>(g_wh);   bf16* wl  = symaddr<bf16>(g_wl);
    __half* w1h = (__half*)(wh + WOFF_1);
    __half* w2h = (__half*)(wh + WOFF_2);
    __half* hidh = symaddr<__half>(g_hid);
    __half* hidl = hidh + (size_t)MROWS * HFF;
    float* b3 = symaddr<float>(g_b3);

    // launches 1-5 (QKV GEMM is #6 -> ncu -s 5 -c 1 profiles it)
    wconv_all<<<4 * (DIM * DIM / 4) / 256, 256>>>(wq, wk, wv, wo, wh, wl);
    wconvh<<<(HFF * DIM / 2 + 255) / 256, 256>>>(w1, w1h, HFF * DIM / 2);
    wconvh<<<(HFF * DIM / 2 + 255) / 256, 256>>>(w2, w2h, HFF * DIM / 2);
    bcat<<<(QKVN + 255) / 256, 256>>>(bq, bk, bv, b3);
    ln_kernel<false><<<MROWS, 256>>>(x, (uint16_t*)lnh, (uint16_t*)lnl,
                                     alpha, beta);

    // 6) fused QKV projection: [8192, 3072] (bf16 3-MMA)
    dim3 gqkv(QKVN / 128, MROWS / 128, 1);
    gemm4<true><<<gqkv, 128, SMEM_G>>>(
        lnh, lnl, DIM, wh + WOFF_Q, wl + WOFF_Q, DIM,
        nullptr, qkvh, qkvl, QKVN, DIM, b3, nullptr, 0, 1.f, 0);

    // 7) fused attention -> split bf16 planes (into lnh/lnl, reused)
    dim3 gfa(SEQ / 64, BATCH * HEADS, 1);
    flash_attn<<<gfa, 128, FSMEM>>>(qkvh, qkvl, lnh, lnl);

    // 8) O projection + residual x -> x1 (fp32, bf16 3-MMA)
    dim3 gw(DIM / 128, MROWS / 128, 1);
    gemm4<false><<<gw, 128, SMEM_G>>>(
        lnh, lnl, DIM, wh + WOFF_O, wl + WOFF_O, DIM,
        x1, nullptr, nullptr, DIM, DIM, bo, x, DIM, 1.f, 0);

    // 9) LN2 -> fp16 split planes (same buffers, punned)
    ln_kernel<true><<<MROWS, 256>>>(x1, (uint16_t*)lnh, (uint16_t*)lnl,
                                    alpha, beta);

    // 10) FFN1 (+ReLU) -> fp16 split hidden (fp16 2-MMA)
    dim3 gf1(HFF / 128, MROWS / 128, 1);
    gemm_h2<true><<<gf1, 128, SMEM_H2>>>(
        (const __half*)lnh, (const __half*)lnl, DIM, w1h, DIM,
        nullptr, hidh, hidl, HFF, DIM, b1, nullptr, 0, 1);

    // 11) FFN2 + residual x1 -> out (fp32, fp16 2-MMA)
    dim3 gf2(DIM / 128, MROWS / 128, 1);
    gemm_h2<false><<<gf2, 128, SMEM_H2>>>(
        hidh, hidl, HFF, w2h, HFF,
        out, nullptr, nullptr, DIM, HFF, b2, x1, DIM, 0);
}

// round 12
// speedup vs baseline: 4.2658x; 1.1081x over previous
#include <cuda_runtime.h>
#include <cuda_bf16.h>
#include <cuda_fp16.h>
#include <math.h>
#include <stdint.h>

#define BATCH 8
#define SEQ   1024
#define DIM   1024
#define HEADS 16
#define DH    64
#define HFF   4096
#define MROWS (BATCH*SEQ)   // 8192
#define QKVN  (3*DIM)       // 3072

typedef __nv_bfloat16 bf16;

// ---------------- scratch (static device arrays: allocation-free) ----------
// all activation planes are fp16 hi/lo splits now
__device__ __half g_lnh[(size_t)MROWS*DIM], g_lnl[(size_t)MROWS*DIM];
__device__ __half g_qkvh[(size_t)MROWS*QKVN], g_qkvl[(size_t)MROWS*QKVN];
__device__ float  g_x1[(size_t)MROWS*DIM];
__device__ __half g_hid[(size_t)2*MROWS*HFF];
__device__ float  g_b3[QKVN];
// single fp16 weight planes: wqkv (3M) | wo (1M) | w1 (4M) | w2 (4M)
#define HOFF_QKV 0
#define HOFF_O   ((size_t)3*DIM*DIM)
#define HOFF_1   ((size_t)4*DIM*DIM)
#define HOFF_2   ((size_t)4*DIM*DIM + (size_t)HFF*DIM)
__device__ __half g_w16[(size_t)4*DIM*DIM + (size_t)2*HFF*DIM];

// ==================== helpers ====================
__device__ __forceinline__ uint32_t smem_u32(const void* p) {
    uint32_t a;
    asm("{ .reg .u64 t; cvta.to.shared.u64 t, %1; cvt.u32.u64 %0, t; }"
        : "=r"(a) : "l"(p));
    return a;
}
__device__ __forceinline__ void cp_async16(uint32_t dst, const void* src) {
    uint64_t g;
    asm("cvta.to.global.u64 %0, %1;" : "=l"(g) : "l"(src));
    asm volatile("cp.async.cg.shared.global [%0], [%1], 16;"
                 :: "r"(dst), "l"(g) : "memory");
}
#define CP_COMMIT() asm volatile("cp.async.commit_group;" ::: "memory")
#define CP_WAIT0()  asm volatile("cp.async.wait_group 0;"  ::: "memory")

// fp32 -> (hi, lo) fp16 split, packed pairs (22-bit effective)
__device__ __forceinline__ void cvt2h(float a, float b, uint32_t& h, uint32_t& l) {
    __half2 hh = __floats2half2_rn(a, b);
    float ra = a - __half2float(__low2half(hh));
    float rb = b - __half2float(__high2half(hh));
    __half2 ll = __floats2half2_rn(ra, rb);
    h = *(uint32_t*)&hh;
    l = *(uint32_t*)&ll;
}

#define LDM4(r0, r1, r2, r3, addr) \
    asm volatile("ldmatrix.sync.aligned.m8n8.x4.shared.b16 {%0,%1,%2,%3}, [%4];" \
                 : "=r"(r0), "=r"(r1), "=r"(r2), "=r"(r3) : "r"(addr))
#define LDM2T(r0, r1, addr) \
    asm volatile("ldmatrix.sync.aligned.m8n8.x2.trans.shared.b16 {%0,%1}, [%2];" \
                 : "=r"(r0), "=r"(r1) : "r"(addr))
#define MMAH16816(c, a, b) \
    asm volatile("mma.sync.aligned.m16n8k16.row.col.f32.f16.f16.f32 " \
                 "{%0,%1,%2,%3}, {%4,%5,%6,%7}, {%8,%9}, {%0,%1,%2,%3};" \
                 : "+f"((c)[0]), "+f"((c)[1]), "+f"((c)[2]), "+f"((c)[3]) \
                 : "r"((a)[0]), "r"((a)[1]), "r"((a)[2]), "r"((a)[3]), \
                   "r"((b)[0]), "r"((b)[1]))

// ------------- weight conversions: fp32 -> single fp16 plane ---------------
__global__ __launch_bounds__(256) void wconvh_all(
    const float* __restrict__ w0, const float* __restrict__ w1p,
    const float* __restrict__ w2p, const float* __restrict__ w3,
    __half* __restrict__ o) {
    const int n2p = DIM * DIM / 2;
    const int i = blockIdx.x * 256 + threadIdx.x;    // [0, 4*n2p)
    const float* src = (i < n2p) ? w0 : (i < 2 * n2p) ? w1p
                     : (i < 3 * n2p) ? w2p : w3;
    const int j = i & (n2p - 1);
    const float2 v = ((const float2*)src)[j];
    ((__half2*)o)[i] = __floats2half2_rn(v.x, v.y);
}
__global__ __launch_bounds__(256) void wconvh(const float* __restrict__ w,
                                              __half* __restrict__ o, int n2) {
    const int i = blockIdx.x * 256 + threadIdx.x;
    if (i >= n2) return;
    const float2 v = ((const float2*)w)[i];
    ((__half2*)o)[i] = __floats2half2_rn(v.x, v.y);
}
__global__ __launch_bounds__(256) void bcat(const float* __restrict__ a,
                                            const float* __restrict__ b,
                                            const float* __restrict__ c,
                                            float* __restrict__ o) {
    const int i = blockIdx.x * 256 + threadIdx.x;
    if (i < DIM)            o[i] = a[i];
    else if (i < 2 * DIM)   o[i] = b[i - DIM];
    else if (i < 3 * DIM)   o[i] = c[i - 2 * DIM];
}

// ==================== fp16 2-MMA GEMM (all weight GEMMs) ====================
// A: exact fp16 hi/lo split planes; B: single fp16 plane (weight-rounded).
// C = (Ah+Al)B + bias (+relu, +resid). 128 thr, 2x2 warps, 64x64 warp tiles.
template<bool OSPLIT>
__global__ __launch_bounds__(128, 2) void gemm_h2(
    const __half* __restrict__ Ah, const __half* __restrict__ Al, int lda,
    const __half* __restrict__ B, int ldb,
    float* __restrict__ Cf,
    __half* __restrict__ Ch, __half* __restrict__ Cl, int ldc,
    int K,
    const float* __restrict__ bias,
    const float* __restrict__ resid, int ldr,
    int relu)
{
    constexpr int BK = 32;
    constexpr int ABYTES = 128 * 80;
    constexpr int BBYTES = 128 * 80;
    constexpr int SS = 2 * ABYTES + BBYTES;

    extern __shared__ char sm[];
    const uint32_t smBase = smem_u32(sm);

    const int tid = threadIdx.x, wid = tid >> 5, lane = tid & 31;
    const int wm = wid >> 1, wn = wid & 1;
    const int m0 = blockIdx.y * 128, n0 = blockIdx.x * 128;

    float acc[4][8][4];
#pragma unroll
    for (int i = 0; i < 4; i++)
#pragma unroll
        for (int j = 0; j < 8; j++)
#pragma unroll
            for (int r = 0; r < 4; r++) acc[i][j][r] = 0.f;

    auto issueA = [&](int s, int t) {
        const uint32_t sA = smBase + s * SS;
#pragma unroll
        for (int i = 0; i < 8; i++) {
            const int idx = i * 128 + tid;
            const int c = idx & 3, row = (idx >> 2) & 127, pl = idx >> 9;
            const __half* g = (pl ? Al : Ah) + (size_t)(m0 + row) * lda + t * BK + c * 8;
            cp_async16(sA + pl * ABYTES + row * 80 + c * 16, g);
        }
    };
    auto issueB = [&](int s, int t) {
        const uint32_t sB = smBase + s * SS + 2 * ABYTES;
#pragma unroll
        for (int i = 0; i < 4; i++) {
            const int idx = i * 128 + tid;
            const int c = idx & 3, row = idx >> 2;
            const __half* g = B + (size_t)(n0 + row) * ldb + t * BK + c * 8;
            cp_async16(sB + row * 80 + c * 16, g);
        }
    };

    auto compute = [&](int s) {
        const uint32_t aHiB = smBase + s * SS;
        const uint32_t aLoB = aHiB + ABYTES;
        const uint32_t bB   = aHiB + 2 * ABYTES;
#pragma unroll
        for (int ks = 0; ks < 2; ks++) {
            uint32_t bf[8][2];
#pragma unroll
            for (int p = 0; p < 4; p++) {
                const uint32_t rb =
                    (uint32_t)((wn * 64 + p * 16 + ((lane >> 4) & 1) * 8 + (lane & 7)) * 80
                               + ks * 32 + ((lane >> 3) & 1) * 16);
                LDM4(bf[2*p][0], bf[2*p][1], bf[2*p+1][0], bf[2*p+1][1], bB + rb);
            }
            const uint32_t kbA = (uint32_t)((ks * 16 + (lane >> 4) * 8) * 2);
#pragma unroll
            for (int mt = 0; mt < 4; mt++) {
                uint32_t ah[4], al[4];
                const uint32_t ra = (uint32_t)((wm * 64 + mt * 16 + (lane & 15)) * 80) + kbA;
                LDM4(ah[0], ah[1], ah[2], ah[3], aHiB + ra);
                LDM4(al[0], al[1], al[2], al[3], aLoB + ra);
#pragma unroll
                for (int nt = 0; nt < 8; nt++) MMAH16816(acc[mt][nt], ah, bf[nt]);
#pragma unroll
                for (int nt = 0; nt < 8; nt++) MMAH16816(acc[mt][nt], al, bf[nt]);
            }
        }
    };

    const int T = K / BK;
    issueA(0, 0);
    issueB(0, 0);
    CP_COMMIT();
    CP_WAIT0();
    __syncthreads();

    for (int t = 0; t < T; t++) {
        const int s = t & 1;
        if (t + 1 < T) {
            issueA(s ^ 1, t + 1);
            issueB(s ^ 1, t + 1);
            CP_COMMIT();
        }
        compute(s);
        CP_WAIT0();
        __syncthreads();
    }

#pragma unroll
    for (int mt = 0; mt < 4; mt++) {
#pragma unroll
        for (int nt = 0; nt < 8; nt++) {
            const int r0 = m0 + wm * 64 + mt * 16 + (lane >> 2);
            const int cc = n0 + wn * 64 + nt * 8 + (lane & 3) * 2;
#pragma unroll
            for (int h = 0; h < 2; h++) {
                const int m = r0 + h * 8;
                float vx = acc[mt][nt][2 * h];
                float vy = acc[mt][nt][2 * h + 1];
                if (bias)  { vx += bias[cc]; vy += bias[cc + 1]; }
                if (relu)  { vx = fmaxf(vx, 0.f); vy = fmaxf(vy, 0.f); }
                if (resid) {
                    const float2 rr = *(const float2*)(resid + (size_t)m * ldr + cc);
                    vx += rr.x; vy += rr.y;
                }
                if constexpr (OSPLIT) {
                    uint32_t hh, ll;
                    cvt2h(vx, vy, hh, ll);
                    *(uint32_t*)(Ch + (size_t)m * ldc + cc) = hh;
                    *(uint32_t*)(Cl + (size_t)m * ldc + cc) = ll;
                } else {
                    *(float2*)(Cf + (size_t)m * ldc + cc) = make_float2(vx, vy);
                }
            }
        }
    }
}

// ==================== fused flash attention (fp16 splits) ====================
#define FQ_PL 9216
#define FK_PL 18432
#define FSMEM (2*FQ_PL + 4*FK_PL)   // 92160

__global__ __launch_bounds__(128, 2) void flash_attn(
    const __half* __restrict__ qkvh, const __half* __restrict__ qkvl,
    __half* __restrict__ oh, __half* __restrict__ ol)
{
    extern __shared__ char sm[];
    const uint32_t smBase = smem_u32(sm);
    const int tid = threadIdx.x, lane = tid & 31, w = tid >> 5;
    const int b = blockIdx.y >> 4, h = blockIdx.y & 15;
    const size_t rowQ  = (size_t)b * SEQ + blockIdx.x * 64;
    const size_t rowKV = (size_t)b * SEQ;
    const int colh = h * DH;

    const uint32_t sQ = smBase;
    const uint32_t sK = smBase + 2 * FQ_PL;
    const uint32_t sV = sK + 2 * FK_PL;

#pragma unroll
    for (int i = 0; i < 8; i++) {
        const int idx = i * 128 + tid;
        const int pl = idx >> 9, row = (idx >> 3) & 63, c = idx & 7;
        const __half* g = (pl ? qkvl : qkvh) + (rowQ + row) * QKVN + colh + c * 8;
        cp_async16(sQ + pl * FQ_PL + row * 144 + c * 16, g);
    }
    auto loadKV = [&](int kt) {
        const size_t base = (rowKV + kt * 128) * QKVN + colh;
#pragma unroll
        for (int i = 0; i < 16; i++) {
            const int idx = i * 128 + tid;
            const int pl = idx >> 10, row = (idx >> 3) & 127, c = idx & 7;
            const size_t off = base + (size_t)row * QKVN + c * 8;
            const uint32_t d = pl * FK_PL + row * 144 + c * 16;
            cp_async16(sK + d, (pl ? qkvl : qkvh) + off + DIM);
            cp_async16(sV + d, (pl ? qkvl : qkvh) + off + 2 * DIM);
        }
    };
    loadKV(0);
    CP_COMMIT(); CP_WAIT0();
    __syncthreads();

    float oacc[8][4];
#pragma unroll
    for (int i = 0; i < 8; i++)
#pragma unroll
        for (int j = 0; j < 4; j++) oacc[i][j] = 0.f;
    float m0 = -INFINITY, m1 = -INFINITY, l0 = 0.f, l1 = 0.f;

    for (int kt = 0; kt < 8; kt++) {
        float sfr[16][4];
#pragma unroll
        for (int i = 0; i < 16; i++)
#pragma unroll
            for (int j = 0; j < 4; j++) sfr[i][j] = 0.f;
#pragma unroll
        for (int ks = 0; ks < 4; ks++) {
            uint32_t qa[4], qb[4];
            const uint32_t ra = sQ + (w * 16 + (lane & 15)) * 144
                              + ks * 32 + (lane >> 4) * 16;
            LDM4(qa[0], qa[1], qa[2], qa[3], ra);
            LDM4(qb[0], qb[1], qb[2], qb[3], ra + FQ_PL);
#pragma unroll
            for (int p = 0; p < 8; p++) {
                uint32_t kbh[4], kbl[4];
                const uint32_t rb = sK + (p * 16 + ((lane >> 4) & 1) * 8 + (lane & 7)) * 144
                                  + ks * 32 + ((lane >> 3) & 1) * 16;
                LDM4(kbh[0], kbh[1], kbh[2], kbh[3], rb);
                LDM4(kbl[0], kbl[1], kbl[2], kbl[3], rb + FK_PL);
                MMAH16816(sfr[2*p],   qa, (&kbh[0]));
                MMAH16816(sfr[2*p],   qa, (&kbl[0]));
                MMAH16816(sfr[2*p],   qb, (&kbh[0]));
                MMAH16816(sfr[2*p+1], qa, (&kbh[2]));
                MMAH16816(sfr[2*p+1], qa, (&kbl[2]));
                MMAH16816(sfr[2*p+1], qb, (&kbh[2]));
            }
        }
        float mx0 = -INFINITY, mx1 = -INFINITY;
#pragma unroll
        for (int nt = 0; nt < 16; nt++) {
            mx0 = fmaxf(mx0, fmaxf(sfr[nt][0], sfr[nt][1]));
            mx1 = fmaxf(mx1, fmaxf(sfr[nt][2], sfr[nt][3]));
        }
        mx0 = fmaxf(mx0, __shfl_xor_sync(0xffffffffu, mx0, 1));
        mx0 = fmaxf(mx0, __shfl_xor_sync(0xffffffffu, mx0, 2));
        mx1 = fmaxf(mx1, __shfl_xor_sync(0xffffffffu, mx1, 1));
        mx1 = fmaxf(mx1, __shfl_xor_sync(0xffffffffu, mx1, 2));
        const float mn0 = fmaxf(m0, 0.125f * mx0);
        const float mn1 = fmaxf(m1, 0.125f * mx1);
        const float f0 = __expf(m0 - mn0);
        const float f1 = __expf(m1 - mn1);
        float rs0 = 0.f, rs1 = 0.f;
#pragma unroll
        for (int nt = 0; nt < 16; nt++) {
            const float p0 = __expf(fmaf(sfr[nt][0], 0.125f, -mn0));
            const float p1 = __expf(fmaf(sfr[nt][1], 0.125f, -mn0));
            const float p2 = __expf(fmaf(sfr[nt][2], 0.125f, -mn1));
            const float p3 = __expf(fmaf(sfr[nt][3], 0.125f, -mn1));
            rs0 += p0 + p1; rs1 += p2 + p3;
            sfr[nt][0] = p0; sfr[nt][1] = p1; sfr[nt][2] = p2; sfr[nt][3] = p3;
        }
        rs0 += __shfl_xor_sync(0xffffffffu, rs0, 1);
        rs0 += __shfl_xor_sync(0xffffffffu, rs0, 2);
        rs1 += __shfl_xor_sync(0xffffffffu, rs1, 1);
        rs1 += __shfl_xor_sync(0xffffffffu, rs1, 2);
        l0 = l0 * f0 + rs0; l1 = l1 * f1 + rs1;
        m0 = mn0; m1 = mn1;
#pragma unroll
        for (int dt = 0; dt < 8; dt++) {
            oacc[dt][0] *= f0; oacc[dt][1] *= f0;
            oacc[dt][2] *= f1; oacc[dt][3] *= f1;
        }
#pragma unroll
        for (int ks = 0; ks < 8; ks++) {
            uint32_t ah[4], al[4];
            cvt2h(sfr[2 * ks][0],     sfr[2 * ks][1],     ah[0], al[0]);
            cvt2h(sfr[2 * ks][2],     sfr[2 * ks][3],     ah[1], al[1]);
            cvt2h(sfr[2 * ks + 1][0], sfr[2 * ks + 1][1], ah[2], al[2]);
            cvt2h(sfr[2 * ks + 1][2], sfr[2 * ks + 1][3], ah[3], al[3]);
#pragma unroll
            for (int dt = 0; dt < 8; dt++) {
                uint32_t vbh[2], vbl[2];
                const uint32_t rv = sV + (ks * 16 + (lane & 15)) * 144 + dt * 16;
                LDM2T(vbh[0], vbh[1], rv);
                LDM2T(vbl[0], vbl[1], rv + FK_PL);
                MMAH16816(oacc[dt], ah, vbh);
                MMAH16816(oacc[dt], ah, vbl);
                MMAH16816(oacc[dt], al, vbh);
            }
        }
        if (kt < 7) {
            __syncthreads();
            loadKV(kt + 1);
            CP_COMMIT(); CP_WAIT0();
            __syncthreads();
        }
    }

    const float i0 = 1.f / l0, i1 = 1.f / l1;
    const int r = w * 16 + (lane >> 2);
    const int cc = (lane & 3) * 2;
#pragma unroll
    for (int dt = 0; dt < 8; dt++) {
        uint32_t hh, ll;
        const size_t o0 = (rowQ + r) * DIM + colh + dt * 8 + cc;
        cvt2h(oacc[dt][0] * i0, oacc[dt][1] * i0, hh, ll);
        *(uint32_t*)(oh + o0) = hh;
        *(uint32_t*)(ol + o0) = ll;
        const size_t o1 = o0 + 8 * DIM;
        cvt2h(oacc[dt][2] * i1, oacc[dt][3] * i1, hh, ll);
        *(uint32_t*)(oh + o1) = hh;
        *(uint32_t*)(ol + o1) = ll;
    }
}

// ---------------- LayerNorm -> fp16 split planes ---------------------------
__global__ __launch_bounds__(256) void ln_kernel(const float* __restrict__ x,
                                                 __half* __restrict__ yh,
                                                 __half* __restrict__ yl,
                                                 const float* __restrict__ alpha,
                                                 const float* __restrict__ beta) {
    __shared__ float sh_s[8], sh_q[8];
    const size_t row = blockIdx.x;
    const float4* xr = (const float4*)(x + row * DIM);
    const int tid = threadIdx.x;
    float4 v = xr[tid];
    float s = v.x + v.y + v.z + v.w;
    float q = v.x*v.x + v.y*v.y + v.z*v.z + v.w*v.w;
#pragma unroll
    for (int o = 16; o; o >>= 1) {
        s += __shfl_xor_sync(0xffffffffu, s, o);
        q += __shfl_xor_sync(0xffffffffu, q, o);
    }
    if ((tid & 31) == 0) { sh_s[tid >> 5] = s; sh_q[tid >> 5] = q; }
    __syncthreads();
    if (tid < 32) {
        s = (tid < 8) ? sh_s[tid] : 0.f;
        q = (tid < 8) ? sh_q[tid] : 0.f;
#pragma unroll
        for (int o = 4; o; o >>= 1) {
            s += __shfl_xor_sync(0xffffffffu, s, o);
            q += __shfl_xor_sync(0xffffffffu, q, o);
        }
        if (tid == 0) { sh_s[0] = s; sh_q[0] = q; }
    }
    __syncthreads();
    s = sh_s[0]; q = sh_q[0];
    const float mean = s * (1.0f / DIM);
    const float var  = (q - (float)DIM * mean * mean) * (1.0f / (DIM - 1));
    const float inv  = 1.0f / (sqrtf(fmaxf(var, 0.f)) + 1e-6f);
    const float4 a = ((const float4*)alpha)[tid];
    const float4 b = ((const float4*)beta)[tid];
    float ox = a.x * (v.x - mean) * inv + b.x;
    float oy = a.y * (v.y - mean) * inv + b.y;
    float oz = a.z * (v.z - mean) * inv + b.z;
    float ow = a.w * (v.w - mean) * inv + b.w;
    uint32_t h0, l0, h1, l1;
    cvt2h(ox, oy, h0, l0);
    cvt2h(oz, ow, h1, l1);
    *(uint2*)((uint16_t*)yh + row * DIM + 4 * tid) = make_uint2(h0, h1);
    *(uint2*)((uint16_t*)yl + row * DIM + 4 * tid) = make_uint2(l0, l1);
}

// ---------------- launch ----------------------------------------------------
template<typename T>
static T* symaddr(const void* s) {
    void* p = nullptr;
    cudaGetSymbolAddress(&p, s);
    return (T*)p;
}

#define SMEM_H2 (2 * (2 * 128 * 80 + 128 * 80))       // 61440

extern "C" void kernel_launch(void* const* d_in, const int* in_sizes, int n_in,
                              void* d_out, int out_size) {
    (void)in_sizes; (void)n_in; (void)out_size;
    const float* x     = (const float*)d_in[0];
    const float* wq    = (const float*)d_in[2];
    const float* bq    = (const float*)d_in[3];
    const float* wk    = (const float*)d_in[4];
    const float* bk    = (const float*)d_in[5];
    const float* wv    = (const float*)d_in[6];
    const float* bv    = (const float*)d_in[7];
    const float* wo    = (const float*)d_in[8];
    const float* bo    = (const float*)d_in[9];
    const float* w1    = (const float*)d_in[10];
    const float* b1    = (const float*)d_in[11];
    const float* w2    = (const float*)d_in[12];
    const float* b2    = (const float*)d_in[13];
    const float* alpha = (const float*)d_in[14];
    const float* beta  = (const float*)d_in[15];
    float* out = (float*)d_out;

    cudaFuncSetAttribute(gemm_h2<true>,
                         cudaFuncAttributeMaxDynamicSharedMemorySize, SMEM_H2);
    cudaFuncSetAttribute(gemm_h2<false>,
                         cudaFuncAttributeMaxDynamicSharedMemorySize, SMEM_H2);
    cudaFuncSetAttribute(flash_attn,
                         cudaFuncAttributeMaxDynamicSharedMemorySize, FSMEM);

    __half* lnh  = symaddr<__half>(g_lnh);
    __half* lnl  = symaddr<__half>(g_lnl);
    __half* qkvh = symaddr<__half>(g_qkvh);
    __half* qkvl = symaddr<__half>(g_qkvl);
    float*  x1   = symaddr<float>(g_x1);
    __half* w16  = symaddr<__half>(g_w16);
    __half* hidh = symaddr<__half>(g_hid);
    __half* hidl = hidh + (size_t)MROWS * HFF;
    float*  b3   = symaddr<float>(g_b3);

    // 0) weight conversion (single fp16 planes) + bias concat
    wconvh_all<<<4 * (DIM * DIM / 2) / 256, 256>>>(wq, wk, wv, wo,
                                                   w16 + HOFF_QKV);
    wconvh<<<(HFF * DIM / 2 + 255) / 256, 256>>>(w1, w16 + HOFF_1, HFF * DIM / 2);
    wconvh<<<(HFF * DIM / 2 + 255) / 256, 256>>>(w2, w16 + HOFF_2, HFF * DIM / 2);
    bcat<<<(QKVN + 255) / 256, 256>>>(bq, bk, bv, b3);

    // 1) LN1 -> fp16 split
    ln_kernel<<<MROWS, 256>>>(x, lnh, lnl, alpha, beta);

    // 2) fused QKV projection: [8192, 3072] (fp16 2-MMA)
    dim3 gqkv(QKVN / 128, MROWS / 128, 1);
    gemm_h2<true><<<gqkv, 128, SMEM_H2>>>(
        lnh, lnl, DIM, w16 + HOFF_QKV, DIM,
        nullptr, qkvh, qkvl, QKVN, DIM, b3, nullptr, 0, 0);

    // 3) fused attention -> fp16 split planes (into lnh/lnl, reused)
    dim3 gfa(SEQ / 64, BATCH * HEADS, 1);
    flash_attn<<<gfa, 128, FSMEM>>>(qkvh, qkvl, lnh, lnl);

    // 4) O projection + residual x -> x1 (fp32 out, fp16 2-MMA)
    dim3 gw(DIM / 128, MROWS / 128, 1);
    gemm_h2<false><<<gw, 128, SMEM_H2>>>(
        lnh, lnl, DIM, w16 + HOFF_O, DIM,
        x1, nullptr, nullptr, DIM, DIM, bo, x, DIM, 0);

    // 5) LN2 -> fp16 split
    ln_kernel<<<MROWS, 256>>>(x1, lnh, lnl, alpha, beta);

    // 6) FFN1 (+ReLU) -> fp16 split hidden
    dim3 gf1(HFF / 128, MROWS / 128, 1);
    gemm_h2<true><<<gf1, 128, SMEM_H2>>>(
        lnh, lnl, DIM, w16 + HOFF_1, DIM,
        nullptr, hidh, hidl, HFF, DIM, b1, nullptr, 0, 1);

    // 7) FFN2 + residual x1 -> out (fp32)
    dim3 gf2(DIM / 128, MROWS / 128, 1);
    gemm_h2<false><<<gf2, 128, SMEM_H2>>>(
        hidh, hidl, HFF, w16 + HOFF_2, HFF,
        out, nullptr, nullptr, DIM, HFF, b2, x1, DIM, 0);
}

// round 13
// speedup vs baseline: 8.0979x; 1.8983x over previous
#include <cuda_runtime.h>
#include <cuda_fp16.h>
#include <math.h>
#include <stdint.h>

#define BATCH 8
#define SEQ   1024
#define DIM   1024
#define HEADS 16
#define DH    64
#define HFF   4096
#define MROWS (BATCH*SEQ)   // 8192
#define QKVN  (3*DIM)       // 3072

// ---------------- scratch (static device arrays: allocation-free) ----------
__device__ __half g_ln [(size_t)MROWS*DIM];
__device__ __half g_qkv[(size_t)MROWS*QKVN];
__device__ float  g_x1 [(size_t)MROWS*DIM];
__device__ __half g_hid[(size_t)MROWS*HFF];
__device__ float  g_b3 [QKVN];
// single fp16 weight planes: wqkv (3M) | wo (1M) | w1 (4M) | w2 (4M)
#define HOFF_QKV 0
#define HOFF_O   ((size_t)3*DIM*DIM)
#define HOFF_1   ((size_t)4*DIM*DIM)
#define HOFF_2   ((size_t)4*DIM*DIM + (size_t)HFF*DIM)
__device__ __half g_w16[(size_t)4*DIM*DIM + (size_t)2*HFF*DIM];

// ==================== helpers ====================
__device__ __forceinline__ uint32_t smem_u32(const void* p) {
    uint32_t a;
    asm("{ .reg .u64 t; cvta.to.shared.u64 t, %1; cvt.u32.u64 %0, t; }"
        : "=r"(a) : "l"(p));
    return a;
}
__device__ __forceinline__ void cp_async16(uint32_t dst, const void* src) {
    uint64_t g;
    asm("cvta.to.global.u64 %0, %1;" : "=l"(g) : "l"(src));
    asm volatile("cp.async.cg.shared.global [%0], [%1], 16;"
                 :: "r"(dst), "l"(g) : "memory");
}
#define CP_COMMIT() asm volatile("cp.async.commit_group;" ::: "memory")
#define CP_WAIT0()  asm volatile("cp.async.wait_group 0;"  ::: "memory")

__device__ __forceinline__ uint32_t pack_h2(float a, float b) {
    __half2 h = __floats2half2_rn(a, b);
    return *(uint32_t*)&h;
}

#define LDM4(r0, r1, r2, r3, addr) \
    asm volatile("ldmatrix.sync.aligned.m8n8.x4.shared.b16 {%0,%1,%2,%3}, [%4];" \
                 : "=r"(r0), "=r"(r1), "=r"(r2), "=r"(r3) : "r"(addr))
#define LDM2T(r0, r1, addr) \
    asm volatile("ldmatrix.sync.aligned.m8n8.x2.trans.shared.b16 {%0,%1}, [%2];" \
                 : "=r"(r0), "=r"(r1) : "r"(addr))
#define MMAH16816(c, a, b) \
    asm volatile("mma.sync.aligned.m16n8k16.row.col.f32.f16.f16.f32 " \
                 "{%0,%1,%2,%3}, {%4,%5,%6,%7}, {%8,%9}, {%0,%1,%2,%3};" \
                 : "+f"((c)[0]), "+f"((c)[1]), "+f"((c)[2]), "+f"((c)[3]) \
                 : "r"((a)[0]), "r"((a)[1]), "r"((a)[2]), "r"((a)[3]), \
                   "r"((b)[0]), "r"((b)[1]))

// ------------- weight conversions: fp32 -> single fp16 plane ---------------
__global__ __launch_bounds__(256) void wconvh_all(
    const float* __restrict__ w0, const float* __restrict__ w1p,
    const float* __restrict__ w2p, const float* __restrict__ w3,
    __half* __restrict__ o) {
    const int n2p = DIM * DIM / 2;
    const int i = blockIdx.x * 256 + threadIdx.x;    // [0, 4*n2p)
    const float* src = (i < n2p) ? w0 : (i < 2 * n2p) ? w1p
                     : (i < 3 * n2p) ? w2p : w3;
    const int j = i & (n2p - 1);
    const float2 v = ((const float2*)src)[j];
    ((__half2*)o)[i] = __floats2half2_rn(v.x, v.y);
}
__global__ __launch_bounds__(256) void wconvh(const float* __restrict__ w,
                                              __half* __restrict__ o, int n2) {
    const int i = blockIdx.x * 256 + threadIdx.x;
    if (i >= n2) return;
    const float2 v = ((const float2*)w)[i];
    ((__half2*)o)[i] = __floats2half2_rn(v.x, v.y);
}
__global__ __launch_bounds__(256) void bcat(const float* __restrict__ a,
                                            const float* __restrict__ b,
                                            const float* __restrict__ c,
                                            float* __restrict__ o) {
    const int i = blockIdx.x * 256 + threadIdx.x;
    if (i < DIM)            o[i] = a[i];
    else if (i < 2 * DIM)   o[i] = b[i - DIM];
    else if (i < 3 * DIM)   o[i] = c[i - 2 * DIM];
}

// ==================== single-fp16 1-MMA GEMM ====================
// C[m,n] = sum_k A[m,k]*B[n,k] + bias (+relu, +resid), fp32 accumulate.
// 128 threads, 2x2 warps, 64x64 warp tiles, BM=BN=128, BK=64.
// smem rows 144B-padded (9x16B, odd) -> conflict-free ldmatrix.
template<bool OHALF>
__global__ __launch_bounds__(128, 2) void gemm_h1(
    const __half* __restrict__ A, int lda,
    const __half* __restrict__ B, int ldb,
    float* __restrict__ Cf, __half* __restrict__ Ch, int ldc,
    int K,
    const float* __restrict__ bias,
    const float* __restrict__ resid, int ldr,
    int relu)
{
    constexpr int BK = 64;
    constexpr int TBYTES = 128 * 144;     // one operand tile
    constexpr int SS = 2 * TBYTES;        // stage = A + B

    extern __shared__ char sm[];
    const uint32_t smBase = smem_u32(sm);

    const int tid = threadIdx.x, wid = tid >> 5, lane = tid & 31;
    const int wm = wid >> 1, wn = wid & 1;
    const int m0 = blockIdx.y * 128, n0 = blockIdx.x * 128;

    float acc[4][8][4];
#pragma unroll
    for (int i = 0; i < 4; i++)
#pragma unroll
        for (int j = 0; j < 8; j++)
#pragma unroll
            for (int r = 0; r < 4; r++) acc[i][j][r] = 0.f;

    auto issueA = [&](int s, int t) {
        const uint32_t sA = smBase + s * SS;
#pragma unroll
        for (int i = 0; i < 8; i++) {
            const int idx = i * 128 + tid;
            const int c = idx & 7, row = idx >> 3;
            cp_async16(sA + row * 144 + c * 16,
                       A + (size_t)(m0 + row) * lda + t * BK + c * 8);
        }
    };
    auto issueB = [&](int s, int t) {
        const uint32_t sB = smBase + s * SS + TBYTES;
#pragma unroll
        for (int i = 0; i < 8; i++) {
            const int idx = i * 128 + tid;
            const int c = idx & 7, row = idx >> 3;
            cp_async16(sB + row * 144 + c * 16,
                       B + (size_t)(n0 + row) * ldb + t * BK + c * 8);
        }
    };

    auto compute = [&](int s) {
        const uint32_t aB = smBase + s * SS;
        const uint32_t bB = aB + TBYTES;
#pragma unroll
        for (int ks = 0; ks < 4; ks++) {
            uint32_t bf[8][2];
#pragma unroll
            for (int p = 0; p < 4; p++) {
                const uint32_t rb =
                    (uint32_t)((wn * 64 + p * 16 + ((lane >> 4) & 1) * 8 + (lane & 7)) * 144
                               + ks * 32 + ((lane >> 3) & 1) * 16);
                LDM4(bf[2*p][0], bf[2*p][1], bf[2*p+1][0], bf[2*p+1][1], bB + rb);
            }
#pragma unroll
            for (int mt = 0; mt < 4; mt++) {
                uint32_t af[4];
                const uint32_t ra =
                    (uint32_t)((wm * 64 + mt * 16 + (lane & 15)) * 144
                               + ks * 32 + (lane >> 4) * 16);
                LDM4(af[0], af[1], af[2], af[3], aB + ra);
#pragma unroll
                for (int nt = 0; nt < 8; nt++) MMAH16816(acc[mt][nt], af, bf[nt]);
            }
        }
    };

    const int T = K / BK;
    issueA(0, 0);
    issueB(0, 0);
    CP_COMMIT();
    CP_WAIT0();
    __syncthreads();

    for (int t = 0; t < T; t++) {
        const int s = t & 1;
        if (t + 1 < T) {
            issueA(s ^ 1, t + 1);
            issueB(s ^ 1, t + 1);
            CP_COMMIT();
        }
        compute(s);
        CP_WAIT0();
        __syncthreads();
    }

#pragma unroll
    for (int mt = 0; mt < 4; mt++) {
#pragma unroll
        for (int nt = 0; nt < 8; nt++) {
            const int r0 = m0 + wm * 64 + mt * 16 + (lane >> 2);
            const int cc = n0 + wn * 64 + nt * 8 + (lane & 3) * 2;
#pragma unroll
            for (int h = 0; h < 2; h++) {
                const int m = r0 + h * 8;
                float vx = acc[mt][nt][2 * h];
                float vy = acc[mt][nt][2 * h + 1];
                if (bias)  { vx += bias[cc]; vy += bias[cc + 1]; }
                if (relu)  { vx = fmaxf(vx, 0.f); vy = fmaxf(vy, 0.f); }
                if (resid) {
                    const float2 rr = *(const float2*)(resid + (size_t)m * ldr + cc);
                    vx += rr.x; vy += rr.y;
                }
                if constexpr (OHALF) {
                    *(uint32_t*)(Ch + (size_t)m * ldc + cc) = pack_h2(vx, vy);
                } else {
                    *(float2*)(Cf + (size_t)m * ldc + cc) = make_float2(vx, vy);
                }
            }
        }
    }
}

// ==================== fused flash attention (single fp16) ====================
#define FQ_B 9216       // 64 rows * 144B
#define FK_B 18432      // 128 rows * 144B
#define FSMEM (FQ_B + 2*FK_B)   // 46080

__global__ __launch_bounds__(128, 2) void flash_attn(
    const __half* __restrict__ qkv, __half* __restrict__ o)
{
    extern __shared__ char sm[];
    const uint32_t smBase = smem_u32(sm);
    const int tid = threadIdx.x, lane = tid & 31, w = tid >> 5;
    const int b = blockIdx.y >> 4, h = blockIdx.y & 15;
    const size_t rowQ  = (size_t)b * SEQ + blockIdx.x * 64;
    const size_t rowKV = (size_t)b * SEQ;
    const int colh = h * DH;

    const uint32_t sQ = smBase;
    const uint32_t sK = smBase + FQ_B;
    const uint32_t sV = sK + FK_B;

#pragma unroll
    for (int i = 0; i < 4; i++) {
        const int idx = i * 128 + tid;
        const int c = idx & 7, row = idx >> 3;
        cp_async16(sQ + row * 144 + c * 16,
                   qkv + (rowQ + row) * QKVN + colh + c * 8);
    }
    auto loadKV = [&](int kt) {
        const size_t base = (rowKV + kt * 128) * QKVN + colh;
#pragma unroll
        for (int i = 0; i < 16; i++) {
            const int idx = i * 128 + tid;
            const int kv = idx >> 10, c = idx & 7, row = (idx >> 3) & 127;
            const size_t off = base + (size_t)row * QKVN + c * 8 + (kv + 1) * DIM;
            cp_async16((kv ? sV : sK) + row * 144 + c * 16, qkv + off);
        }
    };
    loadKV(0);
    CP_COMMIT(); CP_WAIT0();
    __syncthreads();

    float oacc[8][4];
#pragma unroll
    for (int i = 0; i < 8; i++)
#pragma unroll
        for (int j = 0; j < 4; j++) oacc[i][j] = 0.f;
    float m0 = -INFINITY, m1 = -INFINITY, l0 = 0.f, l1 = 0.f;

    for (int kt = 0; kt < 8; kt++) {
        float sfr[16][4];
#pragma unroll
        for (int i = 0; i < 16; i++)
#pragma unroll
            for (int j = 0; j < 4; j++) sfr[i][j] = 0.f;
#pragma unroll
        for (int ks = 0; ks < 4; ks++) {
            uint32_t qa[4];
            const uint32_t ra = sQ + (w * 16 + (lane & 15)) * 144
                              + ks * 32 + (lane >> 4) * 16;
            LDM4(qa[0], qa[1], qa[2], qa[3], ra);
#pragma unroll
            for (int p = 0; p < 8; p++) {
                uint32_t kb[4];
                const uint32_t rb = sK + (p * 16 + ((lane >> 4) & 1) * 8 + (lane & 7)) * 144
                                  + ks * 32 + ((lane >> 3) & 1) * 16;
                LDM4(kb[0], kb[1], kb[2], kb[3], rb);
                MMAH16816(sfr[2*p],   qa, (&kb[0]));
                MMAH16816(sfr[2*p+1], qa, (&kb[2]));
            }
        }
        float mx0 = -INFINITY, mx1 = -INFINITY;
#pragma unroll
        for (int nt = 0; nt < 16; nt++) {
            mx0 = fmaxf(mx0, fmaxf(sfr[nt][0], sfr[nt][1]));
            mx1 = fmaxf(mx1, fmaxf(sfr[nt][2], sfr[nt][3]));
        }
        mx0 = fmaxf(mx0, __shfl_xor_sync(0xffffffffu, mx0, 1));
        mx0 = fmaxf(mx0, __shfl_xor_sync(0xffffffffu, mx0, 2));
        mx1 = fmaxf(mx1, __shfl_xor_sync(0xffffffffu, mx1, 1));
        mx1 = fmaxf(mx1, __shfl_xor_sync(0xffffffffu, mx1, 2));
        const float mn0 = fmaxf(m0, 0.125f * mx0);
        const float mn1 = fmaxf(m1, 0.125f * mx1);
        const float f0 = __expf(m0 - mn0);
        const float f1 = __expf(m1 - mn1);
        float rs0 = 0.f, rs1 = 0.f;
#pragma unroll
        for (int nt = 0; nt < 16; nt++) {
            const float p0 = __expf(fmaf(sfr[nt][0], 0.125f, -mn0));
            const float p1 = __expf(fmaf(sfr[nt][1], 0.125f, -mn0));
            const float p2 = __expf(fmaf(sfr[nt][2], 0.125f, -mn1));
            const float p3 = __expf(fmaf(sfr[nt][3], 0.125f, -mn1));
            rs0 += p0 + p1; rs1 += p2 + p3;
            sfr[nt][0] = p0; sfr[nt][1] = p1; sfr[nt][2] = p2; sfr[nt][3] = p3;
        }
        rs0 += __shfl_xor_sync(0xffffffffu, rs0, 1);
        rs0 += __shfl_xor_sync(0xffffffffu, rs0, 2);
        rs1 += __shfl_xor_sync(0xffffffffu, rs1, 1);
        rs1 += __shfl_xor_sync(0xffffffffu, rs1, 2);
        l0 = l0 * f0 + rs0; l1 = l1 * f1 + rs1;
        m0 = mn0; m1 = mn1;
#pragma unroll
        for (int dt = 0; dt < 8; dt++) {
            oacc[dt][0] *= f0; oacc[dt][1] *= f0;
            oacc[dt][2] *= f1; oacc[dt][3] *= f1;
        }
#pragma unroll
        for (int ks = 0; ks < 8; ks++) {
            uint32_t pa[4];
            pa[0] = pack_h2(sfr[2 * ks][0],     sfr[2 * ks][1]);
            pa[1] = pack_h2(sfr[2 * ks][2],     sfr[2 * ks][3]);
            pa[2] = pack_h2(sfr[2 * ks + 1][0], sfr[2 * ks + 1][1]);
            pa[3] = pack_h2(sfr[2 * ks + 1][2], sfr[2 * ks + 1][3]);
#pragma unroll
            for (int dt = 0; dt < 8; dt++) {
                uint32_t vb[2];
                const uint32_t rv = sV + (ks * 16 + (lane & 15)) * 144 + dt * 16;
                LDM2T(vb[0], vb[1], rv);
                MMAH16816(oacc[dt], pa, vb);
            }
        }
        if (kt < 7) {
            __syncthreads();
            loadKV(kt + 1);
            CP_COMMIT(); CP_WAIT0();
            __syncthreads();
        }
    }

    const float i0 = 1.f / l0, i1 = 1.f / l1;
    const int r = w * 16 + (lane >> 2);
    const int cc = (lane & 3) * 2;
#pragma unroll
    for (int dt = 0; dt < 8; dt++) {
        const size_t o0 = (rowQ + r) * DIM + colh + dt * 8 + cc;
        *(uint32_t*)(o + o0) = pack_h2(oacc[dt][0] * i0, oacc[dt][1] * i0);
        const size_t o1 = o0 + 8 * DIM;
        *(uint32_t*)(o + o1) = pack_h2(oacc[dt][2] * i1, oacc[dt][3] * i1);
    }
}

// ---------------- LayerNorm -> single fp16 plane ----------------------------
__global__ __launch_bounds__(256) void ln_kernel(const float* __restrict__ x,
                                                 __half* __restrict__ y,
                                                 const float* __restrict__ alpha,
                                                 const float* __restrict__ beta) {
    __shared__ float sh_s[8], sh_q[8];
    const size_t row = blockIdx.x;
    const float4* xr = (const float4*)(x + row * DIM);
    const int tid = threadIdx.x;
    float4 v = xr[tid];
    float s = v.x + v.y + v.z + v.w;
    float q = v.x*v.x + v.y*v.y + v.z*v.z + v.w*v.w;
#pragma unroll
    for (int o = 16; o; o >>= 1) {
        s += __shfl_xor_sync(0xffffffffu, s, o);
        q += __shfl_xor_sync(0xffffffffu, q, o);
    }
    if ((tid & 31) == 0) { sh_s[tid >> 5] = s; sh_q[tid >> 5] = q; }
    __syncthreads();
    if (tid < 32) {
        s = (tid < 8) ? sh_s[tid] : 0.f;
        q = (tid < 8) ? sh_q[tid] : 0.f;
#pragma unroll
        for (int o = 4; o; o >>= 1) {
            s += __shfl_xor_sync(0xffffffffu, s, o);
            q += __shfl_xor_sync(0xffffffffu, q, o);
        }
        if (tid == 0) { sh_s[0] = s; sh_q[0] = q; }
    }
    __syncthreads();
    s = sh_s[0]; q = sh_q[0];
    const float mean = s * (1.0f / DIM);
    const float var  = (q - (float)DIM * mean * mean) * (1.0f / (DIM - 1));
    const float inv  = 1.0f / (sqrtf(fmaxf(var, 0.f)) + 1e-6f);
    const float4 a = ((const float4*)alpha)[tid];
    const float4 b = ((const float4*)beta)[tid];
    const float ox = a.x * (v.x - mean) * inv + b.x;
    const float oy = a.y * (v.y - mean) * inv + b.y;
    const float oz = a.z * (v.z - mean) * inv + b.z;
    const float ow = a.w * (v.w - mean) * inv + b.w;
    *(uint2*)((uint16_t*)y + row * DIM + 4 * tid) =
        make_uint2(pack_h2(ox, oy), pack_h2(oz, ow));
}

// ---------------- launch ----------------------------------------------------
template<typename T>
static T* symaddr(const void* s) {
    void* p = nullptr;
    cudaGetSymbolAddress(&p, s);
    return (T*)p;
}

#define SMEM_H1 (2 * (2 * 128 * 144))   // 73728

extern "C" void kernel_launch(void* const* d_in, const int* in_sizes, int n_in,
                              void* d_out, int out_size) {
    (void)in_sizes; (void)n_in; (void)out_size;
    const float* x     = (const float*)d_in[0];
    const float* wq    = (const float*)d_in[2];
    const float* bq    = (const float*)d_in[3];
    const float* wk    = (const float*)d_in[4];
    const float* bk    = (const float*)d_in[5];
    const float* wv    = (const float*)d_in[6];
    const float* bv    = (const float*)d_in[7];
    const float* wo    = (const float*)d_in[8];
    const float* bo    = (const float*)d_in[9];
    const float* w1    = (const float*)d_in[10];
    const float* b1    = (const float*)d_in[11];
    const float* w2    = (const float*)d_in[12];
    const float* b2    = (const float*)d_in[13];
    const float* alpha = (const float*)d_in[14];
    const float* beta  = (const float*)d_in[15];
    float* out = (float*)d_out;

    cudaFuncSetAttribute(gemm_h1<true>,
                         cudaFuncAttributeMaxDynamicSharedMemorySize, SMEM_H1);
    cudaFuncSetAttribute(gemm_h1<false>,
                         cudaFuncAttributeMaxDynamicSharedMemorySize, SMEM_H1);
    cudaFuncSetAttribute(flash_attn,
                         cudaFuncAttributeMaxDynamicSharedMemorySize, FSMEM);

    __half* ln   = symaddr<__half>(g_ln);
    __half* qkv  = symaddr<__half>(g_qkv);
    float*  x1   = symaddr<float>(g_x1);
    __half* w16  = symaddr<__half>(g_w16);
    __half* hid  = symaddr<__half>(g_hid);
    float*  b3   = symaddr<float>(g_b3);

    // 0) weight conversion + bias concat
    wconvh_all<<<4 * (DIM * DIM / 2) / 256, 256>>>(wq, wk, wv, wo,
                                                   w16 + HOFF_QKV);
    wconvh<<<(HFF * DIM / 2 + 255) / 256, 256>>>(w1, w16 + HOFF_1, HFF * DIM / 2);
    wconvh<<<(HFF * DIM / 2 + 255) / 256, 256>>>(w2, w16 + HOFF_2, HFF * DIM / 2);
    bcat<<<(QKVN + 255) / 256, 256>>>(bq, bk, bv, b3);

    // 1) LN1
    ln_kernel<<<MROWS, 256>>>(x, ln, alpha, beta);

    // 2) fused QKV projection [8192, 3072]
    dim3 gqkv(QKVN / 128, MROWS / 128, 1);
    gemm_h1<true><<<gqkv, 128, SMEM_H1>>>(
        ln, DIM, w16 + HOFF_QKV, DIM,
        nullptr, qkv, QKVN, DIM, b3, nullptr, 0, 0);

    // 3) fused attention -> fp16 plane (reuse ln buffer)
    dim3 gfa(SEQ / 64, BATCH * HEADS, 1);
    flash_attn<<<gfa, 128, FSMEM>>>(qkv, ln);

    // 4) O projection + residual x -> x1 (fp32)
    dim3 gw(DIM / 128, MROWS / 128, 1);
    gemm_h1<false><<<gw, 128, SMEM_H1>>>(
        ln, DIM, w16 + HOFF_O, DIM,
        x1, nullptr, DIM, DIM, bo, x, DIM, 0);

    // 5) LN2
    ln_kernel<<<MROWS, 256>>>(x1, ln, alpha, beta);

    // 6) FFN1 (+ReLU) -> fp16 hidden
    dim3 gf1(HFF / 128, MROWS / 128, 1);
    gemm_h1<true><<<gf1, 128, SMEM_H1>>>(
        ln, DIM, w16 + HOFF_1, DIM,
        nullptr, hid, HFF, DIM, b1, nullptr, 0, 1);

    // 7) FFN2 + residual x1 -> out (fp32)
    dim3 gf2(DIM / 128, MROWS / 128, 1);
    gemm_h1<false><<<gf2, 128, SMEM_H1>>>(
        hid, HFF, w16 + HOFF_2, HFF,
        out, nullptr, DIM, HFF, b2, x1, DIM, 0);
}

// round 14
// speedup vs baseline: 8.2332x; 1.0167x over previous
#include <cuda_runtime.h>
#include <cuda_fp16.h>
#include <math.h>
#include <stdint.h>

#define BATCH 8
#define SEQ   1024
#define DIM   1024
#define HEADS 16
#define DH    64
#define HFF   4096
#define MROWS (BATCH*SEQ)   // 8192
#define QKVN  (3*DIM)       // 3072

// ---------------- scratch (static device arrays: allocation-free) ----------
__device__ __half g_ln [(size_t)MROWS*DIM];
__device__ __half g_qkv[(size_t)MROWS*QKVN];
__device__ float  g_x1 [(size_t)MROWS*DIM];
__device__ __half g_hid[(size_t)MROWS*HFF];
__device__ float  g_b3 [QKVN];
// single fp16 weight planes: wqkv (3M) | wo (1M) | w1 (4M) | w2 (4M)
#define HOFF_QKV 0
#define HOFF_O   ((size_t)3*DIM*DIM)
#define HOFF_1   ((size_t)4*DIM*DIM)
#define HOFF_2   ((size_t)4*DIM*DIM + (size_t)HFF*DIM)
__device__ __half g_w16[(size_t)4*DIM*DIM + (size_t)2*HFF*DIM];

// ==================== helpers ====================
__device__ __forceinline__ uint32_t smem_u32(const void* p) {
    uint32_t a;
    asm("{ .reg .u64 t; cvta.to.shared.u64 t, %1; cvt.u32.u64 %0, t; }"
        : "=r"(a) : "l"(p));
    return a;
}
__device__ __forceinline__ void cp_async16(uint32_t dst, const void* src) {
    uint64_t g;
    asm("cvta.to.global.u64 %0, %1;" : "=l"(g) : "l"(src));
    asm volatile("cp.async.cg.shared.global [%0], [%1], 16;"
                 :: "r"(dst), "l"(g) : "memory");
}
#define CP_COMMIT() asm volatile("cp.async.commit_group;" ::: "memory")
#define CP_WAIT0()  asm volatile("cp.async.wait_group 0;"  ::: "memory")
#define CP_WAIT1()  asm volatile("cp.async.wait_group 1;"  ::: "memory")

__device__ __forceinline__ uint32_t pack_h2(float a, float b) {
    __half2 h = __floats2half2_rn(a, b);
    return *(uint32_t*)&h;
}

#define LDM4(r0, r1, r2, r3, addr) \
    asm volatile("ldmatrix.sync.aligned.m8n8.x4.shared.b16 {%0,%1,%2,%3}, [%4];" \
                 : "=r"(r0), "=r"(r1), "=r"(r2), "=r"(r3) : "r"(addr))
#define LDM2T(r0, r1, addr) \
    asm volatile("ldmatrix.sync.aligned.m8n8.x2.trans.shared.b16 {%0,%1}, [%2];" \
                 : "=r"(r0), "=r"(r1) : "r"(addr))
#define MMAH16816(c, a, b) \
    asm volatile("mma.sync.aligned.m16n8k16.row.col.f32.f16.f16.f32 " \
                 "{%0,%1,%2,%3}, {%4,%5,%6,%7}, {%8,%9}, {%0,%1,%2,%3};" \
                 : "+f"((c)[0]), "+f"((c)[1]), "+f"((c)[2]), "+f"((c)[3]) \
                 : "r"((a)[0]), "r"((a)[1]), "r"((a)[2]), "r"((a)[3]), \
                   "r"((b)[0]), "r"((b)[1]))

// ------------- weight conversions: fp32 -> single fp16 plane ---------------
__global__ __launch_bounds__(256) void wconvh_all(
    const float* __restrict__ w0, const float* __restrict__ w1p,
    const float* __restrict__ w2p, const float* __restrict__ w3,
    __half* __restrict__ o) {
    const int n2p = DIM * DIM / 2;
    const int i = blockIdx.x * 256 + threadIdx.x;    // [0, 4*n2p)
    const float* src = (i < n2p) ? w0 : (i < 2 * n2p) ? w1p
                     : (i < 3 * n2p) ? w2p : w3;
    const int j = i & (n2p - 1);
    const float2 v = ((const float2*)src)[j];
    ((__half2*)o)[i] = __floats2half2_rn(v.x, v.y);
}
__global__ __launch_bounds__(256) void wconvh(const float* __restrict__ w,
                                              __half* __restrict__ o, int n2) {
    const int i = blockIdx.x * 256 + threadIdx.x;
    if (i >= n2) return;
    const float2 v = ((const float2*)w)[i];
    ((__half2*)o)[i] = __floats2half2_rn(v.x, v.y);
}
__global__ __launch_bounds__(256) void bcat(const float* __restrict__ a,
                                            const float* __restrict__ b,
                                            const float* __restrict__ c,
                                            float* __restrict__ o) {
    const int i = blockIdx.x * 256 + threadIdx.x;
    if (i < DIM)            o[i] = a[i];
    else if (i < 2 * DIM)   o[i] = b[i - DIM];
    else if (i < 3 * DIM)   o[i] = c[i - 2 * DIM];
}

// ==================== single-fp16 1-MMA GEMM, 3-stage pipeline =============
// C[m,n] = sum_k A[m,k]*B[n,k] + bias (+relu, +resid), fp32 accumulate.
// 128 threads, 2x2 warps, 64x64 warp tiles, BM=BN=128, BK=64.
template<bool OHALF>
__global__ __launch_bounds__(128, 2) void gemm_h1(
    const __half* __restrict__ A, int lda,
    const __half* __restrict__ B, int ldb,
    float* __restrict__ Cf, __half* __restrict__ Ch, int ldc,
    int K,
    const float* __restrict__ bias,
    const float* __restrict__ resid, int ldr,
    int relu)
{
    constexpr int BK = 64;
    constexpr int TBYTES = 128 * 144;     // one operand tile
    constexpr int SS = 2 * TBYTES;        // stage = A + B (36864)

    extern __shared__ char sm[];
    const uint32_t smBase = smem_u32(sm);

    const int tid = threadIdx.x, wid = tid >> 5, lane = tid & 31;
    const int wm = wid >> 1, wn = wid & 1;
    const int m0 = blockIdx.y * 128, n0 = blockIdx.x * 128;

    float acc[4][8][4];
#pragma unroll
    for (int i = 0; i < 4; i++)
#pragma unroll
        for (int j = 0; j < 8; j++)
#pragma unroll
            for (int r = 0; r < 4; r++) acc[i][j][r] = 0.f;

    auto issue = [&](int s, int t) {
        const uint32_t sA = smBase + s * SS;
        const uint32_t sB = sA + TBYTES;
#pragma unroll
        for (int i = 0; i < 8; i++) {
            const int idx = i * 128 + tid;
            const int c = idx & 7, row = idx >> 3;
            cp_async16(sA + row * 144 + c * 16,
                       A + (size_t)(m0 + row) * lda + t * BK + c * 8);
        }
#pragma unroll
        for (int i = 0; i < 8; i++) {
            const int idx = i * 128 + tid;
            const int c = idx & 7, row = idx >> 3;
            cp_async16(sB + row * 144 + c * 16,
                       B + (size_t)(n0 + row) * ldb + t * BK + c * 8);
        }
        CP_COMMIT();
    };

    auto compute = [&](int s) {
        const uint32_t aB = smBase + s * SS;
        const uint32_t bB = aB + TBYTES;
#pragma unroll
        for (int ks = 0; ks < 4; ks++) {
            uint32_t bf[8][2];
#pragma unroll
            for (int p = 0; p < 4; p++) {
                const uint32_t rb =
                    (uint32_t)((wn * 64 + p * 16 + ((lane >> 4) & 1) * 8 + (lane & 7)) * 144
                               + ks * 32 + ((lane >> 3) & 1) * 16);
                LDM4(bf[2*p][0], bf[2*p][1], bf[2*p+1][0], bf[2*p+1][1], bB + rb);
            }
#pragma unroll
            for (int mt = 0; mt < 4; mt++) {
                uint32_t af[4];
                const uint32_t ra =
                    (uint32_t)((wm * 64 + mt * 16 + (lane & 15)) * 144
                               + ks * 32 + (lane >> 4) * 16);
                LDM4(af[0], af[1], af[2], af[3], aB + ra);
#pragma unroll
                for (int nt = 0; nt < 8; nt++) MMAH16816(acc[mt][nt], af, bf[nt]);
            }
        }
    };

    const int T = K / BK;
    issue(0, 0);
    if (T > 1) issue(1, 1);
    CP_WAIT1();              // stage 0 ready (stage 1 may be in flight)
    __syncthreads();

    for (int t = 0; t < T; t++) {
        compute(t % 3);
        if (t + 1 < T) {
            if (t + 2 < T) {
                issue((t + 2) % 3, t + 2);   // buffer freed by compute(t-1)
                CP_WAIT1();                  // stage t+1 complete
            } else {
                CP_WAIT0();
            }
            __syncthreads();
        }
    }

#pragma unroll
    for (int mt = 0; mt < 4; mt++) {
#pragma unroll
        for (int nt = 0; nt < 8; nt++) {
            const int r0 = m0 + wm * 64 + mt * 16 + (lane >> 2);
            const int cc = n0 + wn * 64 + nt * 8 + (lane & 3) * 2;
#pragma unroll
            for (int h = 0; h < 2; h++) {
                const int m = r0 + h * 8;
                float vx = acc[mt][nt][2 * h];
                float vy = acc[mt][nt][2 * h + 1];
                if (bias)  { vx += bias[cc]; vy += bias[cc + 1]; }
                if (relu)  { vx = fmaxf(vx, 0.f); vy = fmaxf(vy, 0.f); }
                if (resid) {
                    const float2 rr = *(const float2*)(resid + (size_t)m * ldr + cc);
                    vx += rr.x; vy += rr.y;
                }
                if constexpr (OHALF) {
                    *(uint32_t*)(Ch + (size_t)m * ldc + cc) = pack_h2(vx, vy);
                } else {
                    *(float2*)(Cf + (size_t)m * ldc + cc) = make_float2(vx, vy);
                }
            }
        }
    }
}

// ============== fused flash attention, double-buffered KV ===================
#define FQ_B 9216       // 64 rows * 144B
#define FKV_B 36864     // K(18432) + V(18432) one stage
#define FSMEM (FQ_B + 2*FKV_B)   // 82944

__global__ __launch_bounds__(128, 2) void flash_attn(
    const __half* __restrict__ qkv, __half* __restrict__ o)
{
    extern __shared__ char sm[];
    const uint32_t smBase = smem_u32(sm);
    const int tid = threadIdx.x, lane = tid & 31, w = tid >> 5;
    const int b = blockIdx.y >> 4, h = blockIdx.y & 15;
    const size_t rowQ  = (size_t)b * SEQ + blockIdx.x * 64;
    const size_t rowKV = (size_t)b * SEQ;
    const int colh = h * DH;

    const uint32_t sQ = smBase;
    const uint32_t sKV0 = smBase + FQ_B;

    auto loadKV = [&](int kt, int s) {
        const uint32_t sK = sKV0 + s * FKV_B;
        const size_t base = (rowKV + kt * 128) * QKVN + colh;
#pragma unroll
        for (int i = 0; i < 16; i++) {
            const int idx = i * 128 + tid;
            const int kv = idx >> 10, c = idx & 7, row = (idx >> 3) & 127;
            const size_t off = base + (size_t)row * QKVN + c * 8 + (kv + 1) * DIM;
            cp_async16(sK + kv * 18432 + row * 144 + c * 16, qkv + off);
        }
        CP_COMMIT();
    };

    // prologue: Q + KV0 in group A, KV1 in group B
#pragma unroll
    for (int i = 0; i < 4; i++) {
        const int idx = i * 128 + tid;
        const int c = idx & 7, row = idx >> 3;
        cp_async16(sQ + row * 144 + c * 16,
                   qkv + (rowQ + row) * QKVN + colh + c * 8);
    }
    loadKV(0, 0);          // commits Q + KV0 together
    loadKV(1, 1);
    CP_WAIT1();            // Q + KV0 ready
    __syncthreads();

    float oacc[8][4];
#pragma unroll
    for (int i = 0; i < 8; i++)
#pragma unroll
        for (int j = 0; j < 4; j++) oacc[i][j] = 0.f;
    float m0 = -INFINITY, m1 = -INFINITY, l0 = 0.f, l1 = 0.f;

    for (int kt = 0; kt < 8; kt++) {
        const int s = kt & 1;
        const uint32_t sK = sKV0 + s * FKV_B;
        const uint32_t sV = sK + 18432;

        float sfr[16][4];
#pragma unroll
        for (int i = 0; i < 16; i++)
#pragma unroll
            for (int j = 0; j < 4; j++) sfr[i][j] = 0.f;
#pragma unroll
        for (int ks = 0; ks < 4; ks++) {
            uint32_t qa[4];
            const uint32_t ra = sQ + (w * 16 + (lane & 15)) * 144
                              + ks * 32 + (lane >> 4) * 16;
            LDM4(qa[0], qa[1], qa[2], qa[3], ra);
#pragma unroll
            for (int p = 0; p < 8; p++) {
                uint32_t kb[4];
                const uint32_t rb = sK + (p * 16 + ((lane >> 4) & 1) * 8 + (lane & 7)) * 144
                                  + ks * 32 + ((lane >> 3) & 1) * 16;
                LDM4(kb[0], kb[1], kb[2], kb[3], rb);
                MMAH16816(sfr[2*p],   qa, (&kb[0]));
                MMAH16816(sfr[2*p+1], qa, (&kb[2]));
            }
        }
        float mx0 = -INFINITY, mx1 = -INFINITY;
#pragma unroll
        for (int nt = 0; nt < 16; nt++) {
            mx0 = fmaxf(mx0, fmaxf(sfr[nt][0], sfr[nt][1]));
            mx1 = fmaxf(mx1, fmaxf(sfr[nt][2], sfr[nt][3]));
        }
        mx0 = fmaxf(mx0, __shfl_xor_sync(0xffffffffu, mx0, 1));
        mx0 = fmaxf(mx0, __shfl_xor_sync(0xffffffffu, mx0, 2));
        mx1 = fmaxf(mx1, __shfl_xor_sync(0xffffffffu, mx1, 1));
        mx1 = fmaxf(mx1, __shfl_xor_sync(0xffffffffu, mx1, 2));
        const float mn0 = fmaxf(m0, 0.125f * mx0);
        const float mn1 = fmaxf(m1, 0.125f * mx1);
        const float f0 = __expf(m0 - mn0);
        const float f1 = __expf(m1 - mn1);
        float rs0 = 0.f, rs1 = 0.f;
#pragma unroll
        for (int nt = 0; nt < 16; nt++) {
            const float p0 = __expf(fmaf(sfr[nt][0], 0.125f, -mn0));
            const float p1 = __expf(fmaf(sfr[nt][1], 0.125f, -mn0));
            const float p2 = __expf(fmaf(sfr[nt][2], 0.125f, -mn1));
            const float p3 = __expf(fmaf(sfr[nt][3], 0.125f, -mn1));
            rs0 += p0 + p1; rs1 += p2 + p3;
            sfr[nt][0] = p0; sfr[nt][1] = p1; sfr[nt][2] = p2; sfr[nt][3] = p3;
        }
        rs0 += __shfl_xor_sync(0xffffffffu, rs0, 1);
        rs0 += __shfl_xor_sync(0xffffffffu, rs0, 2);
        rs1 += __shfl_xor_sync(0xffffffffu, rs1, 1);
        rs1 += __shfl_xor_sync(0xffffffffu, rs1, 2);
        l0 = l0 * f0 + rs0; l1 = l1 * f1 + rs1;
        m0 = mn0; m1 = mn1;
#pragma unroll
        for (int dt = 0; dt < 8; dt++) {
            oacc[dt][0] *= f0; oacc[dt][1] *= f0;
            oacc[dt][2] *= f1; oacc[dt][3] *= f1;
        }
#pragma unroll
        for (int ks = 0; ks < 8; ks++) {
            uint32_t pa[4];
            pa[0] = pack_h2(sfr[2 * ks][0],     sfr[2 * ks][1]);
            pa[1] = pack_h2(sfr[2 * ks][2],     sfr[2 * ks][3]);
            pa[2] = pack_h2(sfr[2 * ks + 1][0], sfr[2 * ks + 1][1]);
            pa[3] = pack_h2(sfr[2 * ks + 1][2], sfr[2 * ks + 1][3]);
#pragma unroll
            for (int dt = 0; dt < 8; dt++) {
                uint32_t vb[2];
                const uint32_t rv = sV + (ks * 16 + (lane & 15)) * 144 + dt * 16;
                LDM2T(vb[0], vb[1], rv);
                MMAH16816(oacc[dt], pa, vb);
            }
        }
        // pipeline: free stage s, prefetch kt+2 into it, wait for kt+1
        if (kt + 1 < 8) {
            __syncthreads();                  // all warps done reading stage s
            if (kt + 2 < 8) {
                loadKV(kt + 2, s);
                CP_WAIT1();                   // stage s^1 (kt+1) complete
            } else {
                CP_WAIT0();
            }
            __syncthreads();
        }
    }

    const float i0 = 1.f / l0, i1 = 1.f / l1;
    const int r = w * 16 + (lane >> 2);
    const int cc = (lane & 3) * 2;
#pragma unroll
    for (int dt = 0; dt < 8; dt++) {
        const size_t o0 = (rowQ + r) * DIM + colh + dt * 8 + cc;
        *(uint32_t*)(o + o0) = pack_h2(oacc[dt][0] * i0, oacc[dt][1] * i0);
        const size_t o1 = o0 + 8 * DIM;
        *(uint32_t*)(o + o1) = pack_h2(oacc[dt][2] * i1, oacc[dt][3] * i1);
    }
}

// ---------------- LayerNorm -> single fp16 plane ----------------------------
__global__ __launch_bounds__(256) void ln_kernel(const float* __restrict__ x,
                                                 __half* __restrict__ y,
                                                 const float* __restrict__ alpha,
                                                 const float* __restrict__ beta) {
    __shared__ float sh_s[8], sh_q[8];
    const size_t row = blockIdx.x;
    const float4* xr = (const float4*)(x + row * DIM);
    const int tid = threadIdx.x;
    float4 v = xr[tid];
    float s = v.x + v.y + v.z + v.w;
    float q = v.x*v.x + v.y*v.y + v.z*v.z + v.w*v.w;
#pragma unroll
    for (int o = 16; o; o >>= 1) {
        s += __shfl_xor_sync(0xffffffffu, s, o);
        q += __shfl_xor_sync(0xffffffffu, q, o);
    }
    if ((tid & 31) == 0) { sh_s[tid >> 5] = s; sh_q[tid >> 5] = q; }
    __syncthreads();
    if (tid < 32) {
        s = (tid < 8) ? sh_s[tid] : 0.f;
        q = (tid < 8) ? sh_q[tid] : 0.f;
#pragma unroll
        for (int o = 4; o; o >>= 1) {
            s += __shfl_xor_sync(0xffffffffu, s, o);
            q += __shfl_xor_sync(0xffffffffu, q, o);
        }
        if (tid == 0) { sh_s[0] = s; sh_q[0] = q; }
    }
    __syncthreads();
    s = sh_s[0]; q = sh_q[0];
    const float mean = s * (1.0f / DIM);
    const float var  = (q - (float)DIM * mean * mean) * (1.0f / (DIM - 1));
    const float inv  = 1.0f / (sqrtf(fmaxf(var, 0.f)) + 1e-6f);
    const float4 a = ((const float4*)alpha)[tid];
    const float4 b = ((const float4*)beta)[tid];
    const float ox = a.x * (v.x - mean) * inv + b.x;
    const float oy = a.y * (v.y - mean) * inv + b.y;
    const float oz = a.z * (v.z - mean) * inv + b.z;
    const float ow = a.w * (v.w - mean) * inv + b.w;
    *(uint2*)((uint16_t*)y + row * DIM + 4 * tid) =
        make_uint2(pack_h2(ox, oy), pack_h2(oz, ow));
}

// ---------------- launch ----------------------------------------------------
template<typename T>
static T* symaddr(const void* s) {
    void* p = nullptr;
    cudaGetSymbolAddress(&p, s);
    return (T*)p;
}

#define SMEM_H1 (3 * (2 * 128 * 144))   // 110592

extern "C" void kernel_launch(void* const* d_in, const int* in_sizes, int n_in,
                              void* d_out, int out_size) {
    (void)in_sizes; (void)n_in; (void)out_size;
    const float* x     = (const float*)d_in[0];
    const float* wq    = (const float*)d_in[2];
    const float* bq    = (const float*)d_in[3];
    const float* wk    = (const float*)d_in[4];
    const float* bk    = (const float*)d_in[5];
    const float* wv    = (const float*)d_in[6];
    const float* bv    = (const float*)d_in[7];
    const float* wo    = (const float*)d_in[8];
    const float* bo    = (const float*)d_in[9];
    const float* w1    = (const float*)d_in[10];
    const float* b1    = (const float*)d_in[11];
    const float* w2    = (const float*)d_in[12];
    const float* b2    = (const float*)d_in[13];
    const float* alpha = (const float*)d_in[14];
    const float* beta  = (const float*)d_in[15];
    float* out = (float*)d_out;

    cudaFuncSetAttribute(gemm_h1<true>,
                         cudaFuncAttributeMaxDynamicSharedMemorySize, SMEM_H1);
    cudaFuncSetAttribute(gemm_h1<false>,
                         cudaFuncAttributeMaxDynamicSharedMemorySize, SMEM_H1);
    cudaFuncSetAttribute(flash_attn,
                         cudaFuncAttributeMaxDynamicSharedMemorySize, FSMEM);

    __half* ln   = symaddr<__half>(g_ln);
    __half* qkv  = symaddr<__half>(g_qkv);
    float*  x1   = symaddr<float>(g_x1);
    __half* w16  = symaddr<__half>(g_w16);
    __half* hid  = symaddr<__half>(g_hid);
    float*  b3   = symaddr<float>(g_b3);

    // 0) weight conversion + bias concat
    wconvh_all<<<4 * (DIM * DIM / 2) / 256, 256>>>(wq, wk, wv, wo,
                                                   w16 + HOFF_QKV);
    wconvh<<<(HFF * DIM / 2 + 255) / 256, 256>>>(w1, w16 + HOFF_1, HFF * DIM / 2);
    wconvh<<<(HFF * DIM / 2 + 255) / 256, 256>>>(w2, w16 + HOFF_2, HFF * DIM / 2);
    bcat<<<(QKVN + 255) / 256, 256>>>(bq, bk, bv, b3);

    // 1) LN1
    ln_kernel<<<MROWS, 256>>>(x, ln, alpha, beta);

    // 2) fused QKV projection [8192, 3072]
    dim3 gqkv(QKVN / 128, MROWS / 128, 1);
    gemm_h1<true><<<gqkv, 128, SMEM_H1>>>(
        ln, DIM, w16 + HOFF_QKV, DIM,
        nullptr, qkv, QKVN, DIM, b3, nullptr, 0, 0);

    // 3) fused attention -> fp16 plane (reuse ln buffer)
    dim3 gfa(SEQ / 64, BATCH * HEADS, 1);
    flash_attn<<<gfa, 128, FSMEM>>>(qkv, ln);

    // 4) O projection + residual x -> x1 (fp32)
    dim3 gw(DIM / 128, MROWS / 128, 1);
    gemm_h1<false><<<gw, 128, SMEM_H1>>>(
        ln, DIM, w16 + HOFF_O, DIM,
        x1, nullptr, DIM, DIM, bo, x, DIM, 0);

    // 5) LN2
    ln_kernel<<<MROWS, 256>>>(x1, ln, alpha, beta);

    // 6) FFN1 (+ReLU) -> fp16 hidden
    dim3 gf1(HFF / 128, MROWS / 128, 1);
    gemm_h1<true><<<gf1, 128, SMEM_H1>>>(
        ln, DIM, w16 + HOFF_1, DIM,
        nullptr, hid, HFF, DIM, b1, nullptr, 0, 1);

    // 7) FFN2 + residual x1 -> out (fp32)
    dim3 gf2(DIM / 128, MROWS / 128, 1);
    gemm_h1<false><<<gf2, 128, SMEM_H1>>>(
        hid, HFF, w16 + HOFF_2, HFF,
        out, nullptr, DIM, HFF, b2, x1, DIM, 0);
}